// round 9
// baseline (speedup 1.0000x reference)
#include <cuda_runtime.h>
#include <cuda_bf16.h>

#define NB 4
#define NC 512
#define CKQ 256
#define NW 64
#define NH 64
#define NN 4096   // H*W

// ---------------- scratch (device globals) ----------------------------------
__device__ float g_xbar[NB][NC][NW];            // mean_h x (f32, coalesced)
__device__ float g_x2df[NB][NC][NW];            // interpolated PE row (f32)
__device__ __align__(16) __nv_bfloat16 g_x2dTh[NB][NW][NC], g_x2dTl[NB][NW][NC];
__device__ __align__(16) __nv_bfloat16 g_xbarTh[NB][NW][NC], g_xbarTl[NB][NW][NC];
__device__ __align__(16) __nv_bfloat16 g_Gh[NC][NC], g_Gl[NC][NC];
__device__ __align__(16) __nv_bfloat16 g_Wvh[NC][NC], g_Wvl[NC][NC];
__device__ __align__(16) __nv_bfloat16 g_MTh[NB][NW][NC], g_MTl[NB][NW][NC];
__device__ __align__(16) __nv_bfloat16 g_vbh[NB][NC][NW], g_vbl[NB][NC][NW];
__device__ float g_v1[NC];        // Wq^T bk
__device__ float g_v2[NC];        // Wk^T bq
__device__ float g_s0;            // bq . bk
__device__ float g_dw[NB][NW];

// ---------------- helpers ----------------------------------------------------
__device__ __forceinline__ unsigned pack_bf2(float e, float o) {
  __nv_bfloat162 h;
  h.x = __float2bfloat16(e);
  h.y = __float2bfloat16(o);
  return *reinterpret_cast<unsigned*>(&h);
}
__device__ __forceinline__ void split_bf(float v, __nv_bfloat16& h, __nv_bfloat16& l) {
  h = __float2bfloat16(v);
  l = __float2bfloat16(v - __bfloat162float(h));
}
__device__ __forceinline__ void ldsm4(unsigned& r0, unsigned& r1, unsigned& r2,
                                      unsigned& r3, unsigned addr) {
  asm volatile("ldmatrix.sync.aligned.m8n8.x4.shared.b16 {%0,%1,%2,%3},[%4];"
               : "=r"(r0), "=r"(r1), "=r"(r2), "=r"(r3) : "r"(addr));
}
__device__ __forceinline__ void mma16816(float* d, const unsigned* a,
                                         unsigned b0, unsigned b1) {
  asm volatile(
    "mma.sync.aligned.m16n8k16.row.col.f32.bf16.bf16.f32 "
    "{%0,%1,%2,%3},{%4,%5,%6,%7},{%8,%9},{%0,%1,%2,%3};"
    : "+f"(d[0]), "+f"(d[1]), "+f"(d[2]), "+f"(d[3])
    : "r"(a[0]), "r"(a[1]), "r"(a[2]), "r"(a[3]), "r"(b0), "r"(b1));
}
__device__ __forceinline__ void cp16(unsigned saddr, const void* g) {
  asm volatile("cp.async.cg.shared.global [%0],[%1],16;" :: "r"(saddr), "l"(g));
}
#define CP_COMMIT() asm volatile("cp.async.commit_group;")
#define CP_WAIT(n)  asm volatile("cp.async.wait_group %0;" :: "n"(n))

// =============================================================================
// k_front: [0,2048) prep (f32 coalesced out) | [2048,2112) G | [2112,2144) Wv | 2144 bias
// =============================================================================
#define GA_H 0
#define GA_L 5120
#define GB_H 10240
#define GB_L 15360

__global__ __launch_bounds__(256)
void k_front(const float* __restrict__ x, const int* __restrict__ pos,
             const float* __restrict__ pe, const float* __restrict__ Wq,
             const float* __restrict__ Wk, const float* __restrict__ Wv,
             const float* __restrict__ bq, const float* __restrict__ bk) {
  __shared__ float4 sm4[16][16];
  __shared__ float xbv[64];
  __shared__ float x1s[16];
  __shared__ int pidx[16];
  __shared__ __align__(16) char gsm[20480];

  int bx = blockIdx.x;
  int t = threadIdx.x;

  if (bx < 2048) {                     // ---------------- prep ----------------
    int c = bx & 511, b = bx >> 9;
    int hq = t >> 4, tw = t & 15;
    const float* xp = x + ((size_t)(b * NC + c)) * NH * NW;
    float4 s = {0.f, 0.f, 0.f, 0.f};
    #pragma unroll
    for (int h = hq; h < NH; h += 16) {
      float4 v = *(const float4*)&xp[h * NW + tw * 4];
      s.x += v.x; s.y += v.y; s.z += v.z; s.w += v.w;
    }
    sm4[hq][tw] = s;
    if (t < 16) pidx[t] = pos[b * NN + 4 * t] >> 3;
    __syncthreads();
    if (hq == 0) {
      float4 a = {0.f, 0.f, 0.f, 0.f};
      #pragma unroll
      for (int q = 0; q < 16; q++) {
        float4 v = sm4[q][tw];
        a.x += v.x; a.y += v.y; a.z += v.z; a.w += v.w;
      }
      const float inv = 1.0f / NH;
      a.x *= inv; a.y *= inv; a.z *= inv; a.w *= inv;
      *(float4*)&xbv[tw * 4] = a;
      *(float4*)&g_xbar[b][c][tw * 4] = a;     // coalesced f32
    }
    __syncthreads();
    if (t < 16)
      x1s[t] = 0.25f * (xbv[4*t] + xbv[4*t+1] + xbv[4*t+2] + xbv[4*t+3])
               + pe[pidx[t] * NC + c];
    __syncthreads();
    if (t < NW) {
      float src = (t * 15.0f) / 63.0f;
      int   i0  = (int)floorf(src);
      int   i1  = min(i0 + 1, 15);
      float tt  = src - (float)i0;
      g_x2df[b][c][t] = x1s[i0] * (1.0f - tt) + x1s[i1] * tt;   // coalesced f32
    }
    return;
  }

  if (bx < 2112) {                     // ---------------- G = Wq^T Wk ----------
    int gx = bx - 2048;
    int cx = gx & 7, kx = gx >> 3;
    unsigned sb = (unsigned)__cvta_generic_to_shared(gsm);
    int wid = t >> 5, lane = t & 31;
    int my = (wid >> 2) * 32, nw = (wid & 3) * 16;
    int gI = lane >> 2, tq = lane & 3;
    float acc[2][2][4] = {};
    int oo = t >> 3, gg = t & 7;
    for (int o0 = 0; o0 < CKQ; o0 += 32) {
      #pragma unroll
      for (int j = 0; j < 2; j++) {
        float4 v = *(const float4*)&Wq[(size_t)(o0 + oo) * NC + cx * 64 + gg * 8 + j * 4];
        float a4[4] = {v.x, v.y, v.z, v.w};
        #pragma unroll
        for (int e = 0; e < 4; e++) {
          int cl = gg * 8 + j * 4 + e;
          __nv_bfloat16 h, l; split_bf(a4[e], h, l);
          ((__nv_bfloat16*)(gsm + GA_H))[cl * 40 + oo] = h;
          ((__nv_bfloat16*)(gsm + GA_L))[cl * 40 + oo] = l;
        }
        float4 w = *(const float4*)&Wk[(size_t)(o0 + oo) * NC + kx * 64 + gg * 8 + j * 4];
        float b4[4] = {w.x, w.y, w.z, w.w};
        #pragma unroll
        for (int e = 0; e < 4; e++) {
          int cl = gg * 8 + j * 4 + e;
          __nv_bfloat16 h, l; split_bf(b4[e], h, l);
          ((__nv_bfloat16*)(gsm + GB_H))[cl * 40 + oo] = h;
          ((__nv_bfloat16*)(gsm + GB_L))[cl * 40 + oo] = l;
        }
      }
      __syncthreads();
      #pragma unroll
      for (int ks = 0; ks < 32; ks += 16) {
        unsigned Ah[2][4], Al[2][4];
        #pragma unroll
        for (int mt = 0; mt < 2; mt++) {
          unsigned row = my + mt * 16 + (lane & 15);
          unsigned coff = ks * 2 + ((lane >> 4) << 4);
          ldsm4(Ah[mt][0], Ah[mt][1], Ah[mt][2], Ah[mt][3], sb + GA_H + row * 80 + coff);
          ldsm4(Al[mt][0], Al[mt][1], Al[mt][2], Al[mt][3], sb + GA_L + row * 80 + coff);
        }
        unsigned Bh[4], Bl[4];
        {
          unsigned row = nw + (lane & 7) + ((lane & 16) >> 1);
          unsigned coff = ks * 2 + ((lane & 8) << 1);
          ldsm4(Bh[0], Bh[1], Bh[2], Bh[3], sb + GB_H + row * 80 + coff);
          ldsm4(Bl[0], Bl[1], Bl[2], Bl[3], sb + GB_L + row * 80 + coff);
        }
        #pragma unroll
        for (int mt = 0; mt < 2; mt++)
          #pragma unroll
          for (int sub = 0; sub < 2; sub++) {
            mma16816(acc[mt][sub], Ah[mt], Bh[sub * 2], Bh[sub * 2 + 1]);
            mma16816(acc[mt][sub], Ah[mt], Bl[sub * 2], Bl[sub * 2 + 1]);
            mma16816(acc[mt][sub], Al[mt], Bh[sub * 2], Bh[sub * 2 + 1]);
          }
      }
      __syncthreads();
    }
    #pragma unroll
    for (int mt = 0; mt < 2; mt++)
      #pragma unroll
      for (int nt = 0; nt < 2; nt++) {
        int cg = cx * 64 + my + mt * 16 + gI;
        int kg = kx * 64 + nw + nt * 8 + 2 * tq;
        split_bf(acc[mt][nt][0], g_Gh[cg][kg],     g_Gl[cg][kg]);
        split_bf(acc[mt][nt][1], g_Gh[cg][kg + 1], g_Gl[cg][kg + 1]);
        split_bf(acc[mt][nt][2], g_Gh[cg + 8][kg],     g_Gl[cg + 8][kg]);
        split_bf(acc[mt][nt][3], g_Gh[cg + 8][kg + 1], g_Gl[cg + 8][kg + 1]);
      }
    return;
  }

  if (bx < 2144) {                     // ---------------- Wv convert -----------
    int base = (bx - 2112) * 2048;
    #pragma unroll
    for (int j = 0; j < 8; j++) {
      int idx4 = base + j * 256 + t;
      float4 v = ((const float4*)Wv)[idx4];
      __nv_bfloat16 h0, l0, h1, l1;
      split_bf(v.x, h0, l0); split_bf(v.y, h1, l1);
      ((__nv_bfloat162*)g_Wvh)[idx4 * 2] = {h0, h1};
      ((__nv_bfloat162*)g_Wvl)[idx4 * 2] = {l0, l1};
      split_bf(v.z, h0, l0); split_bf(v.w, h1, l1);
      ((__nv_bfloat162*)g_Wvh)[idx4 * 2 + 1] = {h0, h1};
      ((__nv_bfloat162*)g_Wvl)[idx4 * 2 + 1] = {l0, l1};
    }
    return;
  }

  // ---------------- bias block -----------------------------------------------
  {
    #pragma unroll
    for (int half = 0; half < 2; half++) {
      int c = t + half * 256;
      float s1 = 0.f, s2 = 0.f;
      for (int o = 0; o < CKQ; o++) {
        s1 += Wq[(size_t)o * NC + c] * bk[o];
        s2 += Wk[(size_t)o * NC + c] * bq[o];
      }
      g_v1[c] = s1;
      g_v2[c] = s2;
    }
    if (t == 0) {
      float s = 0.f;
      for (int o = 0; o < CKQ; o++) s += bq[o] * bk[o];
      g_s0 = s;
    }
  }
}

// =============================================================================
// k_trans: smem transpose f32 [c][w] -> bf16 hi/lo [w][c], coalesced both ways
// grid 32 = (b, cgroup of 64)
// =============================================================================
__global__ __launch_bounds__(256)
void k_trans() {
  __shared__ float Sxb[64][68];
  __shared__ float Sx2[64][68];
  int bx = blockIdx.x;
  int b = bx >> 3, c0 = (bx & 7) * 64;
  int t = threadIdx.x;
  int cl = t >> 2, q = t & 3;
  #pragma unroll
  for (int i = 0; i < 4; i++) {
    *(float4*)&Sxb[cl][q * 16 + i * 4] = *(const float4*)&g_xbar[b][c0 + cl][q * 16 + i * 4];
    *(float4*)&Sx2[cl][q * 16 + i * 4] = *(const float4*)&g_x2df[b][c0 + cl][q * 16 + i * 4];
  }
  __syncthreads();
  int w = t >> 2, qc = t & 3;
  __nv_bfloat162 xh[8], xl[8], bh[8], bl[8];
  #pragma unroll
  for (int i = 0; i < 8; i++) {
    int c = qc * 16 + 2 * i;
    __nv_bfloat16 h0, l0, h1, l1;
    split_bf(Sx2[c][w], h0, l0); split_bf(Sx2[c + 1][w], h1, l1);
    xh[i] = {h0, h1}; xl[i] = {l0, l1};
    split_bf(Sxb[c][w], h0, l0); split_bf(Sxb[c + 1][w], h1, l1);
    bh[i] = {h0, h1}; bl[i] = {l0, l1};
  }
  int cb = c0 + qc * 16;
  *(uint4*)&g_x2dTh[b][w][cb]      = *(uint4*)&xh[0];
  *(uint4*)&g_x2dTh[b][w][cb + 8]  = *(uint4*)&xh[4];
  *(uint4*)&g_x2dTl[b][w][cb]      = *(uint4*)&xl[0];
  *(uint4*)&g_x2dTl[b][w][cb + 8]  = *(uint4*)&xl[4];
  *(uint4*)&g_xbarTh[b][w][cb]     = *(uint4*)&bh[0];
  *(uint4*)&g_xbarTh[b][w][cb + 8] = *(uint4*)&bh[4];
  *(uint4*)&g_xbarTl[b][w][cb]     = *(uint4*)&bl[0];
  *(uint4*)&g_xbarTl[b][w][cb + 8] = *(uint4*)&bl[4];
}

// =============================================================================
// k_MV: [0,32) M^T tiles | [32,64) vbar tiles | [64,68) dw
// =============================================================================
#define MV_SAH 0
#define MV_SAL 9216
#define MV_SBH 18432
#define MV_SBL 27648
#define MV_BUF 36864
#define MV_SMEM 73728

__global__ __launch_bounds__(256)
void k_MV(const float* __restrict__ bv) {
  extern __shared__ char dsm[];
  unsigned sb = (unsigned)__cvta_generic_to_shared(dsm);
  int bx = blockIdx.x, tid = threadIdx.x;

  if (bx >= 64) {                      // dw
    int b = bx - 64;
    int w = tid >> 2, q = tid & 3;
    float s = 0.f;
    for (int c = q * 128; c < q * 128 + 128; c++)
      s += (__bfloat162float(g_x2dTh[b][w][c]) + __bfloat162float(g_x2dTl[b][w][c]))
           * g_v2[c];
    s += __shfl_xor_sync(0xffffffffu, s, 1);
    s += __shfl_xor_sync(0xffffffffu, s, 2);
    if (q == 0) g_dw[b][w] = s + g_s0;
    return;
  }

  bool mtr = (bx < 32);
  int b  = mtr ? (bx >> 3) : ((bx - 32) >> 3);
  int c0 = (mtr ? (bx & 7) : ((bx - 32) & 7)) * 64;
  const __nv_bfloat16 *Ahg, *Alg, *Bhg, *Blg;
  if (mtr) { Ahg = &g_x2dTh[b][0][0];  Alg = &g_x2dTl[b][0][0];
             Bhg = &g_Gh[c0][0];       Blg = &g_Gl[c0][0]; }
  else     { Ahg = &g_Wvh[c0][0];      Alg = &g_Wvl[c0][0];
             Bhg = &g_xbarTh[b][0][0]; Blg = &g_xbarTl[b][0][0]; }

  auto issue = [&](int k0, unsigned base) {
    #pragma unroll
    for (int u = tid; u < 512; u += 256) {
      int r = u >> 3, q = u & 7;
      cp16(sb + base + MV_SAH + r * 144 + q * 16, Ahg + r * NC + k0 + q * 8);
      cp16(sb + base + MV_SAL + r * 144 + q * 16, Alg + r * NC + k0 + q * 8);
      cp16(sb + base + MV_SBH + r * 144 + q * 16, Bhg + r * NC + k0 + q * 8);
      cp16(sb + base + MV_SBL + r * 144 + q * 16, Blg + r * NC + k0 + q * 8);
    }
  };

  int wid = tid >> 5, lane = tid & 31;
  int my = (wid >> 2) * 32, nw = (wid & 3) * 16;
  int gI = lane >> 2, tq = lane & 3;
  float acc[2][2][4] = {};

  issue(0, 0); CP_COMMIT();
  for (int kc = 0; kc < 8; kc++) {
    if (kc < 7) {
      issue((kc + 1) * 64, ((kc + 1) & 1) * MV_BUF); CP_COMMIT();
      CP_WAIT(1);
    } else {
      CP_WAIT(0);
    }
    __syncthreads();
    unsigned base = (kc & 1) * MV_BUF;
    #pragma unroll
    for (int ks = 0; ks < 64; ks += 16) {
      unsigned Fh[2][4], Fl[2][4];
      #pragma unroll
      for (int mt = 0; mt < 2; mt++) {
        unsigned row = my + mt * 16 + (lane & 15);
        unsigned coff = ks * 2 + ((lane >> 4) << 4);
        ldsm4(Fh[mt][0], Fh[mt][1], Fh[mt][2], Fh[mt][3], sb + base + MV_SAH + row * 144 + coff);
        ldsm4(Fl[mt][0], Fl[mt][1], Fl[mt][2], Fl[mt][3], sb + base + MV_SAL + row * 144 + coff);
      }
      unsigned Gh4[4], Gl4[4];
      {
        unsigned row = nw + (lane & 7) + ((lane & 16) >> 1);
        unsigned coff = ks * 2 + ((lane & 8) << 1);
        ldsm4(Gh4[0], Gh4[1], Gh4[2], Gh4[3], sb + base + MV_SBH + row * 144 + coff);
        ldsm4(Gl4[0], Gl4[1], Gl4[2], Gl4[3], sb + base + MV_SBL + row * 144 + coff);
      }
      #pragma unroll
      for (int mt = 0; mt < 2; mt++)
        #pragma unroll
        for (int sub = 0; sub < 2; sub++) {
          mma16816(acc[mt][sub], Fh[mt], Gh4[sub * 2], Gh4[sub * 2 + 1]);
          mma16816(acc[mt][sub], Fh[mt], Gl4[sub * 2], Gl4[sub * 2 + 1]);
          mma16816(acc[mt][sub], Fl[mt], Gh4[sub * 2], Gh4[sub * 2 + 1]);
        }
    }
    __syncthreads();
  }

  if (mtr) {
    #pragma unroll
    for (int mt = 0; mt < 2; mt++)
      #pragma unroll
      for (int nt = 0; nt < 2; nt++) {
        int w = my + mt * 16 + gI;
        int c = c0 + nw + nt * 8 + 2 * tq;
        split_bf(acc[mt][nt][0] + g_v1[c],     g_MTh[b][w][c],     g_MTl[b][w][c]);
        split_bf(acc[mt][nt][1] + g_v1[c + 1], g_MTh[b][w][c + 1], g_MTl[b][w][c + 1]);
        split_bf(acc[mt][nt][2] + g_v1[c],     g_MTh[b][w + 8][c],     g_MTl[b][w + 8][c]);
        split_bf(acc[mt][nt][3] + g_v1[c + 1], g_MTh[b][w + 8][c + 1], g_MTl[b][w + 8][c + 1]);
      }
  } else {
    #pragma unroll
    for (int mt = 0; mt < 2; mt++)
      #pragma unroll
      for (int nt = 0; nt < 2; nt++) {
        int c = c0 + my + mt * 16 + gI;
        int w = nw + nt * 8 + 2 * tq;
        float bv0 = bv[c], bv8 = bv[c + 8];
        split_bf(acc[mt][nt][0] + bv0, g_vbh[b][c][w],     g_vbl[b][c][w]);
        split_bf(acc[mt][nt][1] + bv0, g_vbh[b][c][w + 1], g_vbl[b][c][w + 1]);
        split_bf(acc[mt][nt][2] + bv8, g_vbh[b][c + 8][w],     g_vbl[b][c + 8][w]);
        split_bf(acc[mt][nt][3] + bv8, g_vbh[b][c + 8][w + 1], g_vbl[b][c + 8][w + 1]);
      }
  }
}

// =============================================================================
// k_fused: E = x^T M + dw, softmax, out = gamma*(vbar@A^T)+x
// =============================================================================
#define XA0 0
#define XASTRIDE 20480
#define MB0 40960
#define MBSZ 10240
#define EF_OFF 61440
#define ATT_H 0
#define ATT_L 18432
#define VB0 96256
#define VBSZ 36864
#define SMEM_FUSED 169984

__global__ __launch_bounds__(256)
void k_fused(const float* __restrict__ x, const float* __restrict__ gamma,
             float* __restrict__ out) {
  extern __shared__ char sm[];
  unsigned sb = (unsigned)__cvta_generic_to_shared(sm);
  int tid = threadIdx.x;
  int wid = tid >> 5, lane = tid & 31;
  int b = blockIdx.y;
  int n0 = blockIdx.x * 128;
  int gI = lane >> 2, tq = lane & 3;

  const float* xb = x + (size_t)b * NC * NN + n0;
  int lc2a = tid >> 5, ln4a = tid & 31;
  int lc2b = (tid + 256) >> 5, ln4b = tid & 31;
  int mw = tid >> 2, mq = tid & 3;

  auto load_x = [&](float4 (&xr)[4], int c0) {
    const float* p0 = xb + (size_t)(c0 + 2 * lc2a) * NN + ln4a * 4;
    xr[0] = *(const float4*)p0;
    xr[1] = *(const float4*)(p0 + NN);
    const float* p1 = xb + (size_t)(c0 + 2 * lc2b) * NN + ln4b * 4;
    xr[2] = *(const float4*)p1;
    xr[3] = *(const float4*)(p1 + NN);
  };
  auto store_x = [&](float4 (&xr)[4], unsigned xbase) {
    #pragma unroll
    for (int z = 0; z < 2; z++) {
      int c2 = z ? lc2b : lc2a;
      int n4 = z ? ln4b : ln4a;
      float a0[4] = {xr[2*z].x, xr[2*z].y, xr[2*z].z, xr[2*z].w};
      float a1[4] = {xr[2*z+1].x, xr[2*z+1].y, xr[2*z+1].z, xr[2*z+1].w};
      #pragma unroll
      for (int j = 0; j < 4; j++) {
        int n = n4 * 4 + j;
        float h0 = __bfloat162float(__float2bfloat16(a0[j]));
        float h1 = __bfloat162float(__float2bfloat16(a1[j]));
        ((unsigned*)(sm + xbase))[n * 20 + c2]         = pack_bf2(a0[j], a1[j]);
        ((unsigned*)(sm + xbase + 10240))[n * 20 + c2] = pack_bf2(a0[j] - h0, a1[j] - h1);
      }
    }
  };
  auto issue_M = [&](int c0, unsigned mb) {
    cp16(sb + mb + mw * 80 + mq * 16,        &g_MTh[b][mw][c0 + mq * 8]);
    cp16(sb + mb + 5120 + mw * 80 + mq * 16, &g_MTl[b][mw][c0 + mq * 8]);
  };
  auto issue_VB = [&](int cc, unsigned base) {
    #pragma unroll
    for (int it2 = tid; it2 < 1024; it2 += 256) {
      int rr = it2 >> 3, q = it2 & 7;
      cp16(sb + base + rr * 144 + q * 16,         &g_vbh[b][cc * 128 + rr][q * 8]);
      cp16(sb + base + 18432 + rr * 144 + q * 16, &g_vbl[b][cc * 128 + rr][q * 8]);
    }
  };

  // ---------------- phase 1 ---------------------------------------------------
  int ny = (wid >> 1) * 32;
  int wy = (wid & 1) * 32;
  float acc1[2][4][4] = {};

  auto mma_chunk = [&](unsigned xab, unsigned mbb) {
    #pragma unroll
    for (int ks = 0; ks < 32; ks += 16) {
      unsigned Ah[2][4], Al[2][4];
      #pragma unroll
      for (int mt = 0; mt < 2; mt++) {
        unsigned row = ny + mt * 16 + (lane & 15);
        unsigned coff = ks * 2 + ((lane >> 4) << 4);
        ldsm4(Ah[mt][0], Ah[mt][1], Ah[mt][2], Ah[mt][3], sb + xab + row * 80 + coff);
        ldsm4(Al[mt][0], Al[mt][1], Al[mt][2], Al[mt][3], sb + xab + 10240 + row * 80 + coff);
      }
      unsigned Bh[2][4], Bl[2][4];
      #pragma unroll
      for (int bt = 0; bt < 2; bt++) {
        unsigned row = wy + bt * 16 + (lane & 7) + ((lane & 16) >> 1);
        unsigned coff = ks * 2 + ((lane & 8) << 1);
        ldsm4(Bh[bt][0], Bh[bt][1], Bh[bt][2], Bh[bt][3], sb + mbb + row * 80 + coff);
        ldsm4(Bl[bt][0], Bl[bt][1], Bl[bt][2], Bl[bt][3], sb + mbb + 5120 + row * 80 + coff);
      }
      #pragma unroll
      for (int mt = 0; mt < 2; mt++)
        #pragma unroll
        for (int bt = 0; bt < 2; bt++)
          #pragma unroll
          for (int sub = 0; sub < 2; sub++) {
            int wt = bt * 2 + sub;
            mma16816(acc1[mt][wt], Ah[mt], Bh[bt][sub * 2], Bh[bt][sub * 2 + 1]);
            mma16816(acc1[mt][wt], Ah[mt], Bl[bt][sub * 2], Bl[bt][sub * 2 + 1]);
            mma16816(acc1[mt][wt], Al[mt], Bh[bt][sub * 2], Bh[bt][sub * 2 + 1]);
          }
    }
  };

  float4 xrA[4], xrB[4];
  load_x(xrA, 0);
  load_x(xrB, 32);
  issue_M(0, MB0); CP_COMMIT();
  store_x(xrA, XA0);
  CP_WAIT(0);
  __syncthreads();

  auto step = [&](int i, float4 (&nxt)[4], float4 (&sto)[4]) {
    if (i < 14) load_x(nxt, (i + 2) * 32);
    if (i < 15) { issue_M((i + 1) * 32, MB0 + ((i + 1) & 1) * MBSZ); CP_COMMIT(); }
    mma_chunk(XA0 + (i & 1) * XASTRIDE, MB0 + (i & 1) * MBSZ);
    if (i < 15) {
      store_x(sto, XA0 + ((i + 1) & 1) * XASTRIDE);
      CP_WAIT(0);
    }
    __syncthreads();
  };
  for (int i2 = 0; i2 < 16; i2 += 2) {
    step(i2, xrA, xrB);
    step(i2 + 1, xrB, xrA);
  }

  issue_VB(0, VB0);
  CP_COMMIT();

  float* Ef = (float*)(sm + EF_OFF);
  #pragma unroll
  for (int wt = 0; wt < 4; wt++) {
    int wc = wy + wt * 8 + 2 * tq;
    float d0 = g_dw[b][wc], d1 = g_dw[b][wc + 1];
    #pragma unroll
    for (int mt = 0; mt < 2; mt++) {
      int r = ny + mt * 16 + gI;
      float2 v0 = {acc1[mt][wt][0] + d0, acc1[mt][wt][1] + d1};
      float2 v1 = {acc1[mt][wt][2] + d0, acc1[mt][wt][3] + d1};
      *(float2*)&Ef[r * 68 + wc] = v0;
      *(float2*)&Ef[(r + 8) * 68 + wc] = v1;
    }
  }
  __syncthreads();

  {
    int row = tid >> 1, q = tid & 1;
    float mx = -1e30f;
    for (int w = q; w < NW; w += 2) mx = fmaxf(mx, Ef[row * 68 + w]);
    mx = fmaxf(mx, __shfl_xor_sync(0xffffffffu, mx, 1));
    float s = 0.f;
    for (int w = q; w < NW; w += 2) {
      float e = __expf(Ef[row * 68 + w] - mx);
      Ef[row * 68 + w] = e;
      s += e;
    }
    s += __shfl_xor_sync(0xffffffffu, s, 1);
    float inv = 1.0f / s;
    for (int w = q; w < NW; w += 2) Ef[row * 68 + w] *= inv;
  }
  __syncthreads();

  #pragma unroll
  for (int i = 0; i < 16; i++) {
    int p = tid + i * 256;
    int n = p >> 5, wp = p & 31;
    float e0 = Ef[n * 68 + 2 * wp], e1 = Ef[n * 68 + 2 * wp + 1];
    float h0 = __bfloat162float(__float2bfloat16(e0));
    float h1 = __bfloat162float(__float2bfloat16(e1));
    ((unsigned*)(sm + ATT_H))[n * 36 + wp] = pack_bf2(e0, e1);
    ((unsigned*)(sm + ATT_L))[n * 36 + wp] = pack_bf2(e0 - h0, e1 - h1);
  }

  // ---------------- phase 2 ---------------------------------------------------
  float g = gamma[0];
  int cy = (wid >> 1) * 32;
  int nx = (wid & 1) * 64;
  for (int cc = 0; cc < 4; cc++) {
    if (cc < 3) {
      issue_VB(cc + 1, VB0 + ((cc + 1) & 1) * VBSZ);
      CP_COMMIT();
      CP_WAIT(1);
    } else {
      CP_WAIT(0);
    }
    __syncthreads();

    unsigned vbb = VB0 + (cc & 1) * VBSZ;
    float acc2[2][8][4] = {};
    #pragma unroll
    for (int ks = 0; ks < 64; ks += 16) {
      unsigned Ah[2][4], Al[2][4];
      #pragma unroll
      for (int mt = 0; mt < 2; mt++) {
        unsigned row = cy + mt * 16 + (lane & 15);
        unsigned coff = ks * 2 + ((lane >> 4) << 4);
        ldsm4(Ah[mt][0], Ah[mt][1], Ah[mt][2], Ah[mt][3], sb + vbb + row * 144 + coff);
        ldsm4(Al[mt][0], Al[mt][1], Al[mt][2], Al[mt][3], sb + vbb + 18432 + row * 144 + coff);
      }
      unsigned Bh[4][4], Bl[4][4];
      #pragma unroll
      for (int bt = 0; bt < 4; bt++) {
        unsigned row = nx + bt * 16 + (lane & 7) + ((lane & 16) >> 1);
        unsigned coff = ks * 2 + ((lane & 8) << 1);
        ldsm4(Bh[bt][0], Bh[bt][1], Bh[bt][2], Bh[bt][3], sb + ATT_H + row * 144 + coff);
        ldsm4(Bl[bt][0], Bl[bt][1], Bl[bt][2], Bl[bt][3], sb + ATT_L + row * 144 + coff);
      }
      #pragma unroll
      for (int mt = 0; mt < 2; mt++)
        #pragma unroll
        for (int bt = 0; bt < 4; bt++)
          #pragma unroll
          for (int sub = 0; sub < 2; sub++) {
            int nt = bt * 2 + sub;
            mma16816(acc2[mt][nt], Ah[mt], Bh[bt][sub * 2], Bh[bt][sub * 2 + 1]);
            mma16816(acc2[mt][nt], Ah[mt], Bl[bt][sub * 2], Bl[bt][sub * 2 + 1]);
            mma16816(acc2[mt][nt], Al[mt], Bh[bt][sub * 2], Bh[bt][sub * 2 + 1]);
          }
    }
    #pragma unroll
    for (int mt = 0; mt < 2; mt++) {
      int c = cc * 128 + cy + mt * 16 + gI;
      #pragma unroll
      for (int nt = 0; nt < 8; nt++) {
        int n = n0 + nx + nt * 8 + 2 * tq;
        size_t off = ((size_t)(b * NC + c)) * NN + n;
        float2 xv0 = *(const float2*)(x + off);
        float2 xv1 = *(const float2*)(x + off + (size_t)8 * NN);
        float2 o0 = {fmaf(g, acc2[mt][nt][0], xv0.x), fmaf(g, acc2[mt][nt][1], xv0.y)};
        float2 o1 = {fmaf(g, acc2[mt][nt][2], xv1.x), fmaf(g, acc2[mt][nt][3], xv1.y)};
        *(float2*)(out + off) = o0;
        *(float2*)(out + off + (size_t)8 * NN) = o1;
      }
    }
    __syncthreads();
  }
}

// ---------------- launch -----------------------------------------------------
extern "C" void kernel_launch(void* const* d_in, const int* in_sizes, int n_in,
                              void* d_out, int out_size) {
  const float* x     = (const float*)d_in[0];
  const float* Wq    = (const float*)d_in[1];
  const float* bq    = (const float*)d_in[2];
  const float* Wk    = (const float*)d_in[3];
  const float* bk    = (const float*)d_in[4];
  const float* Wv    = (const float*)d_in[5];
  const float* bv    = (const float*)d_in[6];
  const float* gamma = (const float*)d_in[7];
  const float* pe    = (const float*)d_in[8];
  const int*   pos   = (const int*)  d_in[9];
  float* out = (float*)d_out;

  cudaFuncSetAttribute(k_MV, cudaFuncAttributeMaxDynamicSharedMemorySize, MV_SMEM);
  cudaFuncSetAttribute(k_fused, cudaFuncAttributeMaxDynamicSharedMemorySize,
                       SMEM_FUSED);

  k_front<<<2145, 256>>>(x, pos, pe, Wq, Wk, Wv, bq, bk);
  k_trans<<<32, 256>>>();
  k_MV<<<68, 256, MV_SMEM>>>(bv);
  k_fused<<<dim3(NN / 128, NB), 256, SMEM_FUSED>>>(x, gamma, out);
}

// round 10
// speedup vs baseline: 1.1299x; 1.1299x over previous
#include <cuda_runtime.h>
#include <cuda_bf16.h>

#define NB 4
#define NC 512
#define CKQ 256
#define NW 64
#define NH 64
#define NN 4096   // H*W

// ---------------- scratch (device globals) ----------------------------------
__device__ float g_xbar[NB][NC][NW];            // mean_h x (f32, coalesced)
__device__ float g_x2df[NB][NC][NW];            // interpolated PE row (f32)
__device__ __align__(16) __nv_bfloat16 g_x2dTh[NB][NW][NC], g_x2dTl[NB][NW][NC];
__device__ __align__(16) __nv_bfloat16 g_xbarTh[NB][NW][NC], g_xbarTl[NB][NW][NC];
__device__ __align__(16) __nv_bfloat16 g_Gh[NC][NC], g_Gl[NC][NC];
__device__ __align__(16) __nv_bfloat16 g_Wvh[NC][NC], g_Wvl[NC][NC];
__device__ __align__(16) __nv_bfloat16 g_MTh[NB][NW][NC], g_MTl[NB][NW][NC];
__device__ __align__(16) __nv_bfloat16 g_vbh[NB][NC][NW], g_vbl[NB][NC][NW];
__device__ float g_v1[NC];        // Wq^T bk
__device__ float g_v2[NC];        // Wk^T bq
__device__ float g_s0;            // bq . bk
__device__ float g_dw[NB][NW];

// ---------------- helpers ----------------------------------------------------
__device__ __forceinline__ unsigned pack_bf2(float e, float o) {
  __nv_bfloat162 h;
  h.x = __float2bfloat16(e);
  h.y = __float2bfloat16(o);
  return *reinterpret_cast<unsigned*>(&h);
}
__device__ __forceinline__ void split_bf(float v, __nv_bfloat16& h, __nv_bfloat16& l) {
  h = __float2bfloat16(v);
  l = __float2bfloat16(v - __bfloat162float(h));
}
// 4 consecutive values -> hi pair-packed uint2 + lo pair-packed uint2
__device__ __forceinline__ void hilo2(const float* a, uint2& h, uint2& l) {
  float h0 = __bfloat162float(__float2bfloat16(a[0]));
  float h1 = __bfloat162float(__float2bfloat16(a[1]));
  float h2 = __bfloat162float(__float2bfloat16(a[2]));
  float h3 = __bfloat162float(__float2bfloat16(a[3]));
  h.x = pack_bf2(a[0], a[1]);
  h.y = pack_bf2(a[2], a[3]);
  l.x = pack_bf2(a[0] - h0, a[1] - h1);
  l.y = pack_bf2(a[2] - h2, a[3] - h3);
}
__device__ __forceinline__ void ldsm4(unsigned& r0, unsigned& r1, unsigned& r2,
                                      unsigned& r3, unsigned addr) {
  asm volatile("ldmatrix.sync.aligned.m8n8.x4.shared.b16 {%0,%1,%2,%3},[%4];"
               : "=r"(r0), "=r"(r1), "=r"(r2), "=r"(r3) : "r"(addr));
}
__device__ __forceinline__ void ldsm4t(unsigned& r0, unsigned& r1, unsigned& r2,
                                       unsigned& r3, unsigned addr) {
  asm volatile("ldmatrix.sync.aligned.m8n8.x4.trans.shared.b16 {%0,%1,%2,%3},[%4];"
               : "=r"(r0), "=r"(r1), "=r"(r2), "=r"(r3) : "r"(addr));
}
__device__ __forceinline__ void mma16816(float* d, const unsigned* a,
                                         unsigned b0, unsigned b1) {
  asm volatile(
    "mma.sync.aligned.m16n8k16.row.col.f32.bf16.bf16.f32 "
    "{%0,%1,%2,%3},{%4,%5,%6,%7},{%8,%9},{%0,%1,%2,%3};"
    : "+f"(d[0]), "+f"(d[1]), "+f"(d[2]), "+f"(d[3])
    : "r"(a[0]), "r"(a[1]), "r"(a[2]), "r"(a[3]), "r"(b0), "r"(b1));
}
__device__ __forceinline__ void cp16(unsigned saddr, const void* g) {
  asm volatile("cp.async.cg.shared.global [%0],[%1],16;" :: "r"(saddr), "l"(g));
}
#define CP_COMMIT() asm volatile("cp.async.commit_group;")
#define CP_WAIT(n)  asm volatile("cp.async.wait_group %0;" :: "n"(n))

// =============================================================================
// k_front: [0,2048) prep | [2048,2112) G=Wq^T Wk | [2112,2144) Wv conv | 2144 bias
// =============================================================================
#define GA_H 0
#define GA_L 5120
#define GB_H 10240
#define GB_L 15360

__global__ __launch_bounds__(256)
void k_front(const float* __restrict__ x, const int* __restrict__ pos,
             const float* __restrict__ pe, const float* __restrict__ Wq,
             const float* __restrict__ Wk, const float* __restrict__ Wv,
             const float* __restrict__ bq, const float* __restrict__ bk) {
  __shared__ float4 sm4[16][16];
  __shared__ float xbv[64];
  __shared__ float x1s[16];
  __shared__ int pidx[16];
  __shared__ __align__(16) char gsm[20480];

  int bx = blockIdx.x;
  int t = threadIdx.x;

  if (bx < 2048) {                     // ---------------- prep ----------------
    int c = bx & 511, b = bx >> 9;
    int hq = t >> 4, tw = t & 15;
    const float* xp = x + ((size_t)(b * NC + c)) * NH * NW;
    float4 s = {0.f, 0.f, 0.f, 0.f};
    #pragma unroll
    for (int h = hq; h < NH; h += 16) {
      float4 v = *(const float4*)&xp[h * NW + tw * 4];
      s.x += v.x; s.y += v.y; s.z += v.z; s.w += v.w;
    }
    sm4[hq][tw] = s;
    if (t < 16) pidx[t] = pos[b * NN + 4 * t] >> 3;
    __syncthreads();
    if (hq == 0) {
      float4 a = {0.f, 0.f, 0.f, 0.f};
      #pragma unroll
      for (int q = 0; q < 16; q++) {
        float4 v = sm4[q][tw];
        a.x += v.x; a.y += v.y; a.z += v.z; a.w += v.w;
      }
      const float inv = 1.0f / NH;
      a.x *= inv; a.y *= inv; a.z *= inv; a.w *= inv;
      *(float4*)&xbv[tw * 4] = a;
      *(float4*)&g_xbar[b][c][tw * 4] = a;
    }
    __syncthreads();
    if (t < 16)
      x1s[t] = 0.25f * (xbv[4*t] + xbv[4*t+1] + xbv[4*t+2] + xbv[4*t+3])
               + pe[pidx[t] * NC + c];
    __syncthreads();
    if (t < NW) {
      float src = (t * 15.0f) / 63.0f;
      int   i0  = (int)floorf(src);
      int   i1  = min(i0 + 1, 15);
      float tt  = src - (float)i0;
      g_x2df[b][c][t] = x1s[i0] * (1.0f - tt) + x1s[i1] * tt;
    }
    return;
  }

  if (bx < 2112) {                     // ---------------- G = Wq^T Wk ----------
    int gx = bx - 2048;
    int cx = gx & 7, kx = gx >> 3;
    unsigned sb = (unsigned)__cvta_generic_to_shared(gsm);
    int wid = t >> 5, lane = t & 31;
    int my = (wid >> 2) * 32, nw = (wid & 3) * 16;
    int gI = lane >> 2, tq = lane & 3;
    float acc[2][2][4] = {};
    int oo = t >> 3, gg = t & 7;
    for (int o0 = 0; o0 < CKQ; o0 += 32) {
      #pragma unroll
      for (int j = 0; j < 2; j++) {
        float4 v = *(const float4*)&Wq[(size_t)(o0 + oo) * NC + cx * 64 + gg * 8 + j * 4];
        float a4[4] = {v.x, v.y, v.z, v.w};
        #pragma unroll
        for (int e = 0; e < 4; e++) {
          int cl = gg * 8 + j * 4 + e;
          __nv_bfloat16 h, l; split_bf(a4[e], h, l);
          ((__nv_bfloat16*)(gsm + GA_H))[cl * 40 + oo] = h;
          ((__nv_bfloat16*)(gsm + GA_L))[cl * 40 + oo] = l;
        }
        float4 w = *(const float4*)&Wk[(size_t)(o0 + oo) * NC + kx * 64 + gg * 8 + j * 4];
        float b4[4] = {w.x, w.y, w.z, w.w};
        #pragma unroll
        for (int e = 0; e < 4; e++) {
          int cl = gg * 8 + j * 4 + e;
          __nv_bfloat16 h, l; split_bf(b4[e], h, l);
          ((__nv_bfloat16*)(gsm + GB_H))[cl * 40 + oo] = h;
          ((__nv_bfloat16*)(gsm + GB_L))[cl * 40 + oo] = l;
        }
      }
      __syncthreads();
      #pragma unroll
      for (int ks = 0; ks < 32; ks += 16) {
        unsigned Ah[2][4], Al[2][4];
        #pragma unroll
        for (int mt = 0; mt < 2; mt++) {
          unsigned row = my + mt * 16 + (lane & 15);
          unsigned coff = ks * 2 + ((lane >> 4) << 4);
          ldsm4(Ah[mt][0], Ah[mt][1], Ah[mt][2], Ah[mt][3], sb + GA_H + row * 80 + coff);
          ldsm4(Al[mt][0], Al[mt][1], Al[mt][2], Al[mt][3], sb + GA_L + row * 80 + coff);
        }
        unsigned Bh[4], Bl[4];
        {
          unsigned row = nw + (lane & 7) + ((lane & 16) >> 1);
          unsigned coff = ks * 2 + ((lane & 8) << 1);
          ldsm4(Bh[0], Bh[1], Bh[2], Bh[3], sb + GB_H + row * 80 + coff);
          ldsm4(Bl[0], Bl[1], Bl[2], Bl[3], sb + GB_L + row * 80 + coff);
        }
        #pragma unroll
        for (int mt = 0; mt < 2; mt++)
          #pragma unroll
          for (int sub = 0; sub < 2; sub++) {
            mma16816(acc[mt][sub], Ah[mt], Bh[sub * 2], Bh[sub * 2 + 1]);
            mma16816(acc[mt][sub], Ah[mt], Bl[sub * 2], Bl[sub * 2 + 1]);
            mma16816(acc[mt][sub], Al[mt], Bh[sub * 2], Bh[sub * 2 + 1]);
          }
      }
      __syncthreads();
    }
    #pragma unroll
    for (int mt = 0; mt < 2; mt++)
      #pragma unroll
      for (int nt = 0; nt < 2; nt++) {
        int cg = cx * 64 + my + mt * 16 + gI;
        int kg = kx * 64 + nw + nt * 8 + 2 * tq;
        split_bf(acc[mt][nt][0], g_Gh[cg][kg],     g_Gl[cg][kg]);
        split_bf(acc[mt][nt][1], g_Gh[cg][kg + 1], g_Gl[cg][kg + 1]);
        split_bf(acc[mt][nt][2], g_Gh[cg + 8][kg],     g_Gl[cg + 8][kg]);
        split_bf(acc[mt][nt][3], g_Gh[cg + 8][kg + 1], g_Gl[cg + 8][kg + 1]);
      }
    return;
  }

  if (bx < 2144) {                     // ---------------- Wv convert -----------
    int base = (bx - 2112) * 2048;
    #pragma unroll
    for (int j = 0; j < 8; j++) {
      int idx4 = base + j * 256 + t;
      float4 v = ((const float4*)Wv)[idx4];
      __nv_bfloat16 h0, l0, h1, l1;
      split_bf(v.x, h0, l0); split_bf(v.y, h1, l1);
      ((__nv_bfloat162*)g_Wvh)[idx4 * 2] = {h0, h1};
      ((__nv_bfloat162*)g_Wvl)[idx4 * 2] = {l0, l1};
      split_bf(v.z, h0, l0); split_bf(v.w, h1, l1);
      ((__nv_bfloat162*)g_Wvh)[idx4 * 2 + 1] = {h0, h1};
      ((__nv_bfloat162*)g_Wvl)[idx4 * 2 + 1] = {l0, l1};
    }
    return;
  }

  // ---------------- bias block -----------------------------------------------
  {
    #pragma unroll
    for (int half = 0; half < 2; half++) {
      int c = t + half * 256;
      float s1 = 0.f, s2 = 0.f;
      #pragma unroll 8
      for (int o = 0; o < CKQ; o++) {
        s1 += Wq[(size_t)o * NC + c] * bk[o];
        s2 += Wk[(size_t)o * NC + c] * bq[o];
      }
      g_v1[c] = s1;
      g_v2[c] = s2;
    }
    if (t == 0) {
      float s = 0.f;
      for (int o = 0; o < CKQ; o++) s += bq[o] * bk[o];
      g_s0 = s;
    }
  }
}

// =============================================================================
// k_trans: smem transpose f32 [c][w] -> bf16 hi/lo [w][c]
// =============================================================================
__global__ __launch_bounds__(256)
void k_trans() {
  __shared__ float Sxb[64][68];
  __shared__ float Sx2[64][68];
  int bx = blockIdx.x;
  int b = bx >> 3, c0 = (bx & 7) * 64;
  int t = threadIdx.x;
  int cl = t >> 2, q = t & 3;
  #pragma unroll
  for (int i = 0; i < 4; i++) {
    *(float4*)&Sxb[cl][q * 16 + i * 4] = *(const float4*)&g_xbar[b][c0 + cl][q * 16 + i * 4];
    *(float4*)&Sx2[cl][q * 16 + i * 4] = *(const float4*)&g_x2df[b][c0 + cl][q * 16 + i * 4];
  }
  __syncthreads();
  int w = t >> 2, qc = t & 3;
  __nv_bfloat162 xh[8], xl[8], bh[8], bl[8];
  #pragma unroll
  for (int i = 0; i < 8; i++) {
    int c = qc * 16 + 2 * i;
    __nv_bfloat16 h0, l0, h1, l1;
    split_bf(Sx2[c][w], h0, l0); split_bf(Sx2[c + 1][w], h1, l1);
    xh[i] = {h0, h1}; xl[i] = {l0, l1};
    split_bf(Sxb[c][w], h0, l0); split_bf(Sxb[c + 1][w], h1, l1);
    bh[i] = {h0, h1}; bl[i] = {l0, l1};
  }
  int cb = c0 + qc * 16;
  *(uint4*)&g_x2dTh[b][w][cb]      = *(uint4*)&xh[0];
  *(uint4*)&g_x2dTh[b][w][cb + 8]  = *(uint4*)&xh[4];
  *(uint4*)&g_x2dTl[b][w][cb]      = *(uint4*)&xl[0];
  *(uint4*)&g_x2dTl[b][w][cb + 8]  = *(uint4*)&xl[4];
  *(uint4*)&g_xbarTh[b][w][cb]     = *(uint4*)&bh[0];
  *(uint4*)&g_xbarTh[b][w][cb + 8] = *(uint4*)&bh[4];
  *(uint4*)&g_xbarTl[b][w][cb]     = *(uint4*)&bl[0];
  *(uint4*)&g_xbarTl[b][w][cb + 8] = *(uint4*)&bl[4];
}

// =============================================================================
// k_MV: [0,32) M^T tiles | [32,64) vbar tiles | [64,68) dw
// =============================================================================
#define MV_SAH 0
#define MV_SAL 9216
#define MV_SBH 18432
#define MV_SBL 27648
#define MV_BUF 36864
#define MV_SMEM 73728

__global__ __launch_bounds__(256)
void k_MV(const float* __restrict__ bv) {
  extern __shared__ char dsm[];
  unsigned sb = (unsigned)__cvta_generic_to_shared(dsm);
  int bx = blockIdx.x, tid = threadIdx.x;

  if (bx >= 64) {                      // dw
    int b = bx - 64;
    int w = tid >> 2, q = tid & 3;
    float s = 0.f;
    #pragma unroll 8
    for (int c = q * 128; c < q * 128 + 128; c++)
      s += (__bfloat162float(g_x2dTh[b][w][c]) + __bfloat162float(g_x2dTl[b][w][c]))
           * g_v2[c];
    s += __shfl_xor_sync(0xffffffffu, s, 1);
    s += __shfl_xor_sync(0xffffffffu, s, 2);
    if (q == 0) g_dw[b][w] = s + g_s0;
    return;
  }

  bool mtr = (bx < 32);
  int b  = mtr ? (bx >> 3) : ((bx - 32) >> 3);
  int c0 = (mtr ? (bx & 7) : ((bx - 32) & 7)) * 64;
  const __nv_bfloat16 *Ahg, *Alg, *Bhg, *Blg;
  if (mtr) { Ahg = &g_x2dTh[b][0][0];  Alg = &g_x2dTl[b][0][0];
             Bhg = &g_Gh[c0][0];       Blg = &g_Gl[c0][0]; }
  else     { Ahg = &g_Wvh[c0][0];      Alg = &g_Wvl[c0][0];
             Bhg = &g_xbarTh[b][0][0]; Blg = &g_xbarTl[b][0][0]; }

  auto issue = [&](int k0, unsigned base) {
    #pragma unroll
    for (int u = tid; u < 512; u += 256) {
      int r = u >> 3, q = u & 7;
      cp16(sb + base + MV_SAH + r * 144 + q * 16, Ahg + r * NC + k0 + q * 8);
      cp16(sb + base + MV_SAL + r * 144 + q * 16, Alg + r * NC + k0 + q * 8);
      cp16(sb + base + MV_SBH + r * 144 + q * 16, Bhg + r * NC + k0 + q * 8);
      cp16(sb + base + MV_SBL + r * 144 + q * 16, Blg + r * NC + k0 + q * 8);
    }
  };

  int wid = tid >> 5, lane = tid & 31;
  int my = (wid >> 2) * 32, nw = (wid & 3) * 16;
  int gI = lane >> 2, tq = lane & 3;
  float acc[2][2][4] = {};

  issue(0, 0); CP_COMMIT();
  for (int kc = 0; kc < 8; kc++) {
    if (kc < 7) {
      issue((kc + 1) * 64, ((kc + 1) & 1) * MV_BUF); CP_COMMIT();
      CP_WAIT(1);
    } else {
      CP_WAIT(0);
    }
    __syncthreads();
    unsigned base = (kc & 1) * MV_BUF;
    #pragma unroll
    for (int ks = 0; ks < 64; ks += 16) {
      unsigned Fh[2][4], Fl[2][4];
      #pragma unroll
      for (int mt = 0; mt < 2; mt++) {
        unsigned row = my + mt * 16 + (lane & 15);
        unsigned coff = ks * 2 + ((lane >> 4) << 4);
        ldsm4(Fh[mt][0], Fh[mt][1], Fh[mt][2], Fh[mt][3], sb + base + MV_SAH + row * 144 + coff);
        ldsm4(Fl[mt][0], Fl[mt][1], Fl[mt][2], Fl[mt][3], sb + base + MV_SAL + row * 144 + coff);
      }
      unsigned Gh4[4], Gl4[4];
      {
        unsigned row = nw + (lane & 7) + ((lane & 16) >> 1);
        unsigned coff = ks * 2 + ((lane & 8) << 1);
        ldsm4(Gh4[0], Gh4[1], Gh4[2], Gh4[3], sb + base + MV_SBH + row * 144 + coff);
        ldsm4(Gl4[0], Gl4[1], Gl4[2], Gl4[3], sb + base + MV_SBL + row * 144 + coff);
      }
      #pragma unroll
      for (int mt = 0; mt < 2; mt++)
        #pragma unroll
        for (int sub = 0; sub < 2; sub++) {
          mma16816(acc[mt][sub], Fh[mt], Gh4[sub * 2], Gh4[sub * 2 + 1]);
          mma16816(acc[mt][sub], Fh[mt], Gl4[sub * 2], Gl4[sub * 2 + 1]);
          mma16816(acc[mt][sub], Fl[mt], Gh4[sub * 2], Gh4[sub * 2 + 1]);
        }
    }
    __syncthreads();
  }

  if (mtr) {
    #pragma unroll
    for (int mt = 0; mt < 2; mt++)
      #pragma unroll
      for (int nt = 0; nt < 2; nt++) {
        int w = my + mt * 16 + gI;
        int c = c0 + nw + nt * 8 + 2 * tq;
        split_bf(acc[mt][nt][0] + g_v1[c],     g_MTh[b][w][c],     g_MTl[b][w][c]);
        split_bf(acc[mt][nt][1] + g_v1[c + 1], g_MTh[b][w][c + 1], g_MTl[b][w][c + 1]);
        split_bf(acc[mt][nt][2] + g_v1[c],     g_MTh[b][w + 8][c],     g_MTl[b][w + 8][c]);
        split_bf(acc[mt][nt][3] + g_v1[c + 1], g_MTh[b][w + 8][c + 1], g_MTl[b][w + 8][c + 1]);
      }
  } else {
    #pragma unroll
    for (int mt = 0; mt < 2; mt++)
      #pragma unroll
      for (int nt = 0; nt < 2; nt++) {
        int c = c0 + my + mt * 16 + gI;
        int w = nw + nt * 8 + 2 * tq;
        float bv0 = bv[c], bv8 = bv[c + 8];
        split_bf(acc[mt][nt][0] + bv0, g_vbh[b][c][w],     g_vbl[b][c][w]);
        split_bf(acc[mt][nt][1] + bv0, g_vbh[b][c][w + 1], g_vbl[b][c][w + 1]);
        split_bf(acc[mt][nt][2] + bv8, g_vbh[b][c + 8][w],     g_vbl[b][c + 8][w]);
        split_bf(acc[mt][nt][3] + bv8, g_vbh[b][c + 8][w + 1], g_vbl[b][c + 8][w + 1]);
      }
  }
}

// =============================================================================
// k_fused: E = x^T M + dw, softmax, out = gamma*(vbar@A^T)+x
// XA: natural [c][n] layout, 272B rows (bank-conflict-free STS.64 + ldsm.trans)
// =============================================================================
#define XA0 0
#define XALO 8704            // lo region offset within buffer
#define XABUF 17408          // per-buffer stride
#define MB0 34816
#define MBSZ 10240
#define EF_OFF 55296         // 128*68*4 = 34816 -> ends 90112
#define ATT_H 0              // aliases XA/MB (dead after phase 1)
#define ATT_L 18432
#define VB0 90112
#define VBSZ 36864
#define SMEM_FUSED 163840

__global__ __launch_bounds__(256)
void k_fused(const float* __restrict__ x, const float* __restrict__ gamma,
             float* __restrict__ out) {
  extern __shared__ char sm[];
  unsigned sb = (unsigned)__cvta_generic_to_shared(sm);
  int tid = threadIdx.x;
  int wid = tid >> 5, lane = tid & 31;
  int b = blockIdx.y;
  int n0 = blockIdx.x * 128;
  int gI = lane >> 2, tq = lane & 3;

  const float* xb = x + (size_t)b * NC * NN + n0;
  int lc2a = tid >> 5, ln4 = tid & 31;       // chunk-c pair index, n-quad index
  int lc2b = lc2a + 8;
  int mw = tid >> 2, mq = tid & 3;

  auto load_x = [&](float4 (&xr)[4], int c0) {
    const float* p0 = xb + (size_t)(c0 + 2 * lc2a) * NN + ln4 * 4;
    xr[0] = *(const float4*)p0;
    xr[1] = *(const float4*)(p0 + NN);
    const float* p1 = xb + (size_t)(c0 + 2 * lc2b) * NN + ln4 * 4;
    xr[2] = *(const float4*)p1;
    xr[3] = *(const float4*)(p1 + NN);
  };
  // store to XA [c][n]: rows 272B; STS.64 conflict-free (lane delta 8B)
  auto store_x = [&](float4 (&xr)[4], unsigned xbase) {
    #pragma unroll
    for (int z = 0; z < 2; z++) {
      int lc2 = z ? lc2b : lc2a;
      unsigned base0 = xbase + (2 * lc2) * 272 + ln4 * 8;
      uint2 h, l;
      hilo2((const float*)&xr[2 * z], h, l);
      *(uint2*)(sm + base0) = h;
      *(uint2*)(sm + base0 + XALO) = l;
      hilo2((const float*)&xr[2 * z + 1], h, l);
      *(uint2*)(sm + base0 + 272) = h;
      *(uint2*)(sm + base0 + 272 + XALO) = l;
    }
  };
  auto issue_M = [&](int c0, unsigned mb) {
    cp16(sb + mb + mw * 80 + mq * 16,        &g_MTh[b][mw][c0 + mq * 8]);
    cp16(sb + mb + 5120 + mw * 80 + mq * 16, &g_MTl[b][mw][c0 + mq * 8]);
  };
  auto issue_VB = [&](int cc, unsigned base) {
    #pragma unroll
    for (int it2 = tid; it2 < 1024; it2 += 256) {
      int rr = it2 >> 3, q = it2 & 7;
      cp16(sb + base + rr * 144 + q * 16,         &g_vbh[b][cc * 128 + rr][q * 8]);
      cp16(sb + base + 18432 + rr * 144 + q * 16, &g_vbl[b][cc * 128 + rr][q * 8]);
    }
  };

  // ---------------- phase 1 ---------------------------------------------------
  int ny = (wid >> 1) * 32;
  int wy = (wid & 1) * 32;
  float acc1[2][4][4] = {};

  auto mma_chunk = [&](unsigned xab, unsigned mbb) {
    #pragma unroll
    for (int ks = 0; ks < 32; ks += 16) {
      unsigned Ah[2][4], Al[2][4];
      unsigned arow = ks + (lane & 7) + ((lane & 16) >> 1);   // c within chunk
      #pragma unroll
      for (int mt = 0; mt < 2; mt++) {
        unsigned noff = ny + mt * 16 + (lane & 8);
        unsigned aaddr = sb + xab + arow * 272 + noff * 2;
        ldsm4t(Ah[mt][0], Ah[mt][1], Ah[mt][2], Ah[mt][3], aaddr);
        ldsm4t(Al[mt][0], Al[mt][1], Al[mt][2], Al[mt][3], aaddr + XALO);
      }
      unsigned Bh[2][4], Bl[2][4];
      #pragma unroll
      for (int bt = 0; bt < 2; bt++) {
        unsigned row = wy + bt * 16 + (lane & 7) + ((lane & 16) >> 1);
        unsigned coff = ks * 2 + ((lane & 8) << 1);
        ldsm4(Bh[bt][0], Bh[bt][1], Bh[bt][2], Bh[bt][3], sb + mbb + row * 80 + coff);
        ldsm4(Bl[bt][0], Bl[bt][1], Bl[bt][2], Bl[bt][3], sb + mbb + 5120 + row * 80 + coff);
      }
      #pragma unroll
      for (int mt = 0; mt < 2; mt++)
        #pragma unroll
        for (int bt = 0; bt < 2; bt++)
          #pragma unroll
          for (int sub = 0; sub < 2; sub++) {
            int wt = bt * 2 + sub;
            mma16816(acc1[mt][wt], Ah[mt], Bh[bt][sub * 2], Bh[bt][sub * 2 + 1]);
            mma16816(acc1[mt][wt], Ah[mt], Bl[bt][sub * 2], Bl[bt][sub * 2 + 1]);
            mma16816(acc1[mt][wt], Al[mt], Bh[bt][sub * 2], Bh[bt][sub * 2 + 1]);
          }
    }
  };

  float4 xrA[4], xrB[4];
  load_x(xrA, 0);
  load_x(xrB, 32);
  issue_M(0, MB0); CP_COMMIT();
  store_x(xrA, XA0);
  CP_WAIT(0);
  __syncthreads();

  auto step = [&](int i, float4 (&nxt)[4], float4 (&sto)[4]) {
    if (i < 14) load_x(nxt, (i + 2) * 32);
    if (i < 15) { issue_M((i + 1) * 32, MB0 + ((i + 1) & 1) * MBSZ); CP_COMMIT(); }
    mma_chunk(XA0 + (i & 1) * XABUF, MB0 + (i & 1) * MBSZ);
    if (i < 15) {
      store_x(sto, XA0 + ((i + 1) & 1) * XABUF);
      CP_WAIT(0);
    }
    __syncthreads();
  };
  for (int i2 = 0; i2 < 16; i2 += 2) {
    step(i2, xrA, xrB);
    step(i2 + 1, xrB, xrA);
  }

  issue_VB(0, VB0);
  CP_COMMIT();

  float* Ef = (float*)(sm + EF_OFF);
  #pragma unroll
  for (int wt = 0; wt < 4; wt++) {
    int wc = wy + wt * 8 + 2 * tq;
    float d0 = g_dw[b][wc], d1 = g_dw[b][wc + 1];
    #pragma unroll
    for (int mt = 0; mt < 2; mt++) {
      int r = ny + mt * 16 + gI;
      float2 v0 = {acc1[mt][wt][0] + d0, acc1[mt][wt][1] + d1};
      float2 v1 = {acc1[mt][wt][2] + d0, acc1[mt][wt][3] + d1};
      *(float2*)&Ef[r * 68 + wc] = v0;
      *(float2*)&Ef[(r + 8) * 68 + wc] = v1;
    }
  }
  __syncthreads();

  {
    int row = tid >> 1, q = tid & 1;
    float mx = -1e30f;
    for (int w = q; w < NW; w += 2) mx = fmaxf(mx, Ef[row * 68 + w]);
    mx = fmaxf(mx, __shfl_xor_sync(0xffffffffu, mx, 1));
    float s = 0.f;
    for (int w = q; w < NW; w += 2) {
      float e = __expf(Ef[row * 68 + w] - mx);
      Ef[row * 68 + w] = e;
      s += e;
    }
    s += __shfl_xor_sync(0xffffffffu, s, 1);
    float inv = 1.0f / s;
    for (int w = q; w < NW; w += 2) Ef[row * 68 + w] *= inv;
  }
  __syncthreads();

  #pragma unroll
  for (int i = 0; i < 16; i++) {
    int p = tid + i * 256;
    int n = p >> 5, wp = p & 31;
    float e0 = Ef[n * 68 + 2 * wp], e1 = Ef[n * 68 + 2 * wp + 1];
    float h0 = __bfloat162float(__float2bfloat16(e0));
    float h1 = __bfloat162float(__float2bfloat16(e1));
    ((unsigned*)(sm + ATT_H))[n * 36 + wp] = pack_bf2(e0, e1);
    ((unsigned*)(sm + ATT_L))[n * 36 + wp] = pack_bf2(e0 - h0, e1 - h1);
  }

  // ---------------- phase 2 ---------------------------------------------------
  float g = gamma[0];
  int cy = (wid >> 1) * 32;
  int nx = (wid & 1) * 64;
  for (int cc = 0; cc < 4; cc++) {
    if (cc < 3) {
      issue_VB(cc + 1, VB0 + ((cc + 1) & 1) * VBSZ);
      CP_COMMIT();
      CP_WAIT(1);
    } else {
      CP_WAIT(0);
    }
    __syncthreads();

    unsigned vbb = VB0 + (cc & 1) * VBSZ;
    float acc2[2][8][4] = {};
    #pragma unroll
    for (int ks = 0; ks < 64; ks += 16) {
      unsigned Ah[2][4], Al[2][4];
      #pragma unroll
      for (int mt = 0; mt < 2; mt++) {
        unsigned row = cy + mt * 16 + (lane & 15);
        unsigned coff = ks * 2 + ((lane >> 4) << 4);
        ldsm4(Ah[mt][0], Ah[mt][1], Ah[mt][2], Ah[mt][3], sb + vbb + row * 144 + coff);
        ldsm4(Al[mt][0], Al[mt][1], Al[mt][2], Al[mt][3], sb + vbb + 18432 + row * 144 + coff);
      }
      unsigned Bh[4][4], Bl[4][4];
      #pragma unroll
      for (int bt = 0; bt < 4; bt++) {
        unsigned row = nx + bt * 16 + (lane & 7) + ((lane & 16) >> 1);
        unsigned coff = ks * 2 + ((lane & 8) << 1);
        ldsm4(Bh[bt][0], Bh[bt][1], Bh[bt][2], Bh[bt][3], sb + ATT_H + row * 144 + coff);
        ldsm4(Bl[bt][0], Bl[bt][1], Bl[bt][2], Bl[bt][3], sb + ATT_L + row * 144 + coff);
      }
      #pragma unroll
      for (int mt = 0; mt < 2; mt++)
        #pragma unroll
        for (int bt = 0; bt < 4; bt++)
          #pragma unroll
          for (int sub = 0; sub < 2; sub++) {
            int nt = bt * 2 + sub;
            mma16816(acc2[mt][nt], Ah[mt], Bh[bt][sub * 2], Bh[bt][sub * 2 + 1]);
            mma16816(acc2[mt][nt], Ah[mt], Bl[bt][sub * 2], Bl[bt][sub * 2 + 1]);
            mma16816(acc2[mt][nt], Al[mt], Bh[bt][sub * 2], Bh[bt][sub * 2 + 1]);
          }
    }
    #pragma unroll
    for (int mt = 0; mt < 2; mt++) {
      int c = cc * 128 + cy + mt * 16 + gI;
      #pragma unroll
      for (int nt = 0; nt < 8; nt++) {
        int n = n0 + nx + nt * 8 + 2 * tq;
        size_t off = ((size_t)(b * NC + c)) * NN + n;
        float2 xv0 = *(const float2*)(x + off);
        float2 xv1 = *(const float2*)(x + off + (size_t)8 * NN);
        float2 o0 = {fmaf(g, acc2[mt][nt][0], xv0.x), fmaf(g, acc2[mt][nt][1], xv0.y)};
        float2 o1 = {fmaf(g, acc2[mt][nt][2], xv1.x), fmaf(g, acc2[mt][nt][3], xv1.y)};
        *(float2*)(out + off) = o0;
        *(float2*)(out + off + (size_t)8 * NN) = o1;
      }
    }
    __syncthreads();
  }
}

// ---------------- launch -----------------------------------------------------
extern "C" void kernel_launch(void* const* d_in, const int* in_sizes, int n_in,
                              void* d_out, int out_size) {
  const float* x     = (const float*)d_in[0];
  const float* Wq    = (const float*)d_in[1];
  const float* bq    = (const float*)d_in[2];
  const float* Wk    = (const float*)d_in[3];
  const float* bk    = (const float*)d_in[4];
  const float* Wv    = (const float*)d_in[5];
  const float* bv    = (const float*)d_in[6];
  const float* gamma = (const float*)d_in[7];
  const float* pe    = (const float*)d_in[8];
  const int*   pos   = (const int*)  d_in[9];
  float* out = (float*)d_out;

  cudaFuncSetAttribute(k_MV, cudaFuncAttributeMaxDynamicSharedMemorySize, MV_SMEM);
  cudaFuncSetAttribute(k_fused, cudaFuncAttributeMaxDynamicSharedMemorySize,
                       SMEM_FUSED);

  k_front<<<2145, 256>>>(x, pos, pe, Wq, Wk, Wv, bq, bk);
  k_trans<<<32, 256>>>();
  k_MV<<<68, 256, MV_SMEM>>>(bv);
  k_fused<<<dim3(NN / 128, NB), 256, SMEM_FUSED>>>(x, gamma, out);
}

// round 11
// speedup vs baseline: 1.4761x; 1.3065x over previous
#include <cuda_runtime.h>
#include <cuda_bf16.h>

#define NB 4
#define NC 512
#define CKQ 256
#define NW 64
#define NH 64
#define NN 4096   // H*W

// ---------------- scratch (device globals) ----------------------------------
__device__ float g_xbar[NB][NC][NW];
__device__ float g_x2df[NB][NC][NW];
__device__ __align__(16) __nv_bfloat16 g_x2dTh[NB][NW][NC], g_x2dTl[NB][NW][NC];
__device__ __align__(16) __nv_bfloat16 g_xbarTh[NB][NW][NC], g_xbarTl[NB][NW][NC];
__device__ __align__(16) __nv_bfloat16 g_Gh[NC][NC], g_Gl[NC][NC];
__device__ __align__(16) __nv_bfloat16 g_Wvh[NC][NC], g_Wvl[NC][NC];
__device__ __align__(16) __nv_bfloat16 g_MTh[NB][NW][NC], g_MTl[NB][NW][NC];
__device__ __align__(16) __nv_bfloat16 g_vbh[NB][NC][NW], g_vbl[NB][NC][NW];
__device__ float g_v1[NC];        // Wq^T bk
__device__ float g_v2[NC];        // Wk^T bq
__device__ float g_s0;            // bq . bk
__device__ float g_dw[NB][NW];

// ---------------- helpers ----------------------------------------------------
__device__ __forceinline__ unsigned pack_bf2(float e, float o) {
  __nv_bfloat162 h;
  h.x = __float2bfloat16(e);
  h.y = __float2bfloat16(o);
  return *reinterpret_cast<unsigned*>(&h);
}
__device__ __forceinline__ void split_bf(float v, __nv_bfloat16& h, __nv_bfloat16& l) {
  h = __float2bfloat16(v);
  l = __float2bfloat16(v - __bfloat162float(h));
}
__device__ __forceinline__ void hilo2(const float* a, uint2& h, uint2& l) {
  float h0 = __bfloat162float(__float2bfloat16(a[0]));
  float h1 = __bfloat162float(__float2bfloat16(a[1]));
  float h2 = __bfloat162float(__float2bfloat16(a[2]));
  float h3 = __bfloat162float(__float2bfloat16(a[3]));
  h.x = pack_bf2(a[0], a[1]);
  h.y = pack_bf2(a[2], a[3]);
  l.x = pack_bf2(a[0] - h0, a[1] - h1);
  l.y = pack_bf2(a[2] - h2, a[3] - h3);
}
__device__ __forceinline__ void ldsm4(unsigned& r0, unsigned& r1, unsigned& r2,
                                      unsigned& r3, unsigned addr) {
  asm volatile("ldmatrix.sync.aligned.m8n8.x4.shared.b16 {%0,%1,%2,%3},[%4];"
               : "=r"(r0), "=r"(r1), "=r"(r2), "=r"(r3) : "r"(addr));
}
__device__ __forceinline__ void ldsm4t(unsigned& r0, unsigned& r1, unsigned& r2,
                                       unsigned& r3, unsigned addr) {
  asm volatile("ldmatrix.sync.aligned.m8n8.x4.trans.shared.b16 {%0,%1,%2,%3},[%4];"
               : "=r"(r0), "=r"(r1), "=r"(r2), "=r"(r3) : "r"(addr));
}
__device__ __forceinline__ void mma16816(float* d, const unsigned* a,
                                         unsigned b0, unsigned b1) {
  asm volatile(
    "mma.sync.aligned.m16n8k16.row.col.f32.bf16.bf16.f32 "
    "{%0,%1,%2,%3},{%4,%5,%6,%7},{%8,%9},{%0,%1,%2,%3};"
    : "+f"(d[0]), "+f"(d[1]), "+f"(d[2]), "+f"(d[3])
    : "r"(a[0]), "r"(a[1]), "r"(a[2]), "r"(a[3]), "r"(b0), "r"(b1));
}
__device__ __forceinline__ void cp16(unsigned saddr, const void* g) {
  asm volatile("cp.async.cg.shared.global [%0],[%1],16;" :: "r"(saddr), "l"(g));
}
#define CP_COMMIT() asm volatile("cp.async.commit_group;")
#define CP_WAIT(n)  asm volatile("cp.async.wait_group %0;" :: "n"(n))

// =============================================================================
// k_front: [0,2048) prep | [2048,2112) G | [2112,2144) Wv conv | [2144,2152) bias
// =============================================================================
// G smem: natural [o][c] layout, 144B rows, conflict-free STS.64 + ldsm.trans
#define GA_H 0
#define GA_L 4608
#define GB_H 9216
#define GB_L 13824

__global__ __launch_bounds__(256)
void k_front(const float* __restrict__ x, const int* __restrict__ pos,
             const float* __restrict__ pe, const float* __restrict__ Wq,
             const float* __restrict__ Wk, const float* __restrict__ Wv,
             const float* __restrict__ bq, const float* __restrict__ bk) {
  __shared__ float4 sm4[16][16];
  __shared__ float xbv[64];
  __shared__ float x1s[16];
  __shared__ int pidx[16];
  __shared__ __align__(16) char gsm[18432];

  int bx = blockIdx.x;
  int t = threadIdx.x;

  if (bx < 2048) {                     // ---------------- prep ----------------
    int c = bx & 511, b = bx >> 9;
    int hq = t >> 4, tw = t & 15;
    const float* xp = x + ((size_t)(b * NC + c)) * NH * NW;
    float4 s = {0.f, 0.f, 0.f, 0.f};
    #pragma unroll
    for (int h = hq; h < NH; h += 16) {
      float4 v = *(const float4*)&xp[h * NW + tw * 4];
      s.x += v.x; s.y += v.y; s.z += v.z; s.w += v.w;
    }
    sm4[hq][tw] = s;
    if (t < 16) pidx[t] = pos[b * NN + 4 * t] >> 3;
    __syncthreads();
    if (hq == 0) {
      float4 a = {0.f, 0.f, 0.f, 0.f};
      #pragma unroll
      for (int q = 0; q < 16; q++) {
        float4 v = sm4[q][tw];
        a.x += v.x; a.y += v.y; a.z += v.z; a.w += v.w;
      }
      const float inv = 1.0f / NH;
      a.x *= inv; a.y *= inv; a.z *= inv; a.w *= inv;
      *(float4*)&xbv[tw * 4] = a;
      *(float4*)&g_xbar[b][c][tw * 4] = a;
    }
    __syncthreads();
    if (t < 16)
      x1s[t] = 0.25f * (xbv[4*t] + xbv[4*t+1] + xbv[4*t+2] + xbv[4*t+3])
               + pe[pidx[t] * NC + c];
    __syncthreads();
    if (t < NW) {
      float src = (t * 15.0f) / 63.0f;
      int   i0  = (int)floorf(src);
      int   i1  = min(i0 + 1, 15);
      float tt  = src - (float)i0;
      g_x2df[b][c][t] = x1s[i0] * (1.0f - tt) + x1s[i1] * tt;
    }
    return;
  }

  if (bx < 2112) {                     // ---------------- G = Wq^T Wk ----------
    int gx = bx - 2048;
    int cx = gx & 7, kx = gx >> 3;     // 64x64 tile: rows c (from Wq), cols k (from Wk)
    unsigned sb = (unsigned)__cvta_generic_to_shared(gsm);
    int wid = t >> 5, lane = t & 31;
    int my = (wid >> 2) * 32, nw = (wid & 3) * 16;
    int gI = lane >> 2, tq = lane & 3;
    float acc[2][2][4] = {};
    int rr0 = t >> 4, c4 = t & 15;     // loader coords
    for (int o0 = 0; o0 < CKQ; o0 += 32) {
      #pragma unroll
      for (int z = 0; z < 2; z++) {
        int row = rr0 + z * 16;
        float4 v = *(const float4*)&Wq[(size_t)(o0 + row) * NC + cx * 64 + c4 * 4];
        uint2 h, l;
        hilo2((const float*)&v, h, l);
        *(uint2*)(gsm + GA_H + row * 144 + c4 * 8) = h;
        *(uint2*)(gsm + GA_L + row * 144 + c4 * 8) = l;
        float4 w = *(const float4*)&Wk[(size_t)(o0 + row) * NC + kx * 64 + c4 * 4];
        hilo2((const float*)&w, h, l);
        *(uint2*)(gsm + GB_H + row * 144 + c4 * 8) = h;
        *(uint2*)(gsm + GB_L + row * 144 + c4 * 8) = l;
      }
      __syncthreads();
      #pragma unroll
      for (int ks = 0; ks < 32; ks += 16) {
        unsigned Ah[2][4], Al[2][4];
        unsigned arow = ks + (lane & 7) + ((lane & 16) >> 1);
        #pragma unroll
        for (int mt = 0; mt < 2; mt++) {
          unsigned mcol = my + mt * 16 + (lane & 8);
          unsigned aaddr = sb + GA_H + arow * 144 + mcol * 2;
          ldsm4t(Ah[mt][0], Ah[mt][1], Ah[mt][2], Ah[mt][3], aaddr);
          ldsm4t(Al[mt][0], Al[mt][1], Al[mt][2], Al[mt][3], aaddr + (GA_L - GA_H));
        }
        unsigned Bh[4], Bl[4];
        {
          unsigned brow = ks + (lane & 7) + (lane & 8);
          unsigned bcol = nw + ((lane & 16) >> 1);
          unsigned baddr = sb + GB_H + brow * 144 + bcol * 2;
          ldsm4t(Bh[0], Bh[1], Bh[2], Bh[3], baddr);
          ldsm4t(Bl[0], Bl[1], Bl[2], Bl[3], baddr + (GB_L - GB_H));
        }
        #pragma unroll
        for (int mt = 0; mt < 2; mt++)
          #pragma unroll
          for (int sub = 0; sub < 2; sub++) {
            mma16816(acc[mt][sub], Ah[mt], Bh[sub * 2], Bh[sub * 2 + 1]);
            mma16816(acc[mt][sub], Ah[mt], Bl[sub * 2], Bl[sub * 2 + 1]);
            mma16816(acc[mt][sub], Al[mt], Bh[sub * 2], Bh[sub * 2 + 1]);
          }
      }
      __syncthreads();
    }
    #pragma unroll
    for (int mt = 0; mt < 2; mt++)
      #pragma unroll
      for (int nt = 0; nt < 2; nt++) {
        int cg = cx * 64 + my + mt * 16 + gI;
        int kg = kx * 64 + nw + nt * 8 + 2 * tq;
        split_bf(acc[mt][nt][0], g_Gh[cg][kg],     g_Gl[cg][kg]);
        split_bf(acc[mt][nt][1], g_Gh[cg][kg + 1], g_Gl[cg][kg + 1]);
        split_bf(acc[mt][nt][2], g_Gh[cg + 8][kg],     g_Gl[cg + 8][kg]);
        split_bf(acc[mt][nt][3], g_Gh[cg + 8][kg + 1], g_Gl[cg + 8][kg + 1]);
      }
    return;
  }

  if (bx < 2144) {                     // ---------------- Wv convert -----------
    int base = (bx - 2112) * 2048;
    #pragma unroll
    for (int j = 0; j < 8; j++) {
      int idx4 = base + j * 256 + t;
      float4 v = ((const float4*)Wv)[idx4];
      __nv_bfloat16 h0, l0, h1, l1;
      split_bf(v.x, h0, l0); split_bf(v.y, h1, l1);
      ((__nv_bfloat162*)g_Wvh)[idx4 * 2] = {h0, h1};
      ((__nv_bfloat162*)g_Wvl)[idx4 * 2] = {l0, l1};
      split_bf(v.z, h0, l0); split_bf(v.w, h1, l1);
      ((__nv_bfloat162*)g_Wvh)[idx4 * 2 + 1] = {h0, h1};
      ((__nv_bfloat162*)g_Wvl)[idx4 * 2 + 1] = {l0, l1};
    }
    return;
  }

  // ---------------- bias blocks (8 blocks, 64 c each, 4 thr/c) ---------------
  {
    int c = (bx - 2144) * 64 + (t >> 2);
    int q = t & 3;
    float s1 = 0.f, s2 = 0.f;
    #pragma unroll 8
    for (int o = q; o < CKQ; o += 4) {
      s1 += Wq[(size_t)o * NC + c] * bk[o];
      s2 += Wk[(size_t)o * NC + c] * bq[o];
    }
    s1 += __shfl_xor_sync(0xffffffffu, s1, 1);
    s1 += __shfl_xor_sync(0xffffffffu, s1, 2);
    s2 += __shfl_xor_sync(0xffffffffu, s2, 1);
    s2 += __shfl_xor_sync(0xffffffffu, s2, 2);
    if (q == 0) { g_v1[c] = s1; g_v2[c] = s2; }
    if (bx == 2144 && t < 32) {
      float s = 0.f;
      for (int o = t; o < CKQ; o += 32) s += bq[o] * bk[o];
      #pragma unroll
      for (int d = 16; d > 0; d >>= 1) s += __shfl_xor_sync(0xffffffffu, s, d);
      if (t == 0) g_s0 = s;
    }
  }
}

// =============================================================================
// k_trans: smem transpose f32 [c][w] -> bf16 hi/lo [w][c]
// =============================================================================
__global__ __launch_bounds__(256)
void k_trans() {
  __shared__ float Sxb[64][68];
  __shared__ float Sx2[64][68];
  int bx = blockIdx.x;
  int b = bx >> 3, c0 = (bx & 7) * 64;
  int t = threadIdx.x;
  int cl = t >> 2, q = t & 3;
  #pragma unroll
  for (int i = 0; i < 4; i++) {
    *(float4*)&Sxb[cl][q * 16 + i * 4] = *(const float4*)&g_xbar[b][c0 + cl][q * 16 + i * 4];
    *(float4*)&Sx2[cl][q * 16 + i * 4] = *(const float4*)&g_x2df[b][c0 + cl][q * 16 + i * 4];
  }
  __syncthreads();
  int w = t >> 2, qc = t & 3;
  __nv_bfloat162 xh[8], xl[8], bh[8], bl[8];
  #pragma unroll
  for (int i = 0; i < 8; i++) {
    int c = qc * 16 + 2 * i;
    __nv_bfloat16 h0, l0, h1, l1;
    split_bf(Sx2[c][w], h0, l0); split_bf(Sx2[c + 1][w], h1, l1);
    xh[i] = {h0, h1}; xl[i] = {l0, l1};
    split_bf(Sxb[c][w], h0, l0); split_bf(Sxb[c + 1][w], h1, l1);
    bh[i] = {h0, h1}; bl[i] = {l0, l1};
  }
  int cb = c0 + qc * 16;
  *(uint4*)&g_x2dTh[b][w][cb]      = *(uint4*)&xh[0];
  *(uint4*)&g_x2dTh[b][w][cb + 8]  = *(uint4*)&xh[4];
  *(uint4*)&g_x2dTl[b][w][cb]      = *(uint4*)&xl[0];
  *(uint4*)&g_x2dTl[b][w][cb + 8]  = *(uint4*)&xl[4];
  *(uint4*)&g_xbarTh[b][w][cb]     = *(uint4*)&bh[0];
  *(uint4*)&g_xbarTh[b][w][cb + 8] = *(uint4*)&bh[4];
  *(uint4*)&g_xbarTl[b][w][cb]     = *(uint4*)&bl[0];
  *(uint4*)&g_xbarTl[b][w][cb + 8] = *(uint4*)&bl[4];
}

// =============================================================================
// k_MV: [0,32) M^T tiles | [32,64) vbar tiles | [64,68) dw
// =============================================================================
#define MV_SAH 0
#define MV_SAL 9216
#define MV_SBH 18432
#define MV_SBL 27648
#define MV_BUF 36864
#define MV_SMEM 73728

__global__ __launch_bounds__(256)
void k_MV(const float* __restrict__ bv) {
  extern __shared__ char dsm[];
  unsigned sb = (unsigned)__cvta_generic_to_shared(dsm);
  int bx = blockIdx.x, tid = threadIdx.x;

  if (bx >= 64) {                      // dw
    int b = bx - 64;
    int w = tid >> 2, q = tid & 3;
    float s = 0.f;
    #pragma unroll 8
    for (int c = q * 128; c < q * 128 + 128; c++)
      s += (__bfloat162float(g_x2dTh[b][w][c]) + __bfloat162float(g_x2dTl[b][w][c]))
           * g_v2[c];
    s += __shfl_xor_sync(0xffffffffu, s, 1);
    s += __shfl_xor_sync(0xffffffffu, s, 2);
    if (q == 0) g_dw[b][w] = s + g_s0;
    return;
  }

  bool mtr = (bx < 32);
  int b  = mtr ? (bx >> 3) : ((bx - 32) >> 3);
  int c0 = (mtr ? (bx & 7) : ((bx - 32) & 7)) * 64;
  const __nv_bfloat16 *Ahg, *Alg, *Bhg, *Blg;
  if (mtr) { Ahg = &g_x2dTh[b][0][0];  Alg = &g_x2dTl[b][0][0];
             Bhg = &g_Gh[c0][0];       Blg = &g_Gl[c0][0]; }
  else     { Ahg = &g_Wvh[c0][0];      Alg = &g_Wvl[c0][0];
             Bhg = &g_xbarTh[b][0][0]; Blg = &g_xbarTl[b][0][0]; }

  auto issue = [&](int k0, unsigned base) {
    #pragma unroll
    for (int u = tid; u < 512; u += 256) {
      int r = u >> 3, q = u & 7;
      cp16(sb + base + MV_SAH + r * 144 + q * 16, Ahg + r * NC + k0 + q * 8);
      cp16(sb + base + MV_SAL + r * 144 + q * 16, Alg + r * NC + k0 + q * 8);
      cp16(sb + base + MV_SBH + r * 144 + q * 16, Bhg + r * NC + k0 + q * 8);
      cp16(sb + base + MV_SBL + r * 144 + q * 16, Blg + r * NC + k0 + q * 8);
    }
  };

  int wid = tid >> 5, lane = tid & 31;
  int my = (wid >> 2) * 32, nw = (wid & 3) * 16;
  int gI = lane >> 2, tq = lane & 3;
  float acc[2][2][4] = {};

  issue(0, 0); CP_COMMIT();
  for (int kc = 0; kc < 8; kc++) {
    if (kc < 7) {
      issue((kc + 1) * 64, ((kc + 1) & 1) * MV_BUF); CP_COMMIT();
      CP_WAIT(1);
    } else {
      CP_WAIT(0);
    }
    __syncthreads();
    unsigned base = (kc & 1) * MV_BUF;
    #pragma unroll
    for (int ks = 0; ks < 64; ks += 16) {
      unsigned Fh[2][4], Fl[2][4];
      #pragma unroll
      for (int mt = 0; mt < 2; mt++) {
        unsigned row = my + mt * 16 + (lane & 15);
        unsigned coff = ks * 2 + ((lane >> 4) << 4);
        ldsm4(Fh[mt][0], Fh[mt][1], Fh[mt][2], Fh[mt][3], sb + base + MV_SAH + row * 144 + coff);
        ldsm4(Fl[mt][0], Fl[mt][1], Fl[mt][2], Fl[mt][3], sb + base + MV_SAL + row * 144 + coff);
      }
      unsigned Gh4[4], Gl4[4];
      {
        unsigned row = nw + (lane & 7) + ((lane & 16) >> 1);
        unsigned coff = ks * 2 + ((lane & 8) << 1);
        ldsm4(Gh4[0], Gh4[1], Gh4[2], Gh4[3], sb + base + MV_SBH + row * 144 + coff);
        ldsm4(Gl4[0], Gl4[1], Gl4[2], Gl4[3], sb + base + MV_SBL + row * 144 + coff);
      }
      #pragma unroll
      for (int mt = 0; mt < 2; mt++)
        #pragma unroll
        for (int sub = 0; sub < 2; sub++) {
          mma16816(acc[mt][sub], Fh[mt], Gh4[sub * 2], Gh4[sub * 2 + 1]);
          mma16816(acc[mt][sub], Fh[mt], Gl4[sub * 2], Gl4[sub * 2 + 1]);
          mma16816(acc[mt][sub], Fl[mt], Gh4[sub * 2], Gh4[sub * 2 + 1]);
        }
    }
    __syncthreads();
  }

  if (mtr) {
    #pragma unroll
    for (int mt = 0; mt < 2; mt++)
      #pragma unroll
      for (int nt = 0; nt < 2; nt++) {
        int w = my + mt * 16 + gI;
        int c = c0 + nw + nt * 8 + 2 * tq;
        split_bf(acc[mt][nt][0] + g_v1[c],     g_MTh[b][w][c],     g_MTl[b][w][c]);
        split_bf(acc[mt][nt][1] + g_v1[c + 1], g_MTh[b][w][c + 1], g_MTl[b][w][c + 1]);
        split_bf(acc[mt][nt][2] + g_v1[c],     g_MTh[b][w + 8][c],     g_MTl[b][w + 8][c]);
        split_bf(acc[mt][nt][3] + g_v1[c + 1], g_MTh[b][w + 8][c + 1], g_MTl[b][w + 8][c + 1]);
      }
  } else {
    #pragma unroll
    for (int mt = 0; mt < 2; mt++)
      #pragma unroll
      for (int nt = 0; nt < 2; nt++) {
        int c = c0 + my + mt * 16 + gI;
        int w = nw + nt * 8 + 2 * tq;
        float bv0 = bv[c], bv8 = bv[c + 8];
        split_bf(acc[mt][nt][0] + bv0, g_vbh[b][c][w],     g_vbl[b][c][w]);
        split_bf(acc[mt][nt][1] + bv0, g_vbh[b][c][w + 1], g_vbl[b][c][w + 1]);
        split_bf(acc[mt][nt][2] + bv8, g_vbh[b][c + 8][w],     g_vbl[b][c + 8][w]);
        split_bf(acc[mt][nt][3] + bv8, g_vbh[b][c + 8][w + 1], g_vbl[b][c + 8][w + 1]);
      }
  }
}

// =============================================================================
// k_fused: n-tile 64, 2 blocks/SM. E = x^T M + dw, softmax, out = g*(vbar@A^T)+x
// =============================================================================
#define XA0 0
#define XALO 4608            // lo offset within buffer
#define XABUF 9216           // buffer stride; 2 buffers end 18432
#define MB0 18432
#define MBSZ 10240           // hi 5120 + lo 5120; 2 buffers end 38912
#define EF_OFF 38912         // 64*68*4 = 17408 -> end 56320
#define ATT_H 0              // aliases XA (dead after phase 1); 64*144 = 9216
#define ATT_L 9216
#define VB0 56320
#define VBLO 9216            // lo offset within buffer
#define VBSZ 18432           // 2 buffers end 93184
#define SMEM_FUSED 93184

__global__ __launch_bounds__(256, 2)
void k_fused(const float* __restrict__ x, const float* __restrict__ gamma,
             float* __restrict__ out) {
  extern __shared__ char sm[];
  unsigned sb = (unsigned)__cvta_generic_to_shared(sm);
  int tid = threadIdx.x;
  int wid = tid >> 5, lane = tid & 31;
  int b = blockIdx.y;
  int n0 = blockIdx.x * 64;
  int gI = lane >> 2, tq = lane & 3;

  const float* xb = x + (size_t)b * NC * NN + n0;
  int rc = tid >> 4, ln4 = tid & 15;         // x loader: c row, n quad
  int mw = tid >> 2, mq = tid & 3;           // M cp coords

  auto load_x = [&](float4 (&xr)[2], int c0) {
    xr[0] = *(const float4*)(xb + (size_t)(c0 + rc) * NN + ln4 * 4);
    xr[1] = *(const float4*)(xb + (size_t)(c0 + rc + 16) * NN + ln4 * 4);
  };
  auto store_x = [&](float4 (&xr)[2], unsigned xbase) {
    uint2 h, l;
    unsigned base0 = xbase + rc * 144 + ln4 * 8;
    hilo2((const float*)&xr[0], h, l);
    *(uint2*)(sm + base0) = h;
    *(uint2*)(sm + base0 + XALO) = l;
    hilo2((const float*)&xr[1], h, l);
    *(uint2*)(sm + base0 + 16 * 144) = h;
    *(uint2*)(sm + base0 + 16 * 144 + XALO) = l;
  };
  auto issue_M = [&](int c0, unsigned mb) {
    cp16(sb + mb + mw * 80 + mq * 16,        &g_MTh[b][mw][c0 + mq * 8]);
    cp16(sb + mb + 5120 + mw * 80 + mq * 16, &g_MTl[b][mw][c0 + mq * 8]);
  };
  auto issue_VB = [&](int cc, unsigned base) {
    #pragma unroll
    for (int u = tid; u < 512; u += 256) {
      int rr = u >> 3, q = u & 7;
      cp16(sb + base + rr * 144 + q * 16,        &g_vbh[b][cc * 64 + rr][q * 8]);
      cp16(sb + base + VBLO + rr * 144 + q * 16, &g_vbl[b][cc * 64 + rr][q * 8]);
    }
  };

  // ---------------- phase 1: E[64n][64w] --------------------------------------
  int ny = (wid >> 2) * 32;
  int wy = (wid & 3) * 16;
  float acc1[2][2][4] = {};

  auto mma_chunk = [&](unsigned xab, unsigned mbb) {
    #pragma unroll
    for (int ks = 0; ks < 32; ks += 16) {
      unsigned Ah[2][4], Al[2][4];
      unsigned arow = ks + (lane & 7) + ((lane & 16) >> 1);
      #pragma unroll
      for (int mt = 0; mt < 2; mt++) {
        unsigned acol = ny + mt * 16 + (lane & 8);
        unsigned aaddr = sb + xab + arow * 144 + acol * 2;
        ldsm4t(Ah[mt][0], Ah[mt][1], Ah[mt][2], Ah[mt][3], aaddr);
        ldsm4t(Al[mt][0], Al[mt][1], Al[mt][2], Al[mt][3], aaddr + XALO);
      }
      unsigned Bh[4], Bl[4];
      {
        unsigned row = wy + (lane & 7) + ((lane & 16) >> 1);
        unsigned coff = ks * 2 + ((lane & 8) << 1);
        ldsm4(Bh[0], Bh[1], Bh[2], Bh[3], sb + mbb + row * 80 + coff);
        ldsm4(Bl[0], Bl[1], Bl[2], Bl[3], sb + mbb + 5120 + row * 80 + coff);
      }
      #pragma unroll
      for (int mt = 0; mt < 2; mt++)
        #pragma unroll
        for (int sub = 0; sub < 2; sub++) {
          mma16816(acc1[mt][sub], Ah[mt], Bh[sub * 2], Bh[sub * 2 + 1]);
          mma16816(acc1[mt][sub], Ah[mt], Bl[sub * 2], Bl[sub * 2 + 1]);
          mma16816(acc1[mt][sub], Al[mt], Bh[sub * 2], Bh[sub * 2 + 1]);
        }
    }
  };

  float4 xrA[2], xrB[2];
  load_x(xrA, 0);
  load_x(xrB, 32);
  issue_M(0, MB0); CP_COMMIT();
  store_x(xrA, XA0);
  CP_WAIT(0);
  __syncthreads();

  auto step = [&](int i, float4 (&nxt)[2], float4 (&sto)[2]) {
    if (i < 14) load_x(nxt, (i + 2) * 32);
    if (i < 15) { issue_M((i + 1) * 32, MB0 + ((i + 1) & 1) * MBSZ); CP_COMMIT(); }
    mma_chunk(XA0 + (i & 1) * XABUF, MB0 + (i & 1) * MBSZ);
    if (i < 15) {
      store_x(sto, XA0 + ((i + 1) & 1) * XABUF);
      CP_WAIT(0);
    }
    __syncthreads();
  };
  for (int i2 = 0; i2 < 16; i2 += 2) {
    step(i2, xrA, xrB);
    step(i2 + 1, xrB, xrA);
  }

  issue_VB(0, VB0);
  CP_COMMIT();

  // epilogue: E += dw -> Ef
  float* Ef = (float*)(sm + EF_OFF);
  #pragma unroll
  for (int sub = 0; sub < 2; sub++) {
    int wc = wy + sub * 8 + 2 * tq;
    float d0 = g_dw[b][wc], d1 = g_dw[b][wc + 1];
    #pragma unroll
    for (int mt = 0; mt < 2; mt++) {
      int r = ny + mt * 16 + gI;
      float2 v0 = {acc1[mt][sub][0] + d0, acc1[mt][sub][1] + d1};
      float2 v1 = {acc1[mt][sub][2] + d0, acc1[mt][sub][3] + d1};
      *(float2*)&Ef[r * 68 + wc] = v0;
      *(float2*)&Ef[(r + 8) * 68 + wc] = v1;
    }
  }
  __syncthreads();

  // softmax over w (4 threads/row, 64 rows)
  {
    int row = tid >> 2, q = tid & 3;
    float mx = -1e30f;
    for (int w = q; w < NW; w += 4) mx = fmaxf(mx, Ef[row * 68 + w]);
    mx = fmaxf(mx, __shfl_xor_sync(0xffffffffu, mx, 1));
    mx = fmaxf(mx, __shfl_xor_sync(0xffffffffu, mx, 2));
    float s = 0.f;
    for (int w = q; w < NW; w += 4) {
      float e = __expf(Ef[row * 68 + w] - mx);
      Ef[row * 68 + w] = e;
      s += e;
    }
    s += __shfl_xor_sync(0xffffffffu, s, 1);
    s += __shfl_xor_sync(0xffffffffu, s, 2);
    float inv = 1.0f / s;
    for (int w = q; w < NW; w += 4) Ef[row * 68 + w] *= inv;
  }
  __syncthreads();

  // convert attn to bf16 hi/lo [n][w], rows 144B (alias XA region)
  #pragma unroll
  for (int i = 0; i < 8; i++) {
    int p = tid + i * 256;
    int n = p >> 5, wp = p & 31;
    float e0 = Ef[n * 68 + 2 * wp], e1 = Ef[n * 68 + 2 * wp + 1];
    float h0 = __bfloat162float(__float2bfloat16(e0));
    float h1 = __bfloat162float(__float2bfloat16(e1));
    *(unsigned*)(sm + ATT_H + n * 144 + wp * 4) = pack_bf2(e0, e1);
    *(unsigned*)(sm + ATT_L + n * 144 + wp * 4) = pack_bf2(e0 - h0, e1 - h1);
  }

  // ---------------- phase 2: out = gamma*(vbar @ A^T) + x ---------------------
  float g = gamma[0];
  int cy = (wid >> 2) * 32;
  int nx = (wid & 3) * 16;
  for (int cc = 0; cc < 8; cc++) {
    if (cc < 7) {
      issue_VB(cc + 1, VB0 + ((cc + 1) & 1) * VBSZ);
      CP_COMMIT();
      CP_WAIT(1);
    } else {
      CP_WAIT(0);
    }
    __syncthreads();

    unsigned vbb = VB0 + (cc & 1) * VBSZ;
    float acc2[2][2][4] = {};
    #pragma unroll
    for (int ks = 0; ks < 64; ks += 16) {
      unsigned Ah[2][4], Al[2][4];
      #pragma unroll
      for (int mt = 0; mt < 2; mt++) {
        unsigned row = cy + mt * 16 + (lane & 15);
        unsigned coff = ks * 2 + ((lane >> 4) << 4);
        ldsm4(Ah[mt][0], Ah[mt][1], Ah[mt][2], Ah[mt][3], sb + vbb + row * 144 + coff);
        ldsm4(Al[mt][0], Al[mt][1], Al[mt][2], Al[mt][3], sb + vbb + VBLO + row * 144 + coff);
      }
      unsigned Bh[4], Bl[4];
      {
        unsigned row = nx + (lane & 7) + ((lane & 16) >> 1);
        unsigned coff = ks * 2 + ((lane & 8) << 1);
        ldsm4(Bh[0], Bh[1], Bh[2], Bh[3], sb + ATT_H + row * 144 + coff);
        ldsm4(Bl[0], Bl[1], Bl[2], Bl[3], sb + ATT_L + row * 144 + coff);
      }
      #pragma unroll
      for (int mt = 0; mt < 2; mt++)
        #pragma unroll
        for (int sub = 0; sub < 2; sub++) {
          mma16816(acc2[mt][sub], Ah[mt], Bh[sub * 2], Bh[sub * 2 + 1]);
          mma16816(acc2[mt][sub], Ah[mt], Bl[sub * 2], Bl[sub * 2 + 1]);
          mma16816(acc2[mt][sub], Al[mt], Bh[sub * 2], Bh[sub * 2 + 1]);
        }
    }
    // epilogue: residual add + store
    #pragma unroll
    for (int mt = 0; mt < 2; mt++) {
      int c = cc * 64 + cy + mt * 16 + gI;
      #pragma unroll
      for (int sub = 0; sub < 2; sub++) {
        int n = n0 + nx + sub * 8 + 2 * tq;
        size_t off = ((size_t)(b * NC + c)) * NN + n;
        float2 xv0 = *(const float2*)(x + off);
        float2 xv1 = *(const float2*)(x + off + (size_t)8 * NN);
        float2 o0 = {fmaf(g, acc2[mt][sub][0], xv0.x), fmaf(g, acc2[mt][sub][1], xv0.y)};
        float2 o1 = {fmaf(g, acc2[mt][sub][2], xv1.x), fmaf(g, acc2[mt][sub][3], xv1.y)};
        *(float2*)(out + off) = o0;
        *(float2*)(out + off + (size_t)8 * NN) = o1;
      }
    }
    __syncthreads();
  }
}

// ---------------- launch -----------------------------------------------------
extern "C" void kernel_launch(void* const* d_in, const int* in_sizes, int n_in,
                              void* d_out, int out_size) {
  const float* x     = (const float*)d_in[0];
  const float* Wq    = (const float*)d_in[1];
  const float* bq    = (const float*)d_in[2];
  const float* Wk    = (const float*)d_in[3];
  const float* bk    = (const float*)d_in[4];
  const float* Wv    = (const float*)d_in[5];
  const float* bv    = (const float*)d_in[6];
  const float* gamma = (const float*)d_in[7];
  const float* pe    = (const float*)d_in[8];
  const int*   pos   = (const int*)  d_in[9];
  float* out = (float*)d_out;

  cudaFuncSetAttribute(k_MV, cudaFuncAttributeMaxDynamicSharedMemorySize, MV_SMEM);
  cudaFuncSetAttribute(k_fused, cudaFuncAttributeMaxDynamicSharedMemorySize,
                       SMEM_FUSED);

  k_front<<<2152, 256>>>(x, pos, pe, Wq, Wk, Wv, bq, bk);
  k_trans<<<32, 256>>>();
  k_MV<<<68, 256, MV_SMEM>>>(bv);
  k_fused<<<dim3(NN / 64, NB), 256, SMEM_FUSED>>>(x, gamma, out);
}

// round 13
// speedup vs baseline: 1.5961x; 1.0813x over previous
#include <cuda_runtime.h>
#include <cuda_bf16.h>

#define NB 4
#define NC 512
#define CKQ 256
#define NW 64
#define NH 64
#define NN 4096   // H*W

// ---------------- scratch (device globals) ----------------------------------
__device__ float g_xbar[NB][NC][NW];
__device__ float g_x2df[NB][NC][NW];
__device__ __align__(16) __nv_bfloat16 g_x2dTh[NB][NW][NC], g_x2dTl[NB][NW][NC];
__device__ __align__(16) __nv_bfloat16 g_xbarTh[NB][NW][NC], g_xbarTl[NB][NW][NC];
__device__ __align__(16) __nv_bfloat16 g_Gh[NC][NC], g_Gl[NC][NC];
__device__ __align__(16) __nv_bfloat16 g_Wvh[NC][NC], g_Wvl[NC][NC];
__device__ __align__(16) __nv_bfloat16 g_MTh[NB][NW][NC], g_MTl[NB][NW][NC];
__device__ __align__(16) __nv_bfloat16 g_vbh[NB][NC][NW], g_vbl[NB][NC][NW];
__device__ float g_v1[NC];        // Wq^T bk
__device__ float g_v2[NC];        // Wk^T bq
__device__ float g_s0;            // bq . bk
__device__ float g_dw[NB][NW];

// ---------------- helpers ----------------------------------------------------
__device__ __forceinline__ unsigned pack_bf2(float e, float o) {
  __nv_bfloat162 h;
  h.x = __float2bfloat16(e);
  h.y = __float2bfloat16(o);
  return *reinterpret_cast<unsigned*>(&h);
}
__device__ __forceinline__ void split_bf(float v, __nv_bfloat16& h, __nv_bfloat16& l) {
  h = __float2bfloat16(v);
  l = __float2bfloat16(v - __bfloat162float(h));
}
__device__ __forceinline__ void hilo2(const float* a, uint2& h, uint2& l) {
  float h0 = __bfloat162float(__float2bfloat16(a[0]));
  float h1 = __bfloat162float(__float2bfloat16(a[1]));
  float h2 = __bfloat162float(__float2bfloat16(a[2]));
  float h3 = __bfloat162float(__float2bfloat16(a[3]));
  h.x = pack_bf2(a[0], a[1]);
  h.y = pack_bf2(a[2], a[3]);
  l.x = pack_bf2(a[0] - h0, a[1] - h1);
  l.y = pack_bf2(a[2] - h2, a[3] - h3);
}
__device__ __forceinline__ void ldsm4(unsigned& r0, unsigned& r1, unsigned& r2,
                                      unsigned& r3, unsigned addr) {
  asm volatile("ldmatrix.sync.aligned.m8n8.x4.shared.b16 {%0,%1,%2,%3},[%4];"
               : "=r"(r0), "=r"(r1), "=r"(r2), "=r"(r3) : "r"(addr));
}
__device__ __forceinline__ void ldsm4t(unsigned& r0, unsigned& r1, unsigned& r2,
                                       unsigned& r3, unsigned addr) {
  asm volatile("ldmatrix.sync.aligned.m8n8.x4.trans.shared.b16 {%0,%1,%2,%3},[%4];"
               : "=r"(r0), "=r"(r1), "=r"(r2), "=r"(r3) : "r"(addr));
}
__device__ __forceinline__ void mma16816(float* d, const unsigned* a,
                                         unsigned b0, unsigned b1) {
  asm volatile(
    "mma.sync.aligned.m16n8k16.row.col.f32.bf16.bf16.f32 "
    "{%0,%1,%2,%3},{%4,%5,%6,%7},{%8,%9},{%0,%1,%2,%3};"
    : "+f"(d[0]), "+f"(d[1]), "+f"(d[2]), "+f"(d[3])
    : "r"(a[0]), "r"(a[1]), "r"(a[2]), "r"(a[3]), "r"(b0), "r"(b1));
}
__device__ __forceinline__ void cp16(unsigned saddr, const void* g) {
  asm volatile("cp.async.cg.shared.global [%0],[%1],16;" :: "r"(saddr), "l"(g));
}
#define CP_COMMIT() asm volatile("cp.async.commit_group;")
#define CP_WAIT(n)  asm volatile("cp.async.wait_group %0;" :: "n"(n))

// =============================================================================
// k_front: [0,2048) prep | [2048,2112) G | [2112,2144) Wv conv | [2144,2152) bias
// =============================================================================
#define GA_H 0
#define GA_L 4608
#define GB_H 9216
#define GB_L 13824

__global__ __launch_bounds__(256)
void k_front(const float* __restrict__ x, const int* __restrict__ pos,
             const float* __restrict__ pe, const float* __restrict__ Wq,
             const float* __restrict__ Wk, const float* __restrict__ Wv,
             const float* __restrict__ bq, const float* __restrict__ bk) {
  __shared__ float4 sm4[16][16];
  __shared__ float xbv[64];
  __shared__ float x1s[16];
  __shared__ int pidx[16];
  __shared__ __align__(16) char gsm[18432];

  int bx = blockIdx.x;
  int t = threadIdx.x;

  if (bx < 2048) {                     // ---------------- prep ----------------
    int c = bx & 511, b = bx >> 9;
    int hq = t >> 4, tw = t & 15;
    const float* xp = x + ((size_t)(b * NC + c)) * NH * NW;
    float4 s = {0.f, 0.f, 0.f, 0.f};
    #pragma unroll
    for (int h = hq; h < NH; h += 16) {
      float4 v = *(const float4*)&xp[h * NW + tw * 4];
      s.x += v.x; s.y += v.y; s.z += v.z; s.w += v.w;
    }
    sm4[hq][tw] = s;
    if (t < 16) pidx[t] = pos[b * NN + 4 * t] >> 3;
    __syncthreads();
    if (hq == 0) {
      float4 a = {0.f, 0.f, 0.f, 0.f};
      #pragma unroll
      for (int q = 0; q < 16; q++) {
        float4 v = sm4[q][tw];
        a.x += v.x; a.y += v.y; a.z += v.z; a.w += v.w;
      }
      const float inv = 1.0f / NH;
      a.x *= inv; a.y *= inv; a.z *= inv; a.w *= inv;
      *(float4*)&xbv[tw * 4] = a;
      *(float4*)&g_xbar[b][c][tw * 4] = a;
    }
    __syncthreads();
    if (t < 16)
      x1s[t] = 0.25f * (xbv[4*t] + xbv[4*t+1] + xbv[4*t+2] + xbv[4*t+3])
               + pe[pidx[t] * NC + c];
    __syncthreads();
    if (t < NW) {
      float src = (t * 15.0f) / 63.0f;
      int   i0  = (int)floorf(src);
      int   i1  = min(i0 + 1, 15);
      float tt  = src - (float)i0;
      g_x2df[b][c][t] = x1s[i0] * (1.0f - tt) + x1s[i1] * tt;
    }
    return;
  }

  if (bx < 2112) {                     // ---------------- G = Wq^T Wk ----------
    int gx = bx - 2048;
    int cx = gx & 7, kx = gx >> 3;
    unsigned sb = (unsigned)__cvta_generic_to_shared(gsm);
    int wid = t >> 5, lane = t & 31;
    int my = (wid >> 2) * 32, nw = (wid & 3) * 16;
    int gI = lane >> 2, tq = lane & 3;
    float acc[2][2][4] = {};
    int rr0 = t >> 4, c4 = t & 15;
    for (int o0 = 0; o0 < CKQ; o0 += 32) {
      #pragma unroll
      for (int z = 0; z < 2; z++) {
        int row = rr0 + z * 16;
        float4 v = *(const float4*)&Wq[(size_t)(o0 + row) * NC + cx * 64 + c4 * 4];
        uint2 h, l;
        hilo2((const float*)&v, h, l);
        *(uint2*)(gsm + GA_H + row * 144 + c4 * 8) = h;
        *(uint2*)(gsm + GA_L + row * 144 + c4 * 8) = l;
        float4 w = *(const float4*)&Wk[(size_t)(o0 + row) * NC + kx * 64 + c4 * 4];
        hilo2((const float*)&w, h, l);
        *(uint2*)(gsm + GB_H + row * 144 + c4 * 8) = h;
        *(uint2*)(gsm + GB_L + row * 144 + c4 * 8) = l;
      }
      __syncthreads();
      #pragma unroll
      for (int ks = 0; ks < 32; ks += 16) {
        unsigned Ah[2][4], Al[2][4];
        unsigned arow = ks + (lane & 7) + ((lane & 16) >> 1);
        #pragma unroll
        for (int mt = 0; mt < 2; mt++) {
          unsigned mcol = my + mt * 16 + (lane & 8);
          unsigned aaddr = sb + GA_H + arow * 144 + mcol * 2;
          ldsm4t(Ah[mt][0], Ah[mt][1], Ah[mt][2], Ah[mt][3], aaddr);
          ldsm4t(Al[mt][0], Al[mt][1], Al[mt][2], Al[mt][3], aaddr + (GA_L - GA_H));
        }
        unsigned Bh[4], Bl[4];
        {
          unsigned brow = ks + (lane & 7) + (lane & 8);
          unsigned bcol = nw + ((lane & 16) >> 1);
          unsigned baddr = sb + GB_H + brow * 144 + bcol * 2;
          ldsm4t(Bh[0], Bh[1], Bh[2], Bh[3], baddr);
          ldsm4t(Bl[0], Bl[1], Bl[2], Bl[3], baddr + (GB_L - GB_H));
        }
        #pragma unroll
        for (int mt = 0; mt < 2; mt++)
          #pragma unroll
          for (int sub = 0; sub < 2; sub++) {
            mma16816(acc[mt][sub], Ah[mt], Bh[sub * 2], Bh[sub * 2 + 1]);
            mma16816(acc[mt][sub], Ah[mt], Bl[sub * 2], Bl[sub * 2 + 1]);
            mma16816(acc[mt][sub], Al[mt], Bh[sub * 2], Bh[sub * 2 + 1]);
          }
      }
      __syncthreads();
    }
    #pragma unroll
    for (int mt = 0; mt < 2; mt++)
      #pragma unroll
      for (int nt = 0; nt < 2; nt++) {
        int cg = cx * 64 + my + mt * 16 + gI;
        int kg = kx * 64 + nw + nt * 8 + 2 * tq;
        split_bf(acc[mt][nt][0], g_Gh[cg][kg],     g_Gl[cg][kg]);
        split_bf(acc[mt][nt][1], g_Gh[cg][kg + 1], g_Gl[cg][kg + 1]);
        split_bf(acc[mt][nt][2], g_Gh[cg + 8][kg],     g_Gl[cg + 8][kg]);
        split_bf(acc[mt][nt][3], g_Gh[cg + 8][kg + 1], g_Gl[cg + 8][kg + 1]);
      }
    return;
  }

  if (bx < 2144) {                     // ---------------- Wv convert -----------
    int base = (bx - 2112) * 2048;
    #pragma unroll
    for (int j = 0; j < 8; j++) {
      int idx4 = base + j * 256 + t;
      float4 v = ((const float4*)Wv)[idx4];
      __nv_bfloat16 h0, l0, h1, l1;
      split_bf(v.x, h0, l0); split_bf(v.y, h1, l1);
      ((__nv_bfloat162*)g_Wvh)[idx4 * 2] = {h0, h1};
      ((__nv_bfloat162*)g_Wvl)[idx4 * 2] = {l0, l1};
      split_bf(v.z, h0, l0); split_bf(v.w, h1, l1);
      ((__nv_bfloat162*)g_Wvh)[idx4 * 2 + 1] = {h0, h1};
      ((__nv_bfloat162*)g_Wvl)[idx4 * 2 + 1] = {l0, l1};
    }
    return;
  }

  // ---------------- bias blocks ----------------------------------------------
  {
    int c = (bx - 2144) * 64 + (t >> 2);
    int q = t & 3;
    float s1 = 0.f, s2 = 0.f;
    #pragma unroll 8
    for (int o = q; o < CKQ; o += 4) {
      s1 += Wq[(size_t)o * NC + c] * bk[o];
      s2 += Wk[(size_t)o * NC + c] * bq[o];
    }
    s1 += __shfl_xor_sync(0xffffffffu, s1, 1);
    s1 += __shfl_xor_sync(0xffffffffu, s1, 2);
    s2 += __shfl_xor_sync(0xffffffffu, s2, 1);
    s2 += __shfl_xor_sync(0xffffffffu, s2, 2);
    if (q == 0) { g_v1[c] = s1; g_v2[c] = s2; }
    if (bx == 2144 && t < 32) {
      float s = 0.f;
      for (int o = t; o < CKQ; o += 32) s += bq[o] * bk[o];
      #pragma unroll
      for (int d = 16; d > 0; d >>= 1) s += __shfl_xor_sync(0xffffffffu, s, d);
      if (t == 0) g_s0 = s;
    }
  }
}

// =============================================================================
// k_trans: smem transpose f32 [c][w] -> bf16 hi/lo [w][c]
// =============================================================================
__global__ __launch_bounds__(256)
void k_trans() {
  __shared__ float Sxb[64][68];
  __shared__ float Sx2[64][68];
  int bx = blockIdx.x;
  int b = bx >> 3, c0 = (bx & 7) * 64;
  int t = threadIdx.x;
  int cl = t >> 2, q = t & 3;
  #pragma unroll
  for (int i = 0; i < 4; i++) {
    *(float4*)&Sxb[cl][q * 16 + i * 4] = *(const float4*)&g_xbar[b][c0 + cl][q * 16 + i * 4];
    *(float4*)&Sx2[cl][q * 16 + i * 4] = *(const float4*)&g_x2df[b][c0 + cl][q * 16 + i * 4];
  }
  __syncthreads();
  int w = t >> 2, qc = t & 3;
  __nv_bfloat162 xh[8], xl[8], bh[8], bl[8];
  #pragma unroll
  for (int i = 0; i < 8; i++) {
    int c = qc * 16 + 2 * i;
    __nv_bfloat16 h0, l0, h1, l1;
    split_bf(Sx2[c][w], h0, l0); split_bf(Sx2[c + 1][w], h1, l1);
    xh[i] = {h0, h1}; xl[i] = {l0, l1};
    split_bf(Sxb[c][w], h0, l0); split_bf(Sxb[c + 1][w], h1, l1);
    bh[i] = {h0, h1}; bl[i] = {l0, l1};
  }
  int cb = c0 + qc * 16;
  *(uint4*)&g_x2dTh[b][w][cb]      = *(uint4*)&xh[0];
  *(uint4*)&g_x2dTh[b][w][cb + 8]  = *(uint4*)&xh[4];
  *(uint4*)&g_x2dTl[b][w][cb]      = *(uint4*)&xl[0];
  *(uint4*)&g_x2dTl[b][w][cb + 8]  = *(uint4*)&xl[4];
  *(uint4*)&g_xbarTh[b][w][cb]     = *(uint4*)&bh[0];
  *(uint4*)&g_xbarTh[b][w][cb + 8] = *(uint4*)&bh[4];
  *(uint4*)&g_xbarTl[b][w][cb]     = *(uint4*)&bl[0];
  *(uint4*)&g_xbarTl[b][w][cb + 8] = *(uint4*)&bl[4];
}

// =============================================================================
// k_MV: [0,32) M^T tiles | [32,64) vbar tiles | [64,68) dw
// =============================================================================
#define MV_SAH 0
#define MV_SAL 9216
#define MV_SBH 18432
#define MV_SBL 27648
#define MV_BUF 36864
#define MV_SMEM 73728

__global__ __launch_bounds__(256)
void k_MV(const float* __restrict__ bv) {
  extern __shared__ char dsm[];
  unsigned sb = (unsigned)__cvta_generic_to_shared(dsm);
  int bx = blockIdx.x, tid = threadIdx.x;

  if (bx >= 64) {                      // dw
    int b = bx - 64;
    int w = tid >> 2, q = tid & 3;
    float s = 0.f;
    #pragma unroll 8
    for (int c = q * 128; c < q * 128 + 128; c++)
      s += (__bfloat162float(g_x2dTh[b][w][c]) + __bfloat162float(g_x2dTl[b][w][c]))
           * g_v2[c];
    s += __shfl_xor_sync(0xffffffffu, s, 1);
    s += __shfl_xor_sync(0xffffffffu, s, 2);
    if (q == 0) g_dw[b][w] = s + g_s0;
    return;
  }

  bool mtr = (bx < 32);
  int b  = mtr ? (bx >> 3) : ((bx - 32) >> 3);
  int c0 = (mtr ? (bx & 7) : ((bx - 32) & 7)) * 64;
  const __nv_bfloat16 *Ahg, *Alg, *Bhg, *Blg;
  if (mtr) { Ahg = &g_x2dTh[b][0][0];  Alg = &g_x2dTl[b][0][0];
             Bhg = &g_Gh[c0][0];       Blg = &g_Gl[c0][0]; }
  else     { Ahg = &g_Wvh[c0][0];      Alg = &g_Wvl[c0][0];
             Bhg = &g_xbarTh[b][0][0]; Blg = &g_xbarTl[b][0][0]; }

  auto issue = [&](int k0, unsigned base) {
    #pragma unroll
    for (int u = tid; u < 512; u += 256) {
      int r = u >> 3, q = u & 7;
      cp16(sb + base + MV_SAH + r * 144 + q * 16, Ahg + r * NC + k0 + q * 8);
      cp16(sb + base + MV_SAL + r * 144 + q * 16, Alg + r * NC + k0 + q * 8);
      cp16(sb + base + MV_SBH + r * 144 + q * 16, Bhg + r * NC + k0 + q * 8);
      cp16(sb + base + MV_SBL + r * 144 + q * 16, Blg + r * NC + k0 + q * 8);
    }
  };

  int wid = tid >> 5, lane = tid & 31;
  int my = (wid >> 2) * 32, nw = (wid & 3) * 16;
  int gI = lane >> 2, tq = lane & 3;
  float acc[2][2][4] = {};

  issue(0, 0); CP_COMMIT();
  for (int kc = 0; kc < 8; kc++) {
    if (kc < 7) {
      issue((kc + 1) * 64, ((kc + 1) & 1) * MV_BUF); CP_COMMIT();
      CP_WAIT(1);
    } else {
      CP_WAIT(0);
    }
    __syncthreads();
    unsigned base = (kc & 1) * MV_BUF;
    #pragma unroll
    for (int ks = 0; ks < 64; ks += 16) {
      unsigned Fh[2][4], Fl[2][4];
      #pragma unroll
      for (int mt = 0; mt < 2; mt++) {
        unsigned row = my + mt * 16 + (lane & 15);
        unsigned coff = ks * 2 + ((lane >> 4) << 4);
        ldsm4(Fh[mt][0], Fh[mt][1], Fh[mt][2], Fh[mt][3], sb + base + MV_SAH + row * 144 + coff);
        ldsm4(Fl[mt][0], Fl[mt][1], Fl[mt][2], Fl[mt][3], sb + base + MV_SAL + row * 144 + coff);
      }
      unsigned Gh4[4], Gl4[4];
      {
        unsigned row = nw + (lane & 7) + ((lane & 16) >> 1);
        unsigned coff = ks * 2 + ((lane & 8) << 1);
        ldsm4(Gh4[0], Gh4[1], Gh4[2], Gh4[3], sb + base + MV_SBH + row * 144 + coff);
        ldsm4(Gl4[0], Gl4[1], Gl4[2], Gl4[3], sb + base + MV_SBL + row * 144 + coff);
      }
      #pragma unroll
      for (int mt = 0; mt < 2; mt++)
        #pragma unroll
        for (int sub = 0; sub < 2; sub++) {
          mma16816(acc[mt][sub], Fh[mt], Gh4[sub * 2], Gh4[sub * 2 + 1]);
          mma16816(acc[mt][sub], Fh[mt], Gl4[sub * 2], Gl4[sub * 2 + 1]);
          mma16816(acc[mt][sub], Fl[mt], Gh4[sub * 2], Gh4[sub * 2 + 1]);
        }
    }
    __syncthreads();
  }

  if (mtr) {
    #pragma unroll
    for (int mt = 0; mt < 2; mt++)
      #pragma unroll
      for (int nt = 0; nt < 2; nt++) {
        int w = my + mt * 16 + gI;
        int c = c0 + nw + nt * 8 + 2 * tq;
        split_bf(acc[mt][nt][0] + g_v1[c],     g_MTh[b][w][c],     g_MTl[b][w][c]);
        split_bf(acc[mt][nt][1] + g_v1[c + 1], g_MTh[b][w][c + 1], g_MTl[b][w][c + 1]);
        split_bf(acc[mt][nt][2] + g_v1[c],     g_MTh[b][w + 8][c],     g_MTl[b][w + 8][c]);
        split_bf(acc[mt][nt][3] + g_v1[c + 1], g_MTh[b][w + 8][c + 1], g_MTl[b][w + 8][c + 1]);
      }
  } else {
    #pragma unroll
    for (int mt = 0; mt < 2; mt++)
      #pragma unroll
      for (int nt = 0; nt < 2; nt++) {
        int c = c0 + my + mt * 16 + gI;
        int w = nw + nt * 8 + 2 * tq;
        float bv0 = bv[c], bv8 = bv[c + 8];
        split_bf(acc[mt][nt][0] + bv0, g_vbh[b][c][w],     g_vbl[b][c][w]);
        split_bf(acc[mt][nt][1] + bv0, g_vbh[b][c][w + 1], g_vbl[b][c][w + 1]);
        split_bf(acc[mt][nt][2] + bv8, g_vbh[b][c + 8][w],     g_vbl[b][c + 8][w]);
        split_bf(acc[mt][nt][3] + bv8, g_vbh[b][c + 8][w + 1], g_vbl[b][c + 8][w + 1]);
      }
  }
}

// =============================================================================
// k_fused: n-tile 64, 2 blocks/SM, 32x32 warp tiles.
// phase 1: k-split across warp halves + Ef reduction. phase 2: 128c chunks.
// =============================================================================
#define XA0 0
#define XALO 9216            // lo offset within buffer (hi 64x144)
#define XABUF 18432          // 2 buffers end 36864
#define MB0 36864
#define MBLO 9216
#define MBSZ 18432           // 2 buffers end 73728
#define EF_OFF 73728         // 64*68*4 = 17408 -> end 91136
#define ATT_H 0              // aliases XA buf0 (dead after phase 1)
#define ATT_L 9216
#define VB0 18432            // aliases XA buf1 + MB buf0 (dead when written)
#define VBLO 18432           // lo offset within VB buffer (hi 128x144)
#define VBSZ 36864
#define VB1 55296            // aliases MB buf1 + Ef (dead when written)
#define SMEM_FUSED 92160

__global__ __launch_bounds__(256, 2)
void k_fused(const float* __restrict__ x, const float* __restrict__ gamma,
             float* __restrict__ out) {
  extern __shared__ char sm[];
  unsigned sb = (unsigned)__cvta_generic_to_shared(sm);
  int tid = threadIdx.x;
  int wid = tid >> 5, lane = tid & 31;
  int b = blockIdx.y;
  int n0 = blockIdx.x * 64;
  int gI = lane >> 2, tq = lane & 3;

  const float* xb = x + (size_t)b * NC * NN + n0;
  int rc = tid >> 4, ln4 = tid & 15;         // x loader: c row base, n 8B-unit

  float4 xr[4];
  auto load_x = [&](int c0) {
    #pragma unroll
    for (int z = 0; z < 4; z++)
      xr[z] = *(const float4*)(xb + (size_t)(c0 + rc + z * 16) * NN + ln4 * 4);
  };
  auto store_x = [&](unsigned xbase) {
    #pragma unroll
    for (int z = 0; z < 4; z++) {
      uint2 h, l;
      hilo2((const float*)&xr[z], h, l);
      unsigned base0 = xbase + (rc + z * 16) * 144 + ln4 * 8;
      *(uint2*)(sm + base0) = h;
      *(uint2*)(sm + base0 + XALO) = l;
    }
  };
  auto issue_M = [&](int c0, unsigned mb) {
    #pragma unroll
    for (int u = tid; u < 512; u += 256) {
      int rr = u >> 3, q = u & 7;
      cp16(sb + mb + rr * 144 + q * 16,        &g_MTh[b][rr][c0 + q * 8]);
      cp16(sb + mb + MBLO + rr * 144 + q * 16, &g_MTl[b][rr][c0 + q * 8]);
    }
  };
  auto issue_VB = [&](int cc, unsigned base) {
    #pragma unroll
    for (int u = tid; u < 1024; u += 256) {
      int rr = u >> 3, q = u & 7;
      cp16(sb + base + rr * 144 + q * 16,        &g_vbh[b][cc * 128 + rr][q * 8]);
      cp16(sb + base + VBLO + rr * 144 + q * 16, &g_vbl[b][cc * 128 + rr][q * 8]);
    }
  };

  // ---------------- phase 1: E[64n][64w], k-split across warp halves ----------
  int wq = wid & 3, khalf = wid >> 2;
  int ny = (wq >> 1) * 32, wy = (wq & 1) * 32;
  int ksb = khalf * 32;
  float acc1[2][4][4] = {};

  auto mma_chunk = [&](unsigned xab, unsigned mbb) {
    #pragma unroll
    for (int ks = 0; ks < 32; ks += 16) {
      int kk = ksb + ks;
      unsigned Ah[2][4], Al[2][4];
      unsigned arow = kk + (lane & 7) + ((lane & 16) >> 1);
      #pragma unroll
      for (int mt = 0; mt < 2; mt++) {
        unsigned acol = ny + mt * 16 + (lane & 8);
        unsigned aaddr = sb + xab + arow * 144 + acol * 2;
        ldsm4t(Ah[mt][0], Ah[mt][1], Ah[mt][2], Ah[mt][3], aaddr);
        ldsm4t(Al[mt][0], Al[mt][1], Al[mt][2], Al[mt][3], aaddr + XALO);
      }
      unsigned Bh[2][4], Bl[2][4];
      #pragma unroll
      for (int bt = 0; bt < 2; bt++) {
        unsigned brow = wy + bt * 16 + (lane & 7) + ((lane & 16) >> 1);
        unsigned coff = kk * 2 + ((lane & 8) << 1);
        unsigned baddr = sb + mbb + brow * 144 + coff;
        ldsm4(Bh[bt][0], Bh[bt][1], Bh[bt][2], Bh[bt][3], baddr);
        ldsm4(Bl[bt][0], Bl[bt][1], Bl[bt][2], Bl[bt][3], baddr + MBLO);
      }
      #pragma unroll
      for (int mt = 0; mt < 2; mt++)
        #pragma unroll
        for (int bt = 0; bt < 2; bt++)
          #pragma unroll
          for (int sub = 0; sub < 2; sub++) {
            int wt = bt * 2 + sub;
            mma16816(acc1[mt][wt], Ah[mt], Bh[bt][sub * 2], Bh[bt][sub * 2 + 1]);
            mma16816(acc1[mt][wt], Ah[mt], Bl[bt][sub * 2], Bl[bt][sub * 2 + 1]);
            mma16816(acc1[mt][wt], Al[mt], Bh[bt][sub * 2], Bh[bt][sub * 2 + 1]);
          }
    }
  };

  load_x(0);
  issue_M(0, MB0); CP_COMMIT();
  store_x(XA0);
  CP_WAIT(0);
  __syncthreads();

  for (int i = 0; i < 8; i++) {
    if (i < 7) {
      load_x((i + 1) * 64);
      issue_M((i + 1) * 64, MB0 + ((i + 1) & 1) * MBSZ); CP_COMMIT();
    }
    mma_chunk(XA0 + (i & 1) * XABUF, MB0 + (i & 1) * MBSZ);
    if (i < 7) {
      store_x(XA0 + ((i + 1) & 1) * XABUF);
      CP_WAIT(0);
    }
    __syncthreads();
  }

  issue_VB(0, VB0);
  CP_COMMIT();

  // reduction: khalf 0 writes (with dw), khalf 1 adds
  float* Ef = (float*)(sm + EF_OFF);
  if (khalf == 0) {
    #pragma unroll
    for (int wt = 0; wt < 4; wt++) {
      int wc = wy + (wt >> 1) * 16 + (wt & 1) * 8 + 2 * tq;
      float d0 = g_dw[b][wc], d1 = g_dw[b][wc + 1];
      #pragma unroll
      for (int mt = 0; mt < 2; mt++) {
        int r = ny + mt * 16 + gI;
        float2 v0 = {acc1[mt][wt][0] + d0, acc1[mt][wt][1] + d1};
        float2 v1 = {acc1[mt][wt][2] + d0, acc1[mt][wt][3] + d1};
        *(float2*)&Ef[r * 68 + wc] = v0;
        *(float2*)&Ef[(r + 8) * 68 + wc] = v1;
      }
    }
  }
  __syncthreads();
  if (khalf == 1) {
    #pragma unroll
    for (int wt = 0; wt < 4; wt++) {
      int wc = wy + (wt >> 1) * 16 + (wt & 1) * 8 + 2 * tq;
      #pragma unroll
      for (int mt = 0; mt < 2; mt++) {
        int r = ny + mt * 16 + gI;
        float2 v0 = *(float2*)&Ef[r * 68 + wc];
        float2 v1 = *(float2*)&Ef[(r + 8) * 68 + wc];
        v0.x += acc1[mt][wt][0]; v0.y += acc1[mt][wt][1];
        v1.x += acc1[mt][wt][2]; v1.y += acc1[mt][wt][3];
        *(float2*)&Ef[r * 68 + wc] = v0;
        *(float2*)&Ef[(r + 8) * 68 + wc] = v1;
      }
    }
  }
  __syncthreads();

  // softmax over w (4 threads/row, 64 rows)
  {
    int row = tid >> 2, q = tid & 3;
    float mx = -1e30f;
    for (int w = q; w < NW; w += 4) mx = fmaxf(mx, Ef[row * 68 + w]);
    mx = fmaxf(mx, __shfl_xor_sync(0xffffffffu, mx, 1));
    mx = fmaxf(mx, __shfl_xor_sync(0xffffffffu, mx, 2));
    float s = 0.f;
    for (int w = q; w < NW; w += 4) {
      float e = __expf(Ef[row * 68 + w] - mx);
      Ef[row * 68 + w] = e;
      s += e;
    }
    s += __shfl_xor_sync(0xffffffffu, s, 1);
    s += __shfl_xor_sync(0xffffffffu, s, 2);
    float inv = 1.0f / s;
    for (int w = q; w < NW; w += 4) Ef[row * 68 + w] *= inv;
  }
  __syncthreads();

  // convert attn to bf16 hi/lo [n][w], rows 144B (aliases XA buf0)
  #pragma unroll
  for (int i = 0; i < 8; i++) {
    int p = tid + i * 256;
    int n = p >> 5, wp = p & 31;
    float e0 = Ef[n * 68 + 2 * wp], e1 = Ef[n * 68 + 2 * wp + 1];
    float h0 = __bfloat162float(__float2bfloat16(e0));
    float h1 = __bfloat162float(__float2bfloat16(e1));
    *(unsigned*)(sm + ATT_H + n * 144 + wp * 4) = pack_bf2(e0, e1);
    *(unsigned*)(sm + ATT_L + n * 144 + wp * 4) = pack_bf2(e0 - h0, e1 - h1);
  }
  // RACE FIX: VB1 (issued in phase 2's first iteration) aliases the Ef region.
  // All warps must finish reading Ef above before any warp's cp.async can
  // overwrite it.
  __syncthreads();

  // ---------------- phase 2: out = gamma*(vbar @ A^T) + x, 128c chunks --------
  float g = gamma[0];
  int cy = (wid >> 1) * 32;
  int nx = (wid & 1) * 32;
  for (int cc = 0; cc < 4; cc++) {
    if (cc < 3) {
      issue_VB(cc + 1, ((cc + 1) & 1) ? VB1 : VB0);
      CP_COMMIT();
      CP_WAIT(1);
    } else {
      CP_WAIT(0);
    }
    __syncthreads();

    unsigned vbb = (cc & 1) ? VB1 : VB0;
    float acc2[2][4][4] = {};
    #pragma unroll
    for (int ks = 0; ks < 64; ks += 16) {
      unsigned Ah[2][4], Al[2][4];
      #pragma unroll
      for (int mt = 0; mt < 2; mt++) {
        unsigned row = cy + mt * 16 + (lane & 15);
        unsigned coff = ks * 2 + ((lane >> 4) << 4);
        unsigned aaddr = sb + vbb + row * 144 + coff;
        ldsm4(Ah[mt][0], Ah[mt][1], Ah[mt][2], Ah[mt][3], aaddr);
        ldsm4(Al[mt][0], Al[mt][1], Al[mt][2], Al[mt][3], aaddr + VBLO);
      }
      unsigned Bh[2][4], Bl[2][4];
      #pragma unroll
      for (int bt = 0; bt < 2; bt++) {
        unsigned row = nx + bt * 16 + (lane & 7) + ((lane & 16) >> 1);
        unsigned coff = ks * 2 + ((lane & 8) << 1);
        ldsm4(Bh[bt][0], Bh[bt][1], Bh[bt][2], Bh[bt][3], sb + ATT_H + row * 144 + coff);
        ldsm4(Bl[bt][0], Bl[bt][1], Bl[bt][2], Bl[bt][3], sb + ATT_L + row * 144 + coff);
      }
      #pragma unroll
      for (int mt = 0; mt < 2; mt++)
        #pragma unroll
        for (int bt = 0; bt < 2; bt++)
          #pragma unroll
          for (int sub = 0; sub < 2; sub++) {
            int nt = bt * 2 + sub;
            mma16816(acc2[mt][nt], Ah[mt], Bh[bt][sub * 2], Bh[bt][sub * 2 + 1]);
            mma16816(acc2[mt][nt], Ah[mt], Bl[bt][sub * 2], Bl[bt][sub * 2 + 1]);
            mma16816(acc2[mt][nt], Al[mt], Bh[bt][sub * 2], Bh[bt][sub * 2 + 1]);
          }
    }
    // epilogue: residual add + store
    #pragma unroll
    for (int mt = 0; mt < 2; mt++) {
      int c = cc * 128 + cy + mt * 16 + gI;
      #pragma unroll
      for (int nt = 0; nt < 4; nt++) {
        int n = n0 + nx + (nt >> 1) * 16 + (nt & 1) * 8 + 2 * tq;
        size_t off = ((size_t)(b * NC + c)) * NN + n;
        float2 xv0 = *(const float2*)(x + off);
        float2 xv1 = *(const float2*)(x + off + (size_t)8 * NN);
        float2 o0 = {fmaf(g, acc2[mt][nt][0], xv0.x), fmaf(g, acc2[mt][nt][1], xv0.y)};
        float2 o1 = {fmaf(g, acc2[mt][nt][2], xv1.x), fmaf(g, acc2[mt][nt][3], xv1.y)};
        *(float2*)(out + off) = o0;
        *(float2*)(out + off + (size_t)8 * NN) = o1;
      }
    }
    __syncthreads();
  }
}

// ---------------- launch -----------------------------------------------------
extern "C" void kernel_launch(void* const* d_in, const int* in_sizes, int n_in,
                              void* d_out, int out_size) {
  const float* x     = (const float*)d_in[0];
  const float* Wq    = (const float*)d_in[1];
  const float* bq    = (const float*)d_in[2];
  const float* Wk    = (const float*)d_in[3];
  const float* bk    = (const float*)d_in[4];
  const float* Wv    = (const float*)d_in[5];
  const float* bv    = (const float*)d_in[6];
  const float* gamma = (const float*)d_in[7];
  const float* pe    = (const float*)d_in[8];
  const int*   pos   = (const int*)  d_in[9];
  float* out = (float*)d_out;

  cudaFuncSetAttribute(k_MV, cudaFuncAttributeMaxDynamicSharedMemorySize, MV_SMEM);
  cudaFuncSetAttribute(k_fused, cudaFuncAttributeMaxDynamicSharedMemorySize,
                       SMEM_FUSED);

  k_front<<<2152, 256>>>(x, pos, pe, Wq, Wk, Wv, bq, bk);
  k_trans<<<32, 256>>>();
  k_MV<<<68, 256, MV_SMEM>>>(bv);
  k_fused<<<dim3(NN / 64, NB), 256, SMEM_FUSED>>>(x, gamma, out);
}

// round 14
// speedup vs baseline: 1.5992x; 1.0020x over previous
#include <cuda_runtime.h>
#include <cuda_bf16.h>

#define NB 4
#define NC 512
#define CKQ 256
#define NW 64
#define NH 64
#define NN 4096   // H*W

// ---------------- scratch (device globals) ----------------------------------
__device__ float g_xbar[NB][NC][NW];
__device__ float g_x2df[NB][NC][NW];
__device__ __align__(16) __nv_bfloat16 g_Gh[NC][NC], g_Gl[NC][NC];
__device__ __align__(16) __nv_bfloat16 g_Wvh[NC][NC], g_Wvl[NC][NC];
__device__ __align__(16) __nv_bfloat16 g_MTh[NB][NW][NC], g_MTl[NB][NW][NC];
__device__ __align__(16) __nv_bfloat16 g_vbh[NB][NC][NW], g_vbl[NB][NC][NW];
__device__ float g_v1[NC];        // Wq^T bk
__device__ float g_v2[NC];        // Wk^T bq
__device__ float g_s0;            // bq . bk
__device__ float g_dw[NB][NW];

// ---------------- helpers ----------------------------------------------------
__device__ __forceinline__ unsigned pack_bf2(float e, float o) {
  __nv_bfloat162 h;
  h.x = __float2bfloat16(e);
  h.y = __float2bfloat16(o);
  return *reinterpret_cast<unsigned*>(&h);
}
__device__ __forceinline__ void split_bf(float v, __nv_bfloat16& h, __nv_bfloat16& l) {
  h = __float2bfloat16(v);
  l = __float2bfloat16(v - __bfloat162float(h));
}
__device__ __forceinline__ void hilo2(const float* a, uint2& h, uint2& l) {
  float h0 = __bfloat162float(__float2bfloat16(a[0]));
  float h1 = __bfloat162float(__float2bfloat16(a[1]));
  float h2 = __bfloat162float(__float2bfloat16(a[2]));
  float h3 = __bfloat162float(__float2bfloat16(a[3]));
  h.x = pack_bf2(a[0], a[1]);
  h.y = pack_bf2(a[2], a[3]);
  l.x = pack_bf2(a[0] - h0, a[1] - h1);
  l.y = pack_bf2(a[2] - h2, a[3] - h3);
}
__device__ __forceinline__ void ldsm4(unsigned& r0, unsigned& r1, unsigned& r2,
                                      unsigned& r3, unsigned addr) {
  asm volatile("ldmatrix.sync.aligned.m8n8.x4.shared.b16 {%0,%1,%2,%3},[%4];"
               : "=r"(r0), "=r"(r1), "=r"(r2), "=r"(r3) : "r"(addr));
}
__device__ __forceinline__ void ldsm4t(unsigned& r0, unsigned& r1, unsigned& r2,
                                       unsigned& r3, unsigned addr) {
  asm volatile("ldmatrix.sync.aligned.m8n8.x4.trans.shared.b16 {%0,%1,%2,%3},[%4];"
               : "=r"(r0), "=r"(r1), "=r"(r2), "=r"(r3) : "r"(addr));
}
__device__ __forceinline__ void mma16816(float* d, const unsigned* a,
                                         unsigned b0, unsigned b1) {
  asm volatile(
    "mma.sync.aligned.m16n8k16.row.col.f32.bf16.bf16.f32 "
    "{%0,%1,%2,%3},{%4,%5,%6,%7},{%8,%9},{%0,%1,%2,%3};"
    : "+f"(d[0]), "+f"(d[1]), "+f"(d[2]), "+f"(d[3])
    : "r"(a[0]), "r"(a[1]), "r"(a[2]), "r"(a[3]), "r"(b0), "r"(b1));
}
__device__ __forceinline__ void cp16(unsigned saddr, const void* g) {
  asm volatile("cp.async.cg.shared.global [%0],[%1],16;" :: "r"(saddr), "l"(g));
}
#define CP_COMMIT() asm volatile("cp.async.commit_group;")
#define CP_WAIT(n)  asm volatile("cp.async.wait_group %0;" :: "n"(n))

// =============================================================================
// k_front: [0,2048) prep | [2048,2112) G | [2112,2144) Wv conv | [2144,2152) bias
// =============================================================================
#define GA_H 0
#define GA_L 4608
#define GB_H 9216
#define GB_L 13824

__global__ __launch_bounds__(256)
void k_front(const float* __restrict__ x, const int* __restrict__ pos,
             const float* __restrict__ pe, const float* __restrict__ Wq,
             const float* __restrict__ Wk, const float* __restrict__ Wv,
             const float* __restrict__ bq, const float* __restrict__ bk) {
  __shared__ float4 sm4[16][16];
  __shared__ float xbv[64];
  __shared__ float x1s[16];
  __shared__ int pidx[16];
  __shared__ __align__(16) char gsm[18432];

  int bx = blockIdx.x;
  int t = threadIdx.x;

  if (bx < 2048) {                     // ---------------- prep ----------------
    int c = bx & 511, b = bx >> 9;
    int hq = t >> 4, tw = t & 15;
    const float* xp = x + ((size_t)(b * NC + c)) * NH * NW;
    float4 s = {0.f, 0.f, 0.f, 0.f};
    #pragma unroll
    for (int h = hq; h < NH; h += 16) {
      float4 v = *(const float4*)&xp[h * NW + tw * 4];
      s.x += v.x; s.y += v.y; s.z += v.z; s.w += v.w;
    }
    sm4[hq][tw] = s;
    if (t < 16) pidx[t] = pos[b * NN + 4 * t] >> 3;
    __syncthreads();
    if (hq == 0) {
      float4 a = {0.f, 0.f, 0.f, 0.f};
      #pragma unroll
      for (int q = 0; q < 16; q++) {
        float4 v = sm4[q][tw];
        a.x += v.x; a.y += v.y; a.z += v.z; a.w += v.w;
      }
      const float inv = 1.0f / NH;
      a.x *= inv; a.y *= inv; a.z *= inv; a.w *= inv;
      *(float4*)&xbv[tw * 4] = a;
      *(float4*)&g_xbar[b][c][tw * 4] = a;
    }
    __syncthreads();
    if (t < 16)
      x1s[t] = 0.25f * (xbv[4*t] + xbv[4*t+1] + xbv[4*t+2] + xbv[4*t+3])
               + pe[pidx[t] * NC + c];
    __syncthreads();
    if (t < NW) {
      float src = (t * 15.0f) / 63.0f;
      int   i0  = (int)floorf(src);
      int   i1  = min(i0 + 1, 15);
      float tt  = src - (float)i0;
      g_x2df[b][c][t] = x1s[i0] * (1.0f - tt) + x1s[i1] * tt;
    }
    return;
  }

  if (bx < 2112) {                     // ---------------- G = Wq^T Wk ----------
    int gx = bx - 2048;
    int cx = gx & 7, kx = gx >> 3;
    unsigned sb = (unsigned)__cvta_generic_to_shared(gsm);
    int wid = t >> 5, lane = t & 31;
    int my = (wid >> 2) * 32, nw = (wid & 3) * 16;
    int gI = lane >> 2, tq = lane & 3;
    float acc[2][2][4] = {};
    int rr0 = t >> 4, c4 = t & 15;
    for (int o0 = 0; o0 < CKQ; o0 += 32) {
      #pragma unroll
      for (int z = 0; z < 2; z++) {
        int row = rr0 + z * 16;
        float4 v = *(const float4*)&Wq[(size_t)(o0 + row) * NC + cx * 64 + c4 * 4];
        uint2 h, l;
        hilo2((const float*)&v, h, l);
        *(uint2*)(gsm + GA_H + row * 144 + c4 * 8) = h;
        *(uint2*)(gsm + GA_L + row * 144 + c4 * 8) = l;
        float4 w = *(const float4*)&Wk[(size_t)(o0 + row) * NC + kx * 64 + c4 * 4];
        hilo2((const float*)&w, h, l);
        *(uint2*)(gsm + GB_H + row * 144 + c4 * 8) = h;
        *(uint2*)(gsm + GB_L + row * 144 + c4 * 8) = l;
      }
      __syncthreads();
      #pragma unroll
      for (int ks = 0; ks < 32; ks += 16) {
        unsigned Ah[2][4], Al[2][4];
        unsigned arow = ks + (lane & 7) + ((lane & 16) >> 1);
        #pragma unroll
        for (int mt = 0; mt < 2; mt++) {
          unsigned mcol = my + mt * 16 + (lane & 8);
          unsigned aaddr = sb + GA_H + arow * 144 + mcol * 2;
          ldsm4t(Ah[mt][0], Ah[mt][1], Ah[mt][2], Ah[mt][3], aaddr);
          ldsm4t(Al[mt][0], Al[mt][1], Al[mt][2], Al[mt][3], aaddr + (GA_L - GA_H));
        }
        unsigned Bh[4], Bl[4];
        {
          unsigned brow = ks + (lane & 7) + (lane & 8);
          unsigned bcol = nw + ((lane & 16) >> 1);
          unsigned baddr = sb + GB_H + brow * 144 + bcol * 2;
          ldsm4t(Bh[0], Bh[1], Bh[2], Bh[3], baddr);
          ldsm4t(Bl[0], Bl[1], Bl[2], Bl[3], baddr + (GB_L - GB_H));
        }
        #pragma unroll
        for (int mt = 0; mt < 2; mt++)
          #pragma unroll
          for (int sub = 0; sub < 2; sub++) {
            mma16816(acc[mt][sub], Ah[mt], Bh[sub * 2], Bh[sub * 2 + 1]);
            mma16816(acc[mt][sub], Ah[mt], Bl[sub * 2], Bl[sub * 2 + 1]);
            mma16816(acc[mt][sub], Al[mt], Bh[sub * 2], Bh[sub * 2 + 1]);
          }
      }
      __syncthreads();
    }
    #pragma unroll
    for (int mt = 0; mt < 2; mt++)
      #pragma unroll
      for (int nt = 0; nt < 2; nt++) {
        int cg = cx * 64 + my + mt * 16 + gI;
        int kg = kx * 64 + nw + nt * 8 + 2 * tq;
        split_bf(acc[mt][nt][0], g_Gh[cg][kg],     g_Gl[cg][kg]);
        split_bf(acc[mt][nt][1], g_Gh[cg][kg + 1], g_Gl[cg][kg + 1]);
        split_bf(acc[mt][nt][2], g_Gh[cg + 8][kg],     g_Gl[cg + 8][kg]);
        split_bf(acc[mt][nt][3], g_Gh[cg + 8][kg + 1], g_Gl[cg + 8][kg + 1]);
      }
    return;
  }

  if (bx < 2144) {                     // ---------------- Wv convert -----------
    int base = (bx - 2112) * 2048;
    #pragma unroll
    for (int j = 0; j < 8; j++) {
      int idx4 = base + j * 256 + t;
      float4 v = ((const float4*)Wv)[idx4];
      __nv_bfloat16 h0, l0, h1, l1;
      split_bf(v.x, h0, l0); split_bf(v.y, h1, l1);
      ((__nv_bfloat162*)g_Wvh)[idx4 * 2] = {h0, h1};
      ((__nv_bfloat162*)g_Wvl)[idx4 * 2] = {l0, l1};
      split_bf(v.z, h0, l0); split_bf(v.w, h1, l1);
      ((__nv_bfloat162*)g_Wvh)[idx4 * 2 + 1] = {h0, h1};
      ((__nv_bfloat162*)g_Wvl)[idx4 * 2 + 1] = {l0, l1};
    }
    return;
  }

  // ---------------- bias blocks ----------------------------------------------
  {
    int c = (bx - 2144) * 64 + (t >> 2);
    int q = t & 3;
    float s1 = 0.f, s2 = 0.f;
    #pragma unroll 8
    for (int o = q; o < CKQ; o += 4) {
      s1 += Wq[(size_t)o * NC + c] * bk[o];
      s2 += Wk[(size_t)o * NC + c] * bq[o];
    }
    s1 += __shfl_xor_sync(0xffffffffu, s1, 1);
    s1 += __shfl_xor_sync(0xffffffffu, s1, 2);
    s2 += __shfl_xor_sync(0xffffffffu, s2, 1);
    s2 += __shfl_xor_sync(0xffffffffu, s2, 2);
    if (q == 0) { g_v1[c] = s1; g_v2[c] = s2; }
    if (bx == 2144 && t < 32) {
      float s = 0.f;
      for (int o = t; o < CKQ; o += 32) s += bq[o] * bk[o];
      #pragma unroll
      for (int d = 16; d > 0; d >>= 1) s += __shfl_xor_sync(0xffffffffu, s, d);
      if (t == 0) g_s0 = s;
    }
  }
}

// =============================================================================
// k_MV: [0,32) M^T tiles | [32,64) vbar tiles | [64,68) dw
// f32 operand (x2df / xbar) converted inline to bf16 hi/lo smem (no k_trans).
//   M^T  tile: A = x2df via ldsm.trans, B = G via cp.async + ldsm
//   vbar tile: A = Wv via cp.async + ldsm, B = xbar via ldsm.trans (B-trans addr)
// =============================================================================
#define ACV0 0
#define ACVLO 9216
#define ACVBUF 18432         // 2 buffers end 36864
#define CPB0 36864
#define CPBLO 9216
#define CPBSZ 18432          // 2 buffers end 73728
#define MV_SMEM 73728

__global__ __launch_bounds__(256)
void k_MV(const float* __restrict__ bv) {
  extern __shared__ char dsm[];
  unsigned sb = (unsigned)__cvta_generic_to_shared(dsm);
  int bx = blockIdx.x, tid = threadIdx.x;

  if (bx >= 64) {                      // dw: sum_c x2d[c][w] * v2[c]
    int b = bx - 64;
    int w = tid >> 2, q = tid & 3;
    float s = 0.f;
    #pragma unroll 8
    for (int c = q; c < NC; c += 4) s += g_x2df[b][c][w] * g_v2[c];
    s += __shfl_xor_sync(0xffffffffu, s, 1);
    s += __shfl_xor_sync(0xffffffffu, s, 2);
    if (q == 0) g_dw[b][w] = s + g_s0;
    return;
  }

  bool mtr = (bx < 32);
  int b  = mtr ? (bx >> 3) : ((bx - 32) >> 3);
  int c0 = (mtr ? (bx & 7) : ((bx - 32) & 7)) * 64;
  const float* Xf = mtr ? &g_x2df[b][0][0] : &g_xbar[b][0][0];
  const __nv_bfloat16* Bhg = mtr ? &g_Gh[c0][0] : &g_Wvh[c0][0];
  const __nv_bfloat16* Blg = mtr ? &g_Gl[c0][0] : &g_Wvl[c0][0];

  int rc = tid >> 4, ln4 = tid & 15;
  float4 xr[4];
  auto load_f = [&](int k0) {
    #pragma unroll
    for (int z = 0; z < 4; z++)
      xr[z] = *(const float4*)&Xf[(size_t)(k0 + rc + z * 16) * NW + ln4 * 4];
  };
  auto store_f = [&](unsigned base) {
    #pragma unroll
    for (int z = 0; z < 4; z++) {
      uint2 h, l;
      hilo2((const float*)&xr[z], h, l);
      unsigned a = base + (rc + z * 16) * 144 + ln4 * 8;
      *(uint2*)(dsm + a) = h;
      *(uint2*)(dsm + a + ACVLO) = l;
    }
  };
  auto issueB = [&](int k0, unsigned base) {
    #pragma unroll
    for (int u = tid; u < 512; u += 256) {
      int r = u >> 3, q = u & 7;
      cp16(sb + base + r * 144 + q * 16,         Bhg + (size_t)r * NC + k0 + q * 8);
      cp16(sb + base + CPBLO + r * 144 + q * 16, Blg + (size_t)r * NC + k0 + q * 8);
    }
  };

  int wid = tid >> 5, lane = tid & 31;
  int my = (wid >> 2) * 32, nw = (wid & 3) * 16;
  int gI = lane >> 2, tq = lane & 3;
  float acc[2][2][4] = {};

  load_f(0);
  issueB(0, CPB0); CP_COMMIT();
  store_f(ACV0);
  CP_WAIT(0);
  __syncthreads();

  for (int kc = 0; kc < 8; kc++) {
    if (kc < 7) {
      load_f((kc + 1) * 64);
      issueB((kc + 1) * 64, CPB0 + ((kc + 1) & 1) * CPBSZ); CP_COMMIT();
    }
    unsigned acv = ACV0 + (kc & 1) * ACVBUF;
    unsigned cpb = CPB0 + (kc & 1) * CPBSZ;
    if (mtr) {
      // A = x2d (trans from [k][w]): m=w rows.  B = G (non-trans [cout][k]).
      #pragma unroll
      for (int ks = 0; ks < 64; ks += 16) {
        unsigned Ah[2][4], Al[2][4];
        unsigned arow = ks + (lane & 7) + ((lane & 16) >> 1);
        #pragma unroll
        for (int mt = 0; mt < 2; mt++) {
          unsigned acol = my + mt * 16 + (lane & 8);
          unsigned aaddr = sb + acv + arow * 144 + acol * 2;
          ldsm4t(Ah[mt][0], Ah[mt][1], Ah[mt][2], Ah[mt][3], aaddr);
          ldsm4t(Al[mt][0], Al[mt][1], Al[mt][2], Al[mt][3], aaddr + ACVLO);
        }
        unsigned Bh[4], Bl[4];
        {
          unsigned row = nw + (lane & 7) + ((lane & 16) >> 1);
          unsigned coff = ks * 2 + ((lane & 8) << 1);
          unsigned baddr = sb + cpb + row * 144 + coff;
          ldsm4(Bh[0], Bh[1], Bh[2], Bh[3], baddr);
          ldsm4(Bl[0], Bl[1], Bl[2], Bl[3], baddr + CPBLO);
        }
        #pragma unroll
        for (int mt = 0; mt < 2; mt++)
          #pragma unroll
          for (int sub = 0; sub < 2; sub++) {
            mma16816(acc[mt][sub], Ah[mt], Bh[sub * 2], Bh[sub * 2 + 1]);
            mma16816(acc[mt][sub], Ah[mt], Bl[sub * 2], Bl[sub * 2 + 1]);
            mma16816(acc[mt][sub], Al[mt], Bh[sub * 2], Bh[sub * 2 + 1]);
          }
      }
    } else {
      // A = Wv (non-trans [cout][k]).  B = xbar (trans from [k][w]): n=w.
      #pragma unroll
      for (int ks = 0; ks < 64; ks += 16) {
        unsigned Ah[2][4], Al[2][4];
        #pragma unroll
        for (int mt = 0; mt < 2; mt++) {
          unsigned row = my + mt * 16 + (lane & 15);
          unsigned coff = ks * 2 + ((lane >> 4) << 4);
          unsigned aaddr = sb + cpb + row * 144 + coff;
          ldsm4(Ah[mt][0], Ah[mt][1], Ah[mt][2], Ah[mt][3], aaddr);
          ldsm4(Al[mt][0], Al[mt][1], Al[mt][2], Al[mt][3], aaddr + CPBLO);
        }
        unsigned Bh[4], Bl[4];
        {
          unsigned brow = ks + (lane & 7) + (lane & 8);
          unsigned bcol = nw + ((lane & 16) >> 1);
          unsigned baddr = sb + acv + brow * 144 + bcol * 2;
          ldsm4t(Bh[0], Bh[1], Bh[2], Bh[3], baddr);
          ldsm4t(Bl[0], Bl[1], Bl[2], Bl[3], baddr + ACVLO);
        }
        #pragma unroll
        for (int mt = 0; mt < 2; mt++)
          #pragma unroll
          for (int sub = 0; sub < 2; sub++) {
            mma16816(acc[mt][sub], Ah[mt], Bh[sub * 2], Bh[sub * 2 + 1]);
            mma16816(acc[mt][sub], Ah[mt], Bl[sub * 2], Bl[sub * 2 + 1]);
            mma16816(acc[mt][sub], Al[mt], Bh[sub * 2], Bh[sub * 2 + 1]);
          }
      }
    }
    if (kc < 7) {
      store_f(ACV0 + ((kc + 1) & 1) * ACVBUF);
      CP_WAIT(0);
    }
    __syncthreads();
  }

  if (mtr) {
    #pragma unroll
    for (int mt = 0; mt < 2; mt++)
      #pragma unroll
      for (int nt = 0; nt < 2; nt++) {
        int w = my + mt * 16 + gI;
        int c = c0 + nw + nt * 8 + 2 * tq;
        split_bf(acc[mt][nt][0] + g_v1[c],     g_MTh[b][w][c],     g_MTl[b][w][c]);
        split_bf(acc[mt][nt][1] + g_v1[c + 1], g_MTh[b][w][c + 1], g_MTl[b][w][c + 1]);
        split_bf(acc[mt][nt][2] + g_v1[c],     g_MTh[b][w + 8][c],     g_MTl[b][w + 8][c]);
        split_bf(acc[mt][nt][3] + g_v1[c + 1], g_MTh[b][w + 8][c + 1], g_MTl[b][w + 8][c + 1]);
      }
  } else {
    #pragma unroll
    for (int mt = 0; mt < 2; mt++)
      #pragma unroll
      for (int nt = 0; nt < 2; nt++) {
        int c = c0 + my + mt * 16 + gI;
        int w = nw + nt * 8 + 2 * tq;
        float bv0 = bv[c], bv8 = bv[c + 8];
        split_bf(acc[mt][nt][0] + bv0, g_vbh[b][c][w],     g_vbl[b][c][w]);
        split_bf(acc[mt][nt][1] + bv0, g_vbh[b][c][w + 1], g_vbl[b][c][w + 1]);
        split_bf(acc[mt][nt][2] + bv8, g_vbh[b][c + 8][w],     g_vbl[b][c + 8][w]);
        split_bf(acc[mt][nt][3] + bv8, g_vbh[b][c + 8][w + 1], g_vbl[b][c + 8][w + 1]);
      }
  }
}

// =============================================================================
// k_fused: n-tile 64, 2 blocks/SM, 32x32 warp tiles.
// phase 1: k-split across warp halves + Ef reduction. phase 2: 128c chunks.
// =============================================================================
#define XA0 0
#define XALO 9216            // lo offset within buffer (hi 64x144)
#define XABUF 18432          // 2 buffers end 36864
#define MB0 36864
#define MBLO 9216
#define MBSZ 18432           // 2 buffers end 73728
#define EF_OFF 73728         // 64*68*4 = 17408 -> end 91136
#define ATT_H 0              // aliases XA buf0 (dead after phase 1)
#define ATT_L 9216
#define VB0 18432            // aliases XA buf1 + MB buf0 (dead when written)
#define VBLO 18432           // lo offset within VB buffer (hi 128x144)
#define VBSZ 36864
#define VB1 55296            // aliases MB buf1 + Ef (dead when written)
#define SMEM_FUSED 92160

__global__ __launch_bounds__(256, 2)
void k_fused(const float* __restrict__ x, const float* __restrict__ gamma,
             float* __restrict__ out) {
  extern __shared__ char sm[];
  unsigned sb = (unsigned)__cvta_generic_to_shared(sm);
  int tid = threadIdx.x;
  int wid = tid >> 5, lane = tid & 31;
  int b = blockIdx.y;
  int n0 = blockIdx.x * 64;
  int gI = lane >> 2, tq = lane & 3;

  const float* xb = x + (size_t)b * NC * NN + n0;
  int rc = tid >> 4, ln4 = tid & 15;

  float4 xr[4];
  auto load_x = [&](int c0) {
    #pragma unroll
    for (int z = 0; z < 4; z++)
      xr[z] = *(const float4*)(xb + (size_t)(c0 + rc + z * 16) * NN + ln4 * 4);
  };
  auto store_x = [&](unsigned xbase) {
    #pragma unroll
    for (int z = 0; z < 4; z++) {
      uint2 h, l;
      hilo2((const float*)&xr[z], h, l);
      unsigned base0 = xbase + (rc + z * 16) * 144 + ln4 * 8;
      *(uint2*)(sm + base0) = h;
      *(uint2*)(sm + base0 + XALO) = l;
    }
  };
  auto issue_M = [&](int c0, unsigned mb) {
    #pragma unroll
    for (int u = tid; u < 512; u += 256) {
      int rr = u >> 3, q = u & 7;
      cp16(sb + mb + rr * 144 + q * 16,        &g_MTh[b][rr][c0 + q * 8]);
      cp16(sb + mb + MBLO + rr * 144 + q * 16, &g_MTl[b][rr][c0 + q * 8]);
    }
  };
  auto issue_VB = [&](int cc, unsigned base) {
    #pragma unroll
    for (int u = tid; u < 1024; u += 256) {
      int rr = u >> 3, q = u & 7;
      cp16(sb + base + rr * 144 + q * 16,        &g_vbh[b][cc * 128 + rr][q * 8]);
      cp16(sb + base + VBLO + rr * 144 + q * 16, &g_vbl[b][cc * 128 + rr][q * 8]);
    }
  };

  // ---------------- phase 1: E[64n][64w], k-split across warp halves ----------
  int wq = wid & 3, khalf = wid >> 2;
  int ny = (wq >> 1) * 32, wy = (wq & 1) * 32;
  int ksb = khalf * 32;
  float acc1[2][4][4] = {};

  auto mma_chunk = [&](unsigned xab, unsigned mbb) {
    #pragma unroll
    for (int ks = 0; ks < 32; ks += 16) {
      int kk = ksb + ks;
      unsigned Ah[2][4], Al[2][4];
      unsigned arow = kk + (lane & 7) + ((lane & 16) >> 1);
      #pragma unroll
      for (int mt = 0; mt < 2; mt++) {
        unsigned acol = ny + mt * 16 + (lane & 8);
        unsigned aaddr = sb + xab + arow * 144 + acol * 2;
        ldsm4t(Ah[mt][0], Ah[mt][1], Ah[mt][2], Ah[mt][3], aaddr);
        ldsm4t(Al[mt][0], Al[mt][1], Al[mt][2], Al[mt][3], aaddr + XALO);
      }
      unsigned Bh[2][4], Bl[2][4];
      #pragma unroll
      for (int bt = 0; bt < 2; bt++) {
        unsigned brow = wy + bt * 16 + (lane & 7) + ((lane & 16) >> 1);
        unsigned coff = kk * 2 + ((lane & 8) << 1);
        unsigned baddr = sb + mbb + brow * 144 + coff;
        ldsm4(Bh[bt][0], Bh[bt][1], Bh[bt][2], Bh[bt][3], baddr);
        ldsm4(Bl[bt][0], Bl[bt][1], Bl[bt][2], Bl[bt][3], baddr + MBLO);
      }
      #pragma unroll
      for (int mt = 0; mt < 2; mt++)
        #pragma unroll
        for (int bt = 0; bt < 2; bt++)
          #pragma unroll
          for (int sub = 0; sub < 2; sub++) {
            int wt = bt * 2 + sub;
            mma16816(acc1[mt][wt], Ah[mt], Bh[bt][sub * 2], Bh[bt][sub * 2 + 1]);
            mma16816(acc1[mt][wt], Ah[mt], Bl[bt][sub * 2], Bl[bt][sub * 2 + 1]);
            mma16816(acc1[mt][wt], Al[mt], Bh[bt][sub * 2], Bh[bt][sub * 2 + 1]);
          }
    }
  };

  load_x(0);
  issue_M(0, MB0); CP_COMMIT();
  store_x(XA0);
  CP_WAIT(0);
  __syncthreads();

  for (int i = 0; i < 8; i++) {
    if (i < 7) {
      load_x((i + 1) * 64);
      issue_M((i + 1) * 64, MB0 + ((i + 1) & 1) * MBSZ); CP_COMMIT();
    }
    mma_chunk(XA0 + (i & 1) * XABUF, MB0 + (i & 1) * MBSZ);
    if (i < 7) {
      store_x(XA0 + ((i + 1) & 1) * XABUF);
      CP_WAIT(0);
    }
    __syncthreads();
  }

  issue_VB(0, VB0);
  CP_COMMIT();

  // reduction: khalf 0 writes (with dw), khalf 1 adds
  float* Ef = (float*)(sm + EF_OFF);
  if (khalf == 0) {
    #pragma unroll
    for (int wt = 0; wt < 4; wt++) {
      int wc = wy + (wt >> 1) * 16 + (wt & 1) * 8 + 2 * tq;
      float d0 = g_dw[b][wc], d1 = g_dw[b][wc + 1];
      #pragma unroll
      for (int mt = 0; mt < 2; mt++) {
        int r = ny + mt * 16 + gI;
        float2 v0 = {acc1[mt][wt][0] + d0, acc1[mt][wt][1] + d1};
        float2 v1 = {acc1[mt][wt][2] + d0, acc1[mt][wt][3] + d1};
        *(float2*)&Ef[r * 68 + wc] = v0;
        *(float2*)&Ef[(r + 8) * 68 + wc] = v1;
      }
    }
  }
  __syncthreads();
  if (khalf == 1) {
    #pragma unroll
    for (int wt = 0; wt < 4; wt++) {
      int wc = wy + (wt >> 1) * 16 + (wt & 1) * 8 + 2 * tq;
      #pragma unroll
      for (int mt = 0; mt < 2; mt++) {
        int r = ny + mt * 16 + gI;
        float2 v0 = *(float2*)&Ef[r * 68 + wc];
        float2 v1 = *(float2*)&Ef[(r + 8) * 68 + wc];
        v0.x += acc1[mt][wt][0]; v0.y += acc1[mt][wt][1];
        v1.x += acc1[mt][wt][2]; v1.y += acc1[mt][wt][3];
        *(float2*)&Ef[r * 68 + wc] = v0;
        *(float2*)&Ef[(r + 8) * 68 + wc] = v1;
      }
    }
  }
  __syncthreads();

  // softmax over w (4 threads/row, 64 rows)
  {
    int row = tid >> 2, q = tid & 3;
    float mx = -1e30f;
    for (int w = q; w < NW; w += 4) mx = fmaxf(mx, Ef[row * 68 + w]);
    mx = fmaxf(mx, __shfl_xor_sync(0xffffffffu, mx, 1));
    mx = fmaxf(mx, __shfl_xor_sync(0xffffffffu, mx, 2));
    float s = 0.f;
    for (int w = q; w < NW; w += 4) {
      float e = __expf(Ef[row * 68 + w] - mx);
      Ef[row * 68 + w] = e;
      s += e;
    }
    s += __shfl_xor_sync(0xffffffffu, s, 1);
    s += __shfl_xor_sync(0xffffffffu, s, 2);
    float inv = 1.0f / s;
    for (int w = q; w < NW; w += 4) Ef[row * 68 + w] *= inv;
  }
  __syncthreads();

  // convert attn to bf16 hi/lo [n][w], rows 144B (aliases XA buf0)
  #pragma unroll
  for (int i = 0; i < 8; i++) {
    int p = tid + i * 256;
    int n = p >> 5, wp = p & 31;
    float e0 = Ef[n * 68 + 2 * wp], e1 = Ef[n * 68 + 2 * wp + 1];
    float h0 = __bfloat162float(__float2bfloat16(e0));
    float h1 = __bfloat162float(__float2bfloat16(e1));
    *(unsigned*)(sm + ATT_H + n * 144 + wp * 4) = pack_bf2(e0, e1);
    *(unsigned*)(sm + ATT_L + n * 144 + wp * 4) = pack_bf2(e0 - h0, e1 - h1);
  }
  // VB1 (issued in phase 2's first iteration) aliases Ef — all warps must finish
  // reading Ef before any cp.async can overwrite it.
  __syncthreads();

  // ---------------- phase 2: out = gamma*(vbar @ A^T) + x, 128c chunks --------
  float g = gamma[0];
  int cy = (wid >> 1) * 32;
  int nx = (wid & 1) * 32;
  for (int cc = 0; cc < 4; cc++) {
    if (cc < 3) {
      issue_VB(cc + 1, ((cc + 1) & 1) ? VB1 : VB0);
      CP_COMMIT();
      CP_WAIT(1);
    } else {
      CP_WAIT(0);
    }
    __syncthreads();

    // L2-prefetch this chunk's residual-x lines; hides DRAM under the mma loop.
    {
      const float* px = x + ((size_t)(b * NC + cc * 128 + (tid >> 1))) * NN
                          + n0 + (tid & 1) * 32;
      asm volatile("prefetch.global.L2 [%0];" :: "l"(px));
    }

    unsigned vbb = (cc & 1) ? VB1 : VB0;
    float acc2[2][4][4] = {};
    #pragma unroll
    for (int ks = 0; ks < 64; ks += 16) {
      unsigned Ah[2][4], Al[2][4];
      #pragma unroll
      for (int mt = 0; mt < 2; mt++) {
        unsigned row = cy + mt * 16 + (lane & 15);
        unsigned coff = ks * 2 + ((lane >> 4) << 4);
        unsigned aaddr = sb + vbb + row * 144 + coff;
        ldsm4(Ah[mt][0], Ah[mt][1], Ah[mt][2], Ah[mt][3], aaddr);
        ldsm4(Al[mt][0], Al[mt][1], Al[mt][2], Al[mt][3], aaddr + VBLO);
      }
      unsigned Bh[2][4], Bl[2][4];
      #pragma unroll
      for (int bt = 0; bt < 2; bt++) {
        unsigned row = nx + bt * 16 + (lane & 7) + ((lane & 16) >> 1);
        unsigned coff = ks * 2 + ((lane & 8) << 1);
        ldsm4(Bh[bt][0], Bh[bt][1], Bh[bt][2], Bh[bt][3], sb + ATT_H + row * 144 + coff);
        ldsm4(Bl[bt][0], Bl[bt][1], Bl[bt][2], Bl[bt][3], sb + ATT_L + row * 144 + coff);
      }
      #pragma unroll
      for (int mt = 0; mt < 2; mt++)
        #pragma unroll
        for (int bt = 0; bt < 2; bt++)
          #pragma unroll
          for (int sub = 0; sub < 2; sub++) {
            int nt = bt * 2 + sub;
            mma16816(acc2[mt][nt], Ah[mt], Bh[bt][sub * 2], Bh[bt][sub * 2 + 1]);
            mma16816(acc2[mt][nt], Ah[mt], Bl[bt][sub * 2], Bl[bt][sub * 2 + 1]);
            mma16816(acc2[mt][nt], Al[mt], Bh[bt][sub * 2], Bh[bt][sub * 2 + 1]);
          }
    }
    // epilogue: residual add + store
    #pragma unroll
    for (int mt = 0; mt < 2; mt++) {
      int c = cc * 128 + cy + mt * 16 + gI;
      #pragma unroll
      for (int nt = 0; nt < 4; nt++) {
        int n = n0 + nx + (nt >> 1) * 16 + (nt & 1) * 8 + 2 * tq;
        size_t off = ((size_t)(b * NC + c)) * NN + n;
        float2 xv0 = *(const float2*)(x + off);
        float2 xv1 = *(const float2*)(x + off + (size_t)8 * NN);
        float2 o0 = {fmaf(g, acc2[mt][nt][0], xv0.x), fmaf(g, acc2[mt][nt][1], xv0.y)};
        float2 o1 = {fmaf(g, acc2[mt][nt][2], xv1.x), fmaf(g, acc2[mt][nt][3], xv1.y)};
        *(float2*)(out + off) = o0;
        *(float2*)(out + off + (size_t)8 * NN) = o1;
      }
    }
    __syncthreads();
  }
}

// ---------------- launch -----------------------------------------------------
extern "C" void kernel_launch(void* const* d_in, const int* in_sizes, int n_in,
                              void* d_out, int out_size) {
  const float* x     = (const float*)d_in[0];
  const float* Wq    = (const float*)d_in[1];
  const float* bq    = (const float*)d_in[2];
  const float* Wk    = (const float*)d_in[3];
  const float* bk    = (const float*)d_in[4];
  const float* Wv    = (const float*)d_in[5];
  const float* bv    = (const float*)d_in[6];
  const float* gamma = (const float*)d_in[7];
  const float* pe    = (const float*)d_in[8];
  const int*   pos   = (const int*)  d_in[9];
  float* out = (float*)d_out;

  cudaFuncSetAttribute(k_MV, cudaFuncAttributeMaxDynamicSharedMemorySize, MV_SMEM);
  cudaFuncSetAttribute(k_fused, cudaFuncAttributeMaxDynamicSharedMemorySize,
                       SMEM_FUSED);

  k_front<<<2152, 256>>>(x, pos, pe, Wq, Wk, Wv, bq, bk);
  k_MV<<<68, 256, MV_SMEM>>>(bv);
  k_fused<<<dim3(NN / 64, NB), 256, SMEM_FUSED>>>(x, gamma, out);
}

// round 15
// speedup vs baseline: 1.8062x; 1.1294x over previous
#include <cuda_runtime.h>
#include <cuda_bf16.h>

#define NB 4
#define NC 512
#define CKQ 256
#define NW 64
#define NH 64
#define NN 4096   // H*W

// ---------------- scratch (device globals) ----------------------------------
__device__ float g_xbar[NB][NC][NW];
__device__ float g_x2df[NB][NC][NW];
__device__ __align__(16) __nv_bfloat16 g_Gh[NC][NC], g_Gl[NC][NC];
__device__ __align__(16) __nv_bfloat16 g_Wvh[NC][NC], g_Wvl[NC][NC];
__device__ __align__(16) __nv_bfloat16 g_MTh[NB][NW][NC], g_MTl[NB][NW][NC];
__device__ __align__(16) __nv_bfloat16 g_vbh[NB][NC][NW], g_vbl[NB][NC][NW];
__device__ float g_v1[NC];        // Wq^T bk
__device__ float g_v2[NC];        // Wk^T bq
__device__ float g_s0;            // bq . bk
__device__ float g_dw[NB][NW];

// ---------------- helpers ----------------------------------------------------
__device__ __forceinline__ unsigned pack_bf2(float e, float o) {
  __nv_bfloat162 h;
  h.x = __float2bfloat16(e);
  h.y = __float2bfloat16(o);
  return *reinterpret_cast<unsigned*>(&h);
}
__device__ __forceinline__ void split_bf(float v, __nv_bfloat16& h, __nv_bfloat16& l) {
  h = __float2bfloat16(v);
  l = __float2bfloat16(v - __bfloat162float(h));
}
__device__ __forceinline__ void hilo2(const float* a, uint2& h, uint2& l) {
  float h0 = __bfloat162float(__float2bfloat16(a[0]));
  float h1 = __bfloat162float(__float2bfloat16(a[1]));
  float h2 = __bfloat162float(__float2bfloat16(a[2]));
  float h3 = __bfloat162float(__float2bfloat16(a[3]));
  h.x = pack_bf2(a[0], a[1]);
  h.y = pack_bf2(a[2], a[3]);
  l.x = pack_bf2(a[0] - h0, a[1] - h1);
  l.y = pack_bf2(a[2] - h2, a[3] - h3);
}
__device__ __forceinline__ void ldsm4(unsigned& r0, unsigned& r1, unsigned& r2,
                                      unsigned& r3, unsigned addr) {
  asm volatile("ldmatrix.sync.aligned.m8n8.x4.shared.b16 {%0,%1,%2,%3},[%4];"
               : "=r"(r0), "=r"(r1), "=r"(r2), "=r"(r3) : "r"(addr));
}
__device__ __forceinline__ void ldsm4t(unsigned& r0, unsigned& r1, unsigned& r2,
                                       unsigned& r3, unsigned addr) {
  asm volatile("ldmatrix.sync.aligned.m8n8.x4.trans.shared.b16 {%0,%1,%2,%3},[%4];"
               : "=r"(r0), "=r"(r1), "=r"(r2), "=r"(r3) : "r"(addr));
}
__device__ __forceinline__ void mma16816(float* d, const unsigned* a,
                                         unsigned b0, unsigned b1) {
  asm volatile(
    "mma.sync.aligned.m16n8k16.row.col.f32.bf16.bf16.f32 "
    "{%0,%1,%2,%3},{%4,%5,%6,%7},{%8,%9},{%0,%1,%2,%3};"
    : "+f"(d[0]), "+f"(d[1]), "+f"(d[2]), "+f"(d[3])
    : "r"(a[0]), "r"(a[1]), "r"(a[2]), "r"(a[3]), "r"(b0), "r"(b1));
}
__device__ __forceinline__ void cp16(unsigned saddr, const void* g) {
  asm volatile("cp.async.cg.shared.global [%0],[%1],16;" :: "r"(saddr), "l"(g));
}
#define CP_COMMIT() asm volatile("cp.async.commit_group;")
#define CP_WAIT(n)  asm volatile("cp.async.wait_group %0;" :: "n"(n))

// =============================================================================
// k_front: [0,64) G | [64,96) Wv conv | [96,104) bias | [104,2152) prep
// Heavy blocks first: they overlap the prep storm instead of tailing it.
// =============================================================================
#define GA_H 0
#define GA_L 4608
#define GB_H 9216
#define GB_L 13824

__global__ __launch_bounds__(256)
void k_front(const float* __restrict__ x, const int* __restrict__ pos,
             const float* __restrict__ pe, const float* __restrict__ Wq,
             const float* __restrict__ Wk, const float* __restrict__ Wv,
             const float* __restrict__ bq, const float* __restrict__ bk) {
  __shared__ float4 sm4[16][16];
  __shared__ float xbv[64];
  __shared__ float x1s[16];
  __shared__ int pidx[16];
  __shared__ __align__(16) char gsm[18432];

  int bx = blockIdx.x;
  int t = threadIdx.x;

  if (bx < 64) {                       // ---------------- G = Wq^T Wk ----------
    int cx = bx & 7, kx = bx >> 3;
    unsigned sb = (unsigned)__cvta_generic_to_shared(gsm);
    int wid = t >> 5, lane = t & 31;
    int my = (wid >> 2) * 32, nw = (wid & 3) * 16;
    int gI = lane >> 2, tq = lane & 3;
    float acc[2][2][4] = {};
    int rr0 = t >> 4, c4 = t & 15;
    for (int o0 = 0; o0 < CKQ; o0 += 32) {
      #pragma unroll
      for (int z = 0; z < 2; z++) {
        int row = rr0 + z * 16;
        float4 v = *(const float4*)&Wq[(size_t)(o0 + row) * NC + cx * 64 + c4 * 4];
        uint2 h, l;
        hilo2((const float*)&v, h, l);
        *(uint2*)(gsm + GA_H + row * 144 + c4 * 8) = h;
        *(uint2*)(gsm + GA_L + row * 144 + c4 * 8) = l;
        float4 w = *(const float4*)&Wk[(size_t)(o0 + row) * NC + kx * 64 + c4 * 4];
        hilo2((const float*)&w, h, l);
        *(uint2*)(gsm + GB_H + row * 144 + c4 * 8) = h;
        *(uint2*)(gsm + GB_L + row * 144 + c4 * 8) = l;
      }
      __syncthreads();
      #pragma unroll
      for (int ks = 0; ks < 32; ks += 16) {
        unsigned Ah[2][4], Al[2][4];
        unsigned arow = ks + (lane & 7) + ((lane & 16) >> 1);
        #pragma unroll
        for (int mt = 0; mt < 2; mt++) {
          unsigned mcol = my + mt * 16 + (lane & 8);
          unsigned aaddr = sb + GA_H + arow * 144 + mcol * 2;
          ldsm4t(Ah[mt][0], Ah[mt][1], Ah[mt][2], Ah[mt][3], aaddr);
          ldsm4t(Al[mt][0], Al[mt][1], Al[mt][2], Al[mt][3], aaddr + (GA_L - GA_H));
        }
        unsigned Bh[4], Bl[4];
        {
          unsigned brow = ks + (lane & 7) + (lane & 8);
          unsigned bcol = nw + ((lane & 16) >> 1);
          unsigned baddr = sb + GB_H + brow * 144 + bcol * 2;
          ldsm4t(Bh[0], Bh[1], Bh[2], Bh[3], baddr);
          ldsm4t(Bl[0], Bl[1], Bl[2], Bl[3], baddr + (GB_L - GB_H));
        }
        #pragma unroll
        for (int mt = 0; mt < 2; mt++)
          #pragma unroll
          for (int sub = 0; sub < 2; sub++) {
            mma16816(acc[mt][sub], Ah[mt], Bh[sub * 2], Bh[sub * 2 + 1]);
            mma16816(acc[mt][sub], Ah[mt], Bl[sub * 2], Bl[sub * 2 + 1]);
            mma16816(acc[mt][sub], Al[mt], Bh[sub * 2], Bh[sub * 2 + 1]);
          }
      }
      __syncthreads();
    }
    #pragma unroll
    for (int mt = 0; mt < 2; mt++)
      #pragma unroll
      for (int nt = 0; nt < 2; nt++) {
        int cg = cx * 64 + my + mt * 16 + gI;
        int kg = kx * 64 + nw + nt * 8 + 2 * tq;
        split_bf(acc[mt][nt][0], g_Gh[cg][kg],     g_Gl[cg][kg]);
        split_bf(acc[mt][nt][1], g_Gh[cg][kg + 1], g_Gl[cg][kg + 1]);
        split_bf(acc[mt][nt][2], g_Gh[cg + 8][kg],     g_Gl[cg + 8][kg]);
        split_bf(acc[mt][nt][3], g_Gh[cg + 8][kg + 1], g_Gl[cg + 8][kg + 1]);
      }
    return;
  }

  if (bx < 96) {                       // ---------------- Wv convert -----------
    int base = (bx - 64) * 2048;
    #pragma unroll
    for (int j = 0; j < 8; j++) {
      int idx4 = base + j * 256 + t;
      float4 v = ((const float4*)Wv)[idx4];
      __nv_bfloat16 h0, l0, h1, l1;
      split_bf(v.x, h0, l0); split_bf(v.y, h1, l1);
      ((__nv_bfloat162*)g_Wvh)[idx4 * 2] = {h0, h1};
      ((__nv_bfloat162*)g_Wvl)[idx4 * 2] = {l0, l1};
      split_bf(v.z, h0, l0); split_bf(v.w, h1, l1);
      ((__nv_bfloat162*)g_Wvh)[idx4 * 2 + 1] = {h0, h1};
      ((__nv_bfloat162*)g_Wvl)[idx4 * 2 + 1] = {l0, l1};
    }
    return;
  }

  if (bx < 104) {                      // ---------------- bias blocks ----------
    int c = (bx - 96) * 64 + (t >> 2);
    int q = t & 3;
    float s1 = 0.f, s2 = 0.f;
    #pragma unroll 8
    for (int o = q; o < CKQ; o += 4) {
      s1 += Wq[(size_t)o * NC + c] * bk[o];
      s2 += Wk[(size_t)o * NC + c] * bq[o];
    }
    s1 += __shfl_xor_sync(0xffffffffu, s1, 1);
    s1 += __shfl_xor_sync(0xffffffffu, s1, 2);
    s2 += __shfl_xor_sync(0xffffffffu, s2, 1);
    s2 += __shfl_xor_sync(0xffffffffu, s2, 2);
    if (q == 0) { g_v1[c] = s1; g_v2[c] = s2; }
    if (bx == 96 && t < 32) {
      float s = 0.f;
      for (int o = t; o < CKQ; o += 32) s += bq[o] * bk[o];
      #pragma unroll
      for (int d = 16; d > 0; d >>= 1) s += __shfl_xor_sync(0xffffffffu, s, d);
      if (t == 0) g_s0 = s;
    }
    return;
  }

  // ---------------- prep ------------------------------------------------------
  {
    int p = bx - 104;
    int c = p & 511, b = p >> 9;
    int hq = t >> 4, tw = t & 15;
    const float* xp = x + ((size_t)(b * NC + c)) * NH * NW;
    float4 s = {0.f, 0.f, 0.f, 0.f};
    #pragma unroll
    for (int h = hq; h < NH; h += 16) {
      float4 v = *(const float4*)&xp[h * NW + tw * 4];
      s.x += v.x; s.y += v.y; s.z += v.z; s.w += v.w;
    }
    sm4[hq][tw] = s;
    if (t < 16) pidx[t] = pos[b * NN + 4 * t] >> 3;
    __syncthreads();
    if (hq == 0) {
      float4 a = {0.f, 0.f, 0.f, 0.f};
      #pragma unroll
      for (int q = 0; q < 16; q++) {
        float4 v = sm4[q][tw];
        a.x += v.x; a.y += v.y; a.z += v.z; a.w += v.w;
      }
      const float inv = 1.0f / NH;
      a.x *= inv; a.y *= inv; a.z *= inv; a.w *= inv;
      *(float4*)&xbv[tw * 4] = a;
      *(float4*)&g_xbar[b][c][tw * 4] = a;
    }
    __syncthreads();
    if (t < 16)
      x1s[t] = 0.25f * (xbv[4*t] + xbv[4*t+1] + xbv[4*t+2] + xbv[4*t+3])
               + pe[pidx[t] * NC + c];
    __syncthreads();
    if (t < NW) {
      float src = (t * 15.0f) / 63.0f;
      int   i0  = (int)floorf(src);
      int   i1  = min(i0 + 1, 15);
      float tt  = src - (float)i0;
      g_x2df[b][c][t] = x1s[i0] * (1.0f - tt) + x1s[i1] * tt;
    }
  }
}

// =============================================================================
// k_MV: [0,32) M^T tiles | [32,64) vbar tiles | [64,68) dw
// =============================================================================
#define ACV0 0
#define ACVLO 9216
#define ACVBUF 18432         // 2 buffers end 36864
#define CPB0 36864
#define CPBLO 9216
#define CPBSZ 18432          // 2 buffers end 73728
#define MV_SMEM 73728

__global__ __launch_bounds__(256)
void k_MV(const float* __restrict__ bv) {
  extern __shared__ char dsm[];
  unsigned sb = (unsigned)__cvta_generic_to_shared(dsm);
  int bx = blockIdx.x, tid = threadIdx.x;

  if (bx >= 64) {                      // dw: sum_c x2d[c][w] * v2[c]
    int b = bx - 64;
    int w = tid >> 2, q = tid & 3;
    float s = 0.f;
    #pragma unroll 8
    for (int c = q; c < NC; c += 4) s += g_x2df[b][c][w] * g_v2[c];
    s += __shfl_xor_sync(0xffffffffu, s, 1);
    s += __shfl_xor_sync(0xffffffffu, s, 2);
    if (q == 0) g_dw[b][w] = s + g_s0;
    return;
  }

  bool mtr = (bx < 32);
  int b  = mtr ? (bx >> 3) : ((bx - 32) >> 3);
  int c0 = (mtr ? (bx & 7) : ((bx - 32) & 7)) * 64;
  const float* Xf = mtr ? &g_x2df[b][0][0] : &g_xbar[b][0][0];
  const __nv_bfloat16* Bhg = mtr ? &g_Gh[c0][0] : &g_Wvh[c0][0];
  const __nv_bfloat16* Blg = mtr ? &g_Gl[c0][0] : &g_Wvl[c0][0];

  int rc = tid >> 4, ln4 = tid & 15;
  float4 xr[4];
  auto load_f = [&](int k0) {
    #pragma unroll
    for (int z = 0; z < 4; z++)
      xr[z] = *(const float4*)&Xf[(size_t)(k0 + rc + z * 16) * NW + ln4 * 4];
  };
  auto store_f = [&](unsigned base) {
    #pragma unroll
    for (int z = 0; z < 4; z++) {
      uint2 h, l;
      hilo2((const float*)&xr[z], h, l);
      unsigned a = base + (rc + z * 16) * 144 + ln4 * 8;
      *(uint2*)(dsm + a) = h;
      *(uint2*)(dsm + a + ACVLO) = l;
    }
  };
  auto issueB = [&](int k0, unsigned base) {
    #pragma unroll
    for (int u = tid; u < 512; u += 256) {
      int r = u >> 3, q = u & 7;
      cp16(sb + base + r * 144 + q * 16,         Bhg + (size_t)r * NC + k0 + q * 8);
      cp16(sb + base + CPBLO + r * 144 + q * 16, Blg + (size_t)r * NC + k0 + q * 8);
    }
  };

  int wid = tid >> 5, lane = tid & 31;
  int my = (wid >> 2) * 32, nw = (wid & 3) * 16;
  int gI = lane >> 2, tq = lane & 3;
  float acc[2][2][4] = {};

  load_f(0);
  issueB(0, CPB0); CP_COMMIT();
  store_f(ACV0);
  CP_WAIT(0);
  __syncthreads();

  for (int kc = 0; kc < 8; kc++) {
    if (kc < 7) {
      load_f((kc + 1) * 64);
      issueB((kc + 1) * 64, CPB0 + ((kc + 1) & 1) * CPBSZ); CP_COMMIT();
    }
    unsigned acv = ACV0 + (kc & 1) * ACVBUF;
    unsigned cpb = CPB0 + (kc & 1) * CPBSZ;
    if (mtr) {
      #pragma unroll
      for (int ks = 0; ks < 64; ks += 16) {
        unsigned Ah[2][4], Al[2][4];
        unsigned arow = ks + (lane & 7) + ((lane & 16) >> 1);
        #pragma unroll
        for (int mt = 0; mt < 2; mt++) {
          unsigned acol = my + mt * 16 + (lane & 8);
          unsigned aaddr = sb + acv + arow * 144 + acol * 2;
          ldsm4t(Ah[mt][0], Ah[mt][1], Ah[mt][2], Ah[mt][3], aaddr);
          ldsm4t(Al[mt][0], Al[mt][1], Al[mt][2], Al[mt][3], aaddr + ACVLO);
        }
        unsigned Bh[4], Bl[4];
        {
          unsigned row = nw + (lane & 7) + ((lane & 16) >> 1);
          unsigned coff = ks * 2 + ((lane & 8) << 1);
          unsigned baddr = sb + cpb + row * 144 + coff;
          ldsm4(Bh[0], Bh[1], Bh[2], Bh[3], baddr);
          ldsm4(Bl[0], Bl[1], Bl[2], Bl[3], baddr + CPBLO);
        }
        #pragma unroll
        for (int mt = 0; mt < 2; mt++)
          #pragma unroll
          for (int sub = 0; sub < 2; sub++) {
            mma16816(acc[mt][sub], Ah[mt], Bh[sub * 2], Bh[sub * 2 + 1]);
            mma16816(acc[mt][sub], Ah[mt], Bl[sub * 2], Bl[sub * 2 + 1]);
            mma16816(acc[mt][sub], Al[mt], Bh[sub * 2], Bh[sub * 2 + 1]);
          }
      }
    } else {
      #pragma unroll
      for (int ks = 0; ks < 64; ks += 16) {
        unsigned Ah[2][4], Al[2][4];
        #pragma unroll
        for (int mt = 0; mt < 2; mt++) {
          unsigned row = my + mt * 16 + (lane & 15);
          unsigned coff = ks * 2 + ((lane >> 4) << 4);
          unsigned aaddr = sb + cpb + row * 144 + coff;
          ldsm4(Ah[mt][0], Ah[mt][1], Ah[mt][2], Ah[mt][3], aaddr);
          ldsm4(Al[mt][0], Al[mt][1], Al[mt][2], Al[mt][3], aaddr + CPBLO);
        }
        unsigned Bh[4], Bl[4];
        {
          unsigned brow = ks + (lane & 7) + (lane & 8);
          unsigned bcol = nw + ((lane & 16) >> 1);
          unsigned baddr = sb + acv + brow * 144 + bcol * 2;
          ldsm4t(Bh[0], Bh[1], Bh[2], Bh[3], baddr);
          ldsm4t(Bl[0], Bl[1], Bl[2], Bl[3], baddr + ACVLO);
        }
        #pragma unroll
        for (int mt = 0; mt < 2; mt++)
          #pragma unroll
          for (int sub = 0; sub < 2; sub++) {
            mma16816(acc[mt][sub], Ah[mt], Bh[sub * 2], Bh[sub * 2 + 1]);
            mma16816(acc[mt][sub], Ah[mt], Bl[sub * 2], Bl[sub * 2 + 1]);
            mma16816(acc[mt][sub], Al[mt], Bh[sub * 2], Bh[sub * 2 + 1]);
          }
      }
    }
    if (kc < 7) {
      store_f(ACV0 + ((kc + 1) & 1) * ACVBUF);
      CP_WAIT(0);
    }
    __syncthreads();
  }

  if (mtr) {
    #pragma unroll
    for (int mt = 0; mt < 2; mt++)
      #pragma unroll
      for (int nt = 0; nt < 2; nt++) {
        int w = my + mt * 16 + gI;
        int c = c0 + nw + nt * 8 + 2 * tq;
        split_bf(acc[mt][nt][0] + g_v1[c],     g_MTh[b][w][c],     g_MTl[b][w][c]);
        split_bf(acc[mt][nt][1] + g_v1[c + 1], g_MTh[b][w][c + 1], g_MTl[b][w][c + 1]);
        split_bf(acc[mt][nt][2] + g_v1[c],     g_MTh[b][w + 8][c],     g_MTl[b][w + 8][c]);
        split_bf(acc[mt][nt][3] + g_v1[c + 1], g_MTh[b][w + 8][c + 1], g_MTl[b][w + 8][c + 1]);
      }
  } else {
    #pragma unroll
    for (int mt = 0; mt < 2; mt++)
      #pragma unroll
      for (int nt = 0; nt < 2; nt++) {
        int c = c0 + my + mt * 16 + gI;
        int w = nw + nt * 8 + 2 * tq;
        float bv0 = bv[c], bv8 = bv[c + 8];
        split_bf(acc[mt][nt][0] + bv0, g_vbh[b][c][w],     g_vbl[b][c][w]);
        split_bf(acc[mt][nt][1] + bv0, g_vbh[b][c][w + 1], g_vbl[b][c][w + 1]);
        split_bf(acc[mt][nt][2] + bv8, g_vbh[b][c + 8][w],     g_vbl[b][c + 8][w]);
        split_bf(acc[mt][nt][3] + bv8, g_vbh[b][c + 8][w + 1], g_vbl[b][c + 8][w + 1]);
      }
  }
}

// =============================================================================
// k_fused: n-tile 64, 2 blocks/SM, 32x32 warp tiles.
// phase 1: 3-term hi/lo (softmax-sensitive). phase 2: 2-term (v*attn_hi).
// =============================================================================
#define XA0 0
#define XALO 9216
#define XABUF 18432          // 2 buffers end 36864
#define MB0 36864
#define MBLO 9216
#define MBSZ 18432           // 2 buffers end 73728
#define EF_OFF 73728         // 64*68*4 = 17408 -> end 91136
#define ATT_H 0              // aliases XA buf0 (dead after phase 1)
#define VB0 18432            // aliases XA buf1 + MB buf0
#define VBLO 18432
#define VBSZ 36864
#define VB1 55296            // aliases MB buf1 + Ef
#define SMEM_FUSED 92160

__global__ __launch_bounds__(256, 2)
void k_fused(const float* __restrict__ x, const float* __restrict__ gamma,
             float* __restrict__ out) {
  extern __shared__ char sm[];
  unsigned sb = (unsigned)__cvta_generic_to_shared(sm);
  int tid = threadIdx.x;
  int wid = tid >> 5, lane = tid & 31;
  int b = blockIdx.y;
  int n0 = blockIdx.x * 64;
  int gI = lane >> 2, tq = lane & 3;

  const float* xb = x + (size_t)b * NC * NN + n0;
  int rc = tid >> 4, ln4 = tid & 15;

  float4 xr[4];
  auto load_x = [&](int c0) {
    #pragma unroll
    for (int z = 0; z < 4; z++)
      xr[z] = *(const float4*)(xb + (size_t)(c0 + rc + z * 16) * NN + ln4 * 4);
  };
  auto store_x = [&](unsigned xbase) {
    #pragma unroll
    for (int z = 0; z < 4; z++) {
      uint2 h, l;
      hilo2((const float*)&xr[z], h, l);
      unsigned base0 = xbase + (rc + z * 16) * 144 + ln4 * 8;
      *(uint2*)(sm + base0) = h;
      *(uint2*)(sm + base0 + XALO) = l;
    }
  };
  auto issue_M = [&](int c0, unsigned mb) {
    #pragma unroll
    for (int u = tid; u < 512; u += 256) {
      int rr = u >> 3, q = u & 7;
      cp16(sb + mb + rr * 144 + q * 16,        &g_MTh[b][rr][c0 + q * 8]);
      cp16(sb + mb + MBLO + rr * 144 + q * 16, &g_MTl[b][rr][c0 + q * 8]);
    }
  };
  auto issue_VB = [&](int cc, unsigned base) {
    #pragma unroll
    for (int u = tid; u < 1024; u += 256) {
      int rr = u >> 3, q = u & 7;
      cp16(sb + base + rr * 144 + q * 16,        &g_vbh[b][cc * 128 + rr][q * 8]);
      cp16(sb + base + VBLO + rr * 144 + q * 16, &g_vbl[b][cc * 128 + rr][q * 8]);
    }
  };

  // ---------------- phase 1: E[64n][64w], k-split across warp halves ----------
  int wq = wid & 3, khalf = wid >> 2;
  int ny = (wq >> 1) * 32, wy = (wq & 1) * 32;
  int ksb = khalf * 32;
  float acc1[2][4][4] = {};

  auto mma_chunk = [&](unsigned xab, unsigned mbb) {
    #pragma unroll
    for (int ks = 0; ks < 32; ks += 16) {
      int kk = ksb + ks;
      unsigned Ah[2][4], Al[2][4];
      unsigned arow = kk + (lane & 7) + ((lane & 16) >> 1);
      #pragma unroll
      for (int mt = 0; mt < 2; mt++) {
        unsigned acol = ny + mt * 16 + (lane & 8);
        unsigned aaddr = sb + xab + arow * 144 + acol * 2;
        ldsm4t(Ah[mt][0], Ah[mt][1], Ah[mt][2], Ah[mt][3], aaddr);
        ldsm4t(Al[mt][0], Al[mt][1], Al[mt][2], Al[mt][3], aaddr + XALO);
      }
      unsigned Bh[2][4], Bl[2][4];
      #pragma unroll
      for (int bt = 0; bt < 2; bt++) {
        unsigned brow = wy + bt * 16 + (lane & 7) + ((lane & 16) >> 1);
        unsigned coff = kk * 2 + ((lane & 8) << 1);
        unsigned baddr = sb + mbb + brow * 144 + coff;
        ldsm4(Bh[bt][0], Bh[bt][1], Bh[bt][2], Bh[bt][3], baddr);
        ldsm4(Bl[bt][0], Bl[bt][1], Bl[bt][2], Bl[bt][3], baddr + MBLO);
      }
      #pragma unroll
      for (int mt = 0; mt < 2; mt++)
        #pragma unroll
        for (int bt = 0; bt < 2; bt++)
          #pragma unroll
          for (int sub = 0; sub < 2; sub++) {
            int wt = bt * 2 + sub;
            mma16816(acc1[mt][wt], Ah[mt], Bh[bt][sub * 2], Bh[bt][sub * 2 + 1]);
            mma16816(acc1[mt][wt], Ah[mt], Bl[bt][sub * 2], Bl[bt][sub * 2 + 1]);
            mma16816(acc1[mt][wt], Al[mt], Bh[bt][sub * 2], Bh[bt][sub * 2 + 1]);
          }
    }
  };

  load_x(0);
  issue_M(0, MB0); CP_COMMIT();
  store_x(XA0);
  CP_WAIT(0);
  __syncthreads();

  for (int i = 0; i < 8; i++) {
    if (i < 7) {
      load_x((i + 1) * 64);
      issue_M((i + 1) * 64, MB0 + ((i + 1) & 1) * MBSZ); CP_COMMIT();
    }
    mma_chunk(XA0 + (i & 1) * XABUF, MB0 + (i & 1) * MBSZ);
    if (i < 7) {
      store_x(XA0 + ((i + 1) & 1) * XABUF);
      CP_WAIT(0);
    }
    __syncthreads();
  }

  issue_VB(0, VB0);
  CP_COMMIT();

  // reduction: khalf 0 writes (with dw), khalf 1 adds
  float* Ef = (float*)(sm + EF_OFF);
  if (khalf == 0) {
    #pragma unroll
    for (int wt = 0; wt < 4; wt++) {
      int wc = wy + (wt >> 1) * 16 + (wt & 1) * 8 + 2 * tq;
      float d0 = g_dw[b][wc], d1 = g_dw[b][wc + 1];
      #pragma unroll
      for (int mt = 0; mt < 2; mt++) {
        int r = ny + mt * 16 + gI;
        float2 v0 = {acc1[mt][wt][0] + d0, acc1[mt][wt][1] + d1};
        float2 v1 = {acc1[mt][wt][2] + d0, acc1[mt][wt][3] + d1};
        *(float2*)&Ef[r * 68 + wc] = v0;
        *(float2*)&Ef[(r + 8) * 68 + wc] = v1;
      }
    }
  }
  __syncthreads();
  if (khalf == 1) {
    #pragma unroll
    for (int wt = 0; wt < 4; wt++) {
      int wc = wy + (wt >> 1) * 16 + (wt & 1) * 8 + 2 * tq;
      #pragma unroll
      for (int mt = 0; mt < 2; mt++) {
        int r = ny + mt * 16 + gI;
        float2 v0 = *(float2*)&Ef[r * 68 + wc];
        float2 v1 = *(float2*)&Ef[(r + 8) * 68 + wc];
        v0.x += acc1[mt][wt][0]; v0.y += acc1[mt][wt][1];
        v1.x += acc1[mt][wt][2]; v1.y += acc1[mt][wt][3];
        *(float2*)&Ef[r * 68 + wc] = v0;
        *(float2*)&Ef[(r + 8) * 68 + wc] = v1;
      }
    }
  }
  __syncthreads();

  // softmax over w (4 threads/row, 64 rows)
  {
    int row = tid >> 2, q = tid & 3;
    float mx = -1e30f;
    for (int w = q; w < NW; w += 4) mx = fmaxf(mx, Ef[row * 68 + w]);
    mx = fmaxf(mx, __shfl_xor_sync(0xffffffffu, mx, 1));
    mx = fmaxf(mx, __shfl_xor_sync(0xffffffffu, mx, 2));
    float s = 0.f;
    for (int w = q; w < NW; w += 4) {
      float e = __expf(Ef[row * 68 + w] - mx);
      Ef[row * 68 + w] = e;
      s += e;
    }
    s += __shfl_xor_sync(0xffffffffu, s, 1);
    s += __shfl_xor_sync(0xffffffffu, s, 2);
    float inv = 1.0f / s;
    for (int w = q; w < NW; w += 4) Ef[row * 68 + w] *= inv;
  }
  __syncthreads();

  // convert attn to bf16 hi only [n][w], rows 144B (aliases XA buf0)
  #pragma unroll
  for (int i = 0; i < 8; i++) {
    int p = tid + i * 256;
    int n = p >> 5, wp = p & 31;
    float e0 = Ef[n * 68 + 2 * wp], e1 = Ef[n * 68 + 2 * wp + 1];
    *(unsigned*)(sm + ATT_H + n * 144 + wp * 4) = pack_bf2(e0, e1);
  }
  // VB1 (issued in phase 2's first iteration) aliases Ef — all warps must finish
  // reading Ef before any cp.async can overwrite it.
  __syncthreads();

  // ---------------- phase 2: out = gamma*(vbar @ attn_hi^T) + x ---------------
  float g = gamma[0];
  int cy = (wid >> 1) * 32;
  int nx = (wid & 1) * 32;
  for (int cc = 0; cc < 4; cc++) {
    if (cc < 3) {
      issue_VB(cc + 1, ((cc + 1) & 1) ? VB1 : VB0);
      CP_COMMIT();
      CP_WAIT(1);
    } else {
      CP_WAIT(0);
    }
    __syncthreads();

    // L2-prefetch this chunk's residual-x lines
    {
      const float* px = x + ((size_t)(b * NC + cc * 128 + (tid >> 1))) * NN
                          + n0 + (tid & 1) * 32;
      asm volatile("prefetch.global.L2 [%0];" :: "l"(px));
    }

    unsigned vbb = (cc & 1) ? VB1 : VB0;
    float acc2[2][4][4] = {};
    #pragma unroll
    for (int ks = 0; ks < 64; ks += 16) {
      unsigned Ah[2][4], Al[2][4];
      #pragma unroll
      for (int mt = 0; mt < 2; mt++) {
        unsigned row = cy + mt * 16 + (lane & 15);
        unsigned coff = ks * 2 + ((lane >> 4) << 4);
        unsigned aaddr = sb + vbb + row * 144 + coff;
        ldsm4(Ah[mt][0], Ah[mt][1], Ah[mt][2], Ah[mt][3], aaddr);
        ldsm4(Al[mt][0], Al[mt][1], Al[mt][2], Al[mt][3], aaddr + VBLO);
      }
      unsigned Bh[2][4];
      #pragma unroll
      for (int bt = 0; bt < 2; bt++) {
        unsigned row = nx + bt * 16 + (lane & 7) + ((lane & 16) >> 1);
        unsigned coff = ks * 2 + ((lane & 8) << 1);
        ldsm4(Bh[bt][0], Bh[bt][1], Bh[bt][2], Bh[bt][3], sb + ATT_H + row * 144 + coff);
      }
      #pragma unroll
      for (int mt = 0; mt < 2; mt++)
        #pragma unroll
        for (int bt = 0; bt < 2; bt++)
          #pragma unroll
          for (int sub = 0; sub < 2; sub++) {
            int nt = bt * 2 + sub;
            mma16816(acc2[mt][nt], Ah[mt], Bh[bt][sub * 2], Bh[bt][sub * 2 + 1]);
            mma16816(acc2[mt][nt], Al[mt], Bh[bt][sub * 2], Bh[bt][sub * 2 + 1]);
          }
    }
    // epilogue: residual add + store
    #pragma unroll
    for (int mt = 0; mt < 2; mt++) {
      int c = cc * 128 + cy + mt * 16 + gI;
      #pragma unroll
      for (int nt = 0; nt < 4; nt++) {
        int n = n0 + nx + (nt >> 1) * 16 + (nt & 1) * 8 + 2 * tq;
        size_t off = ((size_t)(b * NC + c)) * NN + n;
        float2 xv0 = *(const float2*)(x + off);
        float2 xv1 = *(const float2*)(x + off + (size_t)8 * NN);
        float2 o0 = {fmaf(g, acc2[mt][nt][0], xv0.x), fmaf(g, acc2[mt][nt][1], xv0.y)};
        float2 o1 = {fmaf(g, acc2[mt][nt][2], xv1.x), fmaf(g, acc2[mt][nt][3], xv1.y)};
        *(float2*)(out + off) = o0;
        *(float2*)(out + off + (size_t)8 * NN) = o1;
      }
    }
    __syncthreads();
  }
}

// ---------------- launch -----------------------------------------------------
extern "C" void kernel_launch(void* const* d_in, const int* in_sizes, int n_in,
                              void* d_out, int out_size) {
  const float* x     = (const float*)d_in[0];
  const float* Wq    = (const float*)d_in[1];
  const float* bq    = (const float*)d_in[2];
  const float* Wk    = (const float*)d_in[3];
  const float* bk    = (const float*)d_in[4];
  const float* Wv    = (const float*)d_in[5];
  const float* bv    = (const float*)d_in[6];
  const float* gamma = (const float*)d_in[7];
  const float* pe    = (const float*)d_in[8];
  const int*   pos   = (const int*)  d_in[9];
  float* out = (float*)d_out;

  cudaFuncSetAttribute(k_MV, cudaFuncAttributeMaxDynamicSharedMemorySize, MV_SMEM);
  cudaFuncSetAttribute(k_fused, cudaFuncAttributeMaxDynamicSharedMemorySize,
                       SMEM_FUSED);

  k_front<<<2152, 256>>>(x, pos, pe, Wq, Wk, Wv, bq, bk);
  k_MV<<<68, 256, MV_SMEM>>>(bv);
  k_fused<<<dim3(NN / 64, NB), 256, SMEM_FUSED>>>(x, gamma, out);
}

// round 16
// speedup vs baseline: 1.9148x; 1.0601x over previous
#include <cuda_runtime.h>
#include <cuda_bf16.h>

#define NB 4
#define NC 512
#define CKQ 256
#define NW 64
#define NH 64
#define NN 4096   // H*W

// ---------------- scratch (device globals) ----------------------------------
__device__ float g_xbar[NB][NC][NW];
__device__ float g_x2df[NB][NC][NW];
__device__ __align__(16) __nv_bfloat16 g_Gh[NC][NC], g_Gl[NC][NC];
__device__ __align__(16) __nv_bfloat16 g_Wvh[NC][NC], g_Wvl[NC][NC];
__device__ __align__(16) __nv_bfloat16 g_MTh[NB][NW][NC], g_MTl[NB][NW][NC];
__device__ __align__(16) __nv_bfloat16 g_vbh[NB][NC][NW];
__device__ float g_v1[NC];        // Wq^T bk
__device__ float g_v2[NC];        // Wk^T bq
__device__ float g_s0;            // bq . bk
__device__ float g_dw[NB][NW];

// ---------------- helpers ----------------------------------------------------
__device__ __forceinline__ unsigned pack_bf2(float e, float o) {
  __nv_bfloat162 h;
  h.x = __float2bfloat16(e);
  h.y = __float2bfloat16(o);
  return *reinterpret_cast<unsigned*>(&h);
}
__device__ __forceinline__ void split_bf(float v, __nv_bfloat16& h, __nv_bfloat16& l) {
  h = __float2bfloat16(v);
  l = __float2bfloat16(v - __bfloat162float(h));
}
__device__ __forceinline__ void hilo2(const float* a, uint2& h, uint2& l) {
  float h0 = __bfloat162float(__float2bfloat16(a[0]));
  float h1 = __bfloat162float(__float2bfloat16(a[1]));
  float h2 = __bfloat162float(__float2bfloat16(a[2]));
  float h3 = __bfloat162float(__float2bfloat16(a[3]));
  h.x = pack_bf2(a[0], a[1]);
  h.y = pack_bf2(a[2], a[3]);
  l.x = pack_bf2(a[0] - h0, a[1] - h1);
  l.y = pack_bf2(a[2] - h2, a[3] - h3);
}
__device__ __forceinline__ void ldsm4(unsigned& r0, unsigned& r1, unsigned& r2,
                                      unsigned& r3, unsigned addr) {
  asm volatile("ldmatrix.sync.aligned.m8n8.x4.shared.b16 {%0,%1,%2,%3},[%4];"
               : "=r"(r0), "=r"(r1), "=r"(r2), "=r"(r3) : "r"(addr));
}
__device__ __forceinline__ void ldsm4t(unsigned& r0, unsigned& r1, unsigned& r2,
                                       unsigned& r3, unsigned addr) {
  asm volatile("ldmatrix.sync.aligned.m8n8.x4.trans.shared.b16 {%0,%1,%2,%3},[%4];"
               : "=r"(r0), "=r"(r1), "=r"(r2), "=r"(r3) : "r"(addr));
}
__device__ __forceinline__ void mma16816(float* d, const unsigned* a,
                                         unsigned b0, unsigned b1) {
  asm volatile(
    "mma.sync.aligned.m16n8k16.row.col.f32.bf16.bf16.f32 "
    "{%0,%1,%2,%3},{%4,%5,%6,%7},{%8,%9},{%0,%1,%2,%3};"
    : "+f"(d[0]), "+f"(d[1]), "+f"(d[2]), "+f"(d[3])
    : "r"(a[0]), "r"(a[1]), "r"(a[2]), "r"(a[3]), "r"(b0), "r"(b1));
}
__device__ __forceinline__ void cp16(unsigned saddr, const void* g) {
  asm volatile("cp.async.cg.shared.global [%0],[%1],16;" :: "r"(saddr), "l"(g));
}
#define CP_COMMIT() asm volatile("cp.async.commit_group;")
#define CP_WAIT(n)  asm volatile("cp.async.wait_group %0;" :: "n"(n))

// =============================================================================
// k_front: [0,64) G | [64,96) Wv conv | [96,104) bias | [104,616) prep (4 c/blk)
// =============================================================================
#define GA_H 0
#define GA_L 4608
#define GB_H 9216
#define GB_L 13824
// prep overlay offsets within smem_all
#define P_SM4 0              // float4 [4][16][16] = 16384
#define P_XBV 16384          // float [4][64]      = 1024
#define P_X1S 17408          // float [4][16]      = 256
#define P_PIX 17664          // int   [16]

__global__ __launch_bounds__(256)
void k_front(const float* __restrict__ x, const int* __restrict__ pos,
             const float* __restrict__ pe, const float* __restrict__ Wq,
             const float* __restrict__ Wk, const float* __restrict__ Wv,
             const float* __restrict__ bq, const float* __restrict__ bk) {
  __shared__ __align__(16) char smem_all[18432];
  char* gsm = smem_all;

  int bx = blockIdx.x;
  int t = threadIdx.x;

  if (bx < 64) {                       // ---------------- G = Wq^T Wk ----------
    int cx = bx & 7, kx = bx >> 3;
    unsigned sb = (unsigned)__cvta_generic_to_shared(gsm);
    int wid = t >> 5, lane = t & 31;
    int my = (wid >> 2) * 32, nw = (wid & 3) * 16;
    int gI = lane >> 2, tq = lane & 3;
    float acc[2][2][4] = {};
    int rr0 = t >> 4, c4 = t & 15;
    for (int o0 = 0; o0 < CKQ; o0 += 32) {
      #pragma unroll
      for (int z = 0; z < 2; z++) {
        int row = rr0 + z * 16;
        float4 v = *(const float4*)&Wq[(size_t)(o0 + row) * NC + cx * 64 + c4 * 4];
        uint2 h, l;
        hilo2((const float*)&v, h, l);
        *(uint2*)(gsm + GA_H + row * 144 + c4 * 8) = h;
        *(uint2*)(gsm + GA_L + row * 144 + c4 * 8) = l;
        float4 w = *(const float4*)&Wk[(size_t)(o0 + row) * NC + kx * 64 + c4 * 4];
        hilo2((const float*)&w, h, l);
        *(uint2*)(gsm + GB_H + row * 144 + c4 * 8) = h;
        *(uint2*)(gsm + GB_L + row * 144 + c4 * 8) = l;
      }
      __syncthreads();
      #pragma unroll
      for (int ks = 0; ks < 32; ks += 16) {
        unsigned Ah[2][4], Al[2][4];
        unsigned arow = ks + (lane & 7) + ((lane & 16) >> 1);
        #pragma unroll
        for (int mt = 0; mt < 2; mt++) {
          unsigned mcol = my + mt * 16 + (lane & 8);
          unsigned aaddr = sb + GA_H + arow * 144 + mcol * 2;
          ldsm4t(Ah[mt][0], Ah[mt][1], Ah[mt][2], Ah[mt][3], aaddr);
          ldsm4t(Al[mt][0], Al[mt][1], Al[mt][2], Al[mt][3], aaddr + (GA_L - GA_H));
        }
        unsigned Bh[4], Bl[4];
        {
          unsigned brow = ks + (lane & 7) + (lane & 8);
          unsigned bcol = nw + ((lane & 16) >> 1);
          unsigned baddr = sb + GB_H + brow * 144 + bcol * 2;
          ldsm4t(Bh[0], Bh[1], Bh[2], Bh[3], baddr);
          ldsm4t(Bl[0], Bl[1], Bl[2], Bl[3], baddr + (GB_L - GB_H));
        }
        #pragma unroll
        for (int mt = 0; mt < 2; mt++)
          #pragma unroll
          for (int sub = 0; sub < 2; sub++) {
            mma16816(acc[mt][sub], Ah[mt], Bh[sub * 2], Bh[sub * 2 + 1]);
            mma16816(acc[mt][sub], Ah[mt], Bl[sub * 2], Bl[sub * 2 + 1]);
            mma16816(acc[mt][sub], Al[mt], Bh[sub * 2], Bh[sub * 2 + 1]);
          }
      }
      __syncthreads();
    }
    #pragma unroll
    for (int mt = 0; mt < 2; mt++)
      #pragma unroll
      for (int nt = 0; nt < 2; nt++) {
        int cg = cx * 64 + my + mt * 16 + gI;
        int kg = kx * 64 + nw + nt * 8 + 2 * tq;
        split_bf(acc[mt][nt][0], g_Gh[cg][kg],     g_Gl[cg][kg]);
        split_bf(acc[mt][nt][1], g_Gh[cg][kg + 1], g_Gl[cg][kg + 1]);
        split_bf(acc[mt][nt][2], g_Gh[cg + 8][kg],     g_Gl[cg + 8][kg]);
        split_bf(acc[mt][nt][3], g_Gh[cg + 8][kg + 1], g_Gl[cg + 8][kg + 1]);
      }
    return;
  }

  if (bx < 96) {                       // ---------------- Wv convert -----------
    int base = (bx - 64) * 2048;
    #pragma unroll
    for (int j = 0; j < 8; j++) {
      int idx4 = base + j * 256 + t;
      float4 v = ((const float4*)Wv)[idx4];
      __nv_bfloat16 h0, l0, h1, l1;
      split_bf(v.x, h0, l0); split_bf(v.y, h1, l1);
      ((__nv_bfloat162*)g_Wvh)[idx4 * 2] = {h0, h1};
      ((__nv_bfloat162*)g_Wvl)[idx4 * 2] = {l0, l1};
      split_bf(v.z, h0, l0); split_bf(v.w, h1, l1);
      ((__nv_bfloat162*)g_Wvh)[idx4 * 2 + 1] = {h0, h1};
      ((__nv_bfloat162*)g_Wvl)[idx4 * 2 + 1] = {l0, l1};
    }
    return;
  }

  if (bx < 104) {                      // ---------------- bias blocks ----------
    int c = (bx - 96) * 64 + (t >> 2);
    int q = t & 3;
    float s1 = 0.f, s2 = 0.f;
    #pragma unroll 8
    for (int o = q; o < CKQ; o += 4) {
      s1 += Wq[(size_t)o * NC + c] * bk[o];
      s2 += Wk[(size_t)o * NC + c] * bq[o];
    }
    s1 += __shfl_xor_sync(0xffffffffu, s1, 1);
    s1 += __shfl_xor_sync(0xffffffffu, s1, 2);
    s2 += __shfl_xor_sync(0xffffffffu, s2, 1);
    s2 += __shfl_xor_sync(0xffffffffu, s2, 2);
    if (q == 0) { g_v1[c] = s1; g_v2[c] = s2; }
    if (bx == 96 && t < 32) {
      float s = 0.f;
      for (int o = t; o < CKQ; o += 32) s += bq[o] * bk[o];
      #pragma unroll
      for (int d = 16; d > 0; d >>= 1) s += __shfl_xor_sync(0xffffffffu, s, d);
      if (t == 0) g_s0 = s;
    }
    return;
  }

  // ---------------- prep: 4 channels per block --------------------------------
  {
    int p = bx - 104;                  // 0..511
    int b = p >> 7, c0 = (p & 127) * 4;
    int hq = t >> 4, tw = t & 15;
    float4* SM4 = (float4*)(smem_all + P_SM4);    // [j][hq][tw]
    float*  XBV = (float*)(smem_all + P_XBV);     // [j][64]
    float*  X1S = (float*)(smem_all + P_X1S);     // [j][16]
    int*    PIX = (int*)(smem_all + P_PIX);
    if (t < 16) PIX[t] = pos[b * NN + 4 * t] >> 3;

    const float* xp = x + ((size_t)(b * NC + c0)) * NH * NW;
    float4 s[4];
    #pragma unroll
    for (int j = 0; j < 4; j++) s[j] = {0.f, 0.f, 0.f, 0.f};
    #pragma unroll
    for (int h = 0; h < 4; h++) {
      #pragma unroll
      for (int j = 0; j < 4; j++) {
        float4 v = *(const float4*)&xp[(size_t)j * NH * NW + (hq + h * 16) * NW + tw * 4];
        s[j].x += v.x; s[j].y += v.y; s[j].z += v.z; s[j].w += v.w;
      }
    }
    #pragma unroll
    for (int j = 0; j < 4; j++) SM4[j * 256 + hq * 16 + tw] = s[j];
    __syncthreads();
    if (hq < 4) {
      float4 a = {0.f, 0.f, 0.f, 0.f};
      #pragma unroll
      for (int q = 0; q < 16; q++) {
        float4 v = SM4[hq * 256 + q * 16 + tw];
        a.x += v.x; a.y += v.y; a.z += v.z; a.w += v.w;
      }
      const float inv = 1.0f / NH;
      a.x *= inv; a.y *= inv; a.z *= inv; a.w *= inv;
      *(float4*)&XBV[hq * 64 + tw * 4] = a;
      *(float4*)&g_xbar[b][c0 + hq][tw * 4] = a;
    }
    __syncthreads();
    if (t < 64) {
      int j = t >> 4, wp = t & 15;
      X1S[j * 16 + wp] = 0.25f * (XBV[j * 64 + 4 * wp] + XBV[j * 64 + 4 * wp + 1] +
                                  XBV[j * 64 + 4 * wp + 2] + XBV[j * 64 + 4 * wp + 3])
                         + pe[PIX[wp] * NC + c0 + j];
    }
    __syncthreads();
    {
      int j = t >> 6, w = t & 63;
      float src = (w * 15.0f) / 63.0f;
      int   i0  = (int)floorf(src);
      int   i1  = min(i0 + 1, 15);
      float tt  = src - (float)i0;
      g_x2df[b][c0 + j][w] = X1S[j * 16 + i0] * (1.0f - tt) + X1S[j * 16 + i1] * tt;
    }
  }
}

// =============================================================================
// k_MV: [0,32) M^T tiles | [32,64) vbar tiles (hi only out) | [64,68) dw
// =============================================================================
#define ACV0 0
#define ACVLO 9216
#define ACVBUF 18432         // 2 buffers end 36864
#define CPB0 36864
#define CPBLO 9216
#define CPBSZ 18432          // 2 buffers end 73728
#define MV_SMEM 73728

__global__ __launch_bounds__(256)
void k_MV(const float* __restrict__ bv) {
  extern __shared__ char dsm[];
  unsigned sb = (unsigned)__cvta_generic_to_shared(dsm);
  int bx = blockIdx.x, tid = threadIdx.x;

  if (bx >= 64) {                      // dw
    int b = bx - 64;
    int w = tid >> 2, q = tid & 3;
    float s = 0.f;
    #pragma unroll 8
    for (int c = q; c < NC; c += 4) s += g_x2df[b][c][w] * g_v2[c];
    s += __shfl_xor_sync(0xffffffffu, s, 1);
    s += __shfl_xor_sync(0xffffffffu, s, 2);
    if (q == 0) g_dw[b][w] = s + g_s0;
    return;
  }

  bool mtr = (bx < 32);
  int b  = mtr ? (bx >> 3) : ((bx - 32) >> 3);
  int c0 = (mtr ? (bx & 7) : ((bx - 32) & 7)) * 64;
  const float* Xf = mtr ? &g_x2df[b][0][0] : &g_xbar[b][0][0];
  const __nv_bfloat16* Bhg = mtr ? &g_Gh[c0][0] : &g_Wvh[c0][0];
  const __nv_bfloat16* Blg = mtr ? &g_Gl[c0][0] : &g_Wvl[c0][0];

  int rc = tid >> 4, ln4 = tid & 15;
  float4 xr[4];
  auto load_f = [&](int k0) {
    #pragma unroll
    for (int z = 0; z < 4; z++)
      xr[z] = *(const float4*)&Xf[(size_t)(k0 + rc + z * 16) * NW + ln4 * 4];
  };
  auto store_f = [&](unsigned base) {
    #pragma unroll
    for (int z = 0; z < 4; z++) {
      uint2 h, l;
      hilo2((const float*)&xr[z], h, l);
      unsigned a = base + (rc + z * 16) * 144 + ln4 * 8;
      *(uint2*)(dsm + a) = h;
      *(uint2*)(dsm + a + ACVLO) = l;
    }
  };
  auto issueB = [&](int k0, unsigned base) {
    #pragma unroll
    for (int u = tid; u < 512; u += 256) {
      int r = u >> 3, q = u & 7;
      cp16(sb + base + r * 144 + q * 16,         Bhg + (size_t)r * NC + k0 + q * 8);
      cp16(sb + base + CPBLO + r * 144 + q * 16, Blg + (size_t)r * NC + k0 + q * 8);
    }
  };

  int wid = tid >> 5, lane = tid & 31;
  int my = (wid >> 2) * 32, nw = (wid & 3) * 16;
  int gI = lane >> 2, tq = lane & 3;
  float acc[2][2][4] = {};

  load_f(0);
  issueB(0, CPB0); CP_COMMIT();
  store_f(ACV0);
  CP_WAIT(0);
  __syncthreads();

  for (int kc = 0; kc < 8; kc++) {
    if (kc < 7) {
      load_f((kc + 1) * 64);
      issueB((kc + 1) * 64, CPB0 + ((kc + 1) & 1) * CPBSZ); CP_COMMIT();
    }
    unsigned acv = ACV0 + (kc & 1) * ACVBUF;
    unsigned cpb = CPB0 + (kc & 1) * CPBSZ;
    if (mtr) {
      #pragma unroll
      for (int ks = 0; ks < 64; ks += 16) {
        unsigned Ah[2][4], Al[2][4];
        unsigned arow = ks + (lane & 7) + ((lane & 16) >> 1);
        #pragma unroll
        for (int mt = 0; mt < 2; mt++) {
          unsigned acol = my + mt * 16 + (lane & 8);
          unsigned aaddr = sb + acv + arow * 144 + acol * 2;
          ldsm4t(Ah[mt][0], Ah[mt][1], Ah[mt][2], Ah[mt][3], aaddr);
          ldsm4t(Al[mt][0], Al[mt][1], Al[mt][2], Al[mt][3], aaddr + ACVLO);
        }
        unsigned Bh[4], Bl[4];
        {
          unsigned row = nw + (lane & 7) + ((lane & 16) >> 1);
          unsigned coff = ks * 2 + ((lane & 8) << 1);
          unsigned baddr = sb + cpb + row * 144 + coff;
          ldsm4(Bh[0], Bh[1], Bh[2], Bh[3], baddr);
          ldsm4(Bl[0], Bl[1], Bl[2], Bl[3], baddr + CPBLO);
        }
        #pragma unroll
        for (int mt = 0; mt < 2; mt++)
          #pragma unroll
          for (int sub = 0; sub < 2; sub++) {
            mma16816(acc[mt][sub], Ah[mt], Bh[sub * 2], Bh[sub * 2 + 1]);
            mma16816(acc[mt][sub], Ah[mt], Bl[sub * 2], Bl[sub * 2 + 1]);
            mma16816(acc[mt][sub], Al[mt], Bh[sub * 2], Bh[sub * 2 + 1]);
          }
      }
    } else {
      #pragma unroll
      for (int ks = 0; ks < 64; ks += 16) {
        unsigned Ah[2][4], Al[2][4];
        #pragma unroll
        for (int mt = 0; mt < 2; mt++) {
          unsigned row = my + mt * 16 + (lane & 15);
          unsigned coff = ks * 2 + ((lane >> 4) << 4);
          unsigned aaddr = sb + cpb + row * 144 + coff;
          ldsm4(Ah[mt][0], Ah[mt][1], Ah[mt][2], Ah[mt][3], aaddr);
          ldsm4(Al[mt][0], Al[mt][1], Al[mt][2], Al[mt][3], aaddr + CPBLO);
        }
        unsigned Bh[4], Bl[4];
        {
          unsigned brow = ks + (lane & 7) + (lane & 8);
          unsigned bcol = nw + ((lane & 16) >> 1);
          unsigned baddr = sb + acv + brow * 144 + bcol * 2;
          ldsm4t(Bh[0], Bh[1], Bh[2], Bh[3], baddr);
          ldsm4t(Bl[0], Bl[1], Bl[2], Bl[3], baddr + ACVLO);
        }
        #pragma unroll
        for (int mt = 0; mt < 2; mt++)
          #pragma unroll
          for (int sub = 0; sub < 2; sub++) {
            mma16816(acc[mt][sub], Ah[mt], Bh[sub * 2], Bh[sub * 2 + 1]);
            mma16816(acc[mt][sub], Ah[mt], Bl[sub * 2], Bl[sub * 2 + 1]);
            mma16816(acc[mt][sub], Al[mt], Bh[sub * 2], Bh[sub * 2 + 1]);
          }
      }
    }
    if (kc < 7) {
      store_f(ACV0 + ((kc + 1) & 1) * ACVBUF);
      CP_WAIT(0);
    }
    __syncthreads();
  }

  if (mtr) {
    #pragma unroll
    for (int mt = 0; mt < 2; mt++)
      #pragma unroll
      for (int nt = 0; nt < 2; nt++) {
        int w = my + mt * 16 + gI;
        int c = c0 + nw + nt * 8 + 2 * tq;
        split_bf(acc[mt][nt][0] + g_v1[c],     g_MTh[b][w][c],     g_MTl[b][w][c]);
        split_bf(acc[mt][nt][1] + g_v1[c + 1], g_MTh[b][w][c + 1], g_MTl[b][w][c + 1]);
        split_bf(acc[mt][nt][2] + g_v1[c],     g_MTh[b][w + 8][c],     g_MTl[b][w + 8][c]);
        split_bf(acc[mt][nt][3] + g_v1[c + 1], g_MTh[b][w + 8][c + 1], g_MTl[b][w + 8][c + 1]);
      }
  } else {
    #pragma unroll
    for (int mt = 0; mt < 2; mt++)
      #pragma unroll
      for (int nt = 0; nt < 2; nt++) {
        int c = c0 + my + mt * 16 + gI;
        int w = nw + nt * 8 + 2 * tq;
        float bv0 = bv[c], bv8 = bv[c + 8];
        g_vbh[b][c][w]         = __float2bfloat16(acc[mt][nt][0] + bv0);
        g_vbh[b][c][w + 1]     = __float2bfloat16(acc[mt][nt][1] + bv0);
        g_vbh[b][c + 8][w]     = __float2bfloat16(acc[mt][nt][2] + bv8);
        g_vbh[b][c + 8][w + 1] = __float2bfloat16(acc[mt][nt][3] + bv8);
      }
  }
}

// =============================================================================
// k_fused: n-tile 64, 2 blocks/SM, 32x32 warp tiles.
// phase 1: 3-term hi/lo. phase 2: pure bf16 (vb_hi x attn_hi), 128c chunks.
// =============================================================================
#define XA0 0
#define XALO 9216
#define XABUF 18432          // 2 buffers end 36864
#define MB0 36864
#define MBLO 9216
#define MBSZ 18432           // 2 buffers end 73728
#define EF_OFF 73728         // 64*68*4 = 17408 -> end 91136
#define ATT_H 0              // aliases XA buf0 (dead after phase 1)
#define VB0 18432            // aliases XA buf1 (dead after phase 1)
#define VB1 36864            // aliases MB buf0 (dead after phase 1)
#define VBSZ 18432           // hi only: 128 rows x 144B
#define SMEM_FUSED 92160

__global__ __launch_bounds__(256, 2)
void k_fused(const float* __restrict__ x, const float* __restrict__ gamma,
             float* __restrict__ out) {
  extern __shared__ char sm[];
  unsigned sb = (unsigned)__cvta_generic_to_shared(sm);
  int tid = threadIdx.x;
  int wid = tid >> 5, lane = tid & 31;
  int b = blockIdx.y;
  int n0 = blockIdx.x * 64;
  int gI = lane >> 2, tq = lane & 3;

  const float* xb = x + (size_t)b * NC * NN + n0;
  int rc = tid >> 4, ln4 = tid & 15;

  float4 xr[4];
  auto load_x = [&](int c0) {
    #pragma unroll
    for (int z = 0; z < 4; z++)
      xr[z] = *(const float4*)(xb + (size_t)(c0 + rc + z * 16) * NN + ln4 * 4);
  };
  auto store_x = [&](unsigned xbase) {
    #pragma unroll
    for (int z = 0; z < 4; z++) {
      uint2 h, l;
      hilo2((const float*)&xr[z], h, l);
      unsigned base0 = xbase + (rc + z * 16) * 144 + ln4 * 8;
      *(uint2*)(sm + base0) = h;
      *(uint2*)(sm + base0 + XALO) = l;
    }
  };
  auto issue_M = [&](int c0, unsigned mb) {
    #pragma unroll
    for (int u = tid; u < 512; u += 256) {
      int rr = u >> 3, q = u & 7;
      cp16(sb + mb + rr * 144 + q * 16,        &g_MTh[b][rr][c0 + q * 8]);
      cp16(sb + mb + MBLO + rr * 144 + q * 16, &g_MTl[b][rr][c0 + q * 8]);
    }
  };
  auto issue_VB = [&](int cc, unsigned base) {
    #pragma unroll
    for (int u = tid; u < 1024; u += 256) {
      int rr = u >> 3, q = u & 7;
      cp16(sb + base + rr * 144 + q * 16, &g_vbh[b][cc * 128 + rr][q * 8]);
    }
  };

  // ---------------- phase 1: E[64n][64w], k-split across warp halves ----------
  int wq = wid & 3, khalf = wid >> 2;
  int ny = (wq >> 1) * 32, wy = (wq & 1) * 32;
  int ksb = khalf * 32;
  float acc1[2][4][4] = {};

  auto mma_chunk = [&](unsigned xab, unsigned mbb) {
    #pragma unroll
    for (int ks = 0; ks < 32; ks += 16) {
      int kk = ksb + ks;
      unsigned Ah[2][4], Al[2][4];
      unsigned arow = kk + (lane & 7) + ((lane & 16) >> 1);
      #pragma unroll
      for (int mt = 0; mt < 2; mt++) {
        unsigned acol = ny + mt * 16 + (lane & 8);
        unsigned aaddr = sb + xab + arow * 144 + acol * 2;
        ldsm4t(Ah[mt][0], Ah[mt][1], Ah[mt][2], Ah[mt][3], aaddr);
        ldsm4t(Al[mt][0], Al[mt][1], Al[mt][2], Al[mt][3], aaddr + XALO);
      }
      unsigned Bh[2][4], Bl[2][4];
      #pragma unroll
      for (int bt = 0; bt < 2; bt++) {
        unsigned brow = wy + bt * 16 + (lane & 7) + ((lane & 16) >> 1);
        unsigned coff = kk * 2 + ((lane & 8) << 1);
        unsigned baddr = sb + mbb + brow * 144 + coff;
        ldsm4(Bh[bt][0], Bh[bt][1], Bh[bt][2], Bh[bt][3], baddr);
        ldsm4(Bl[bt][0], Bl[bt][1], Bl[bt][2], Bl[bt][3], baddr + MBLO);
      }
      #pragma unroll
      for (int mt = 0; mt < 2; mt++)
        #pragma unroll
        for (int bt = 0; bt < 2; bt++)
          #pragma unroll
          for (int sub = 0; sub < 2; sub++) {
            int wt = bt * 2 + sub;
            mma16816(acc1[mt][wt], Ah[mt], Bh[bt][sub * 2], Bh[bt][sub * 2 + 1]);
            mma16816(acc1[mt][wt], Ah[mt], Bl[bt][sub * 2], Bl[bt][sub * 2 + 1]);
            mma16816(acc1[mt][wt], Al[mt], Bh[bt][sub * 2], Bh[bt][sub * 2 + 1]);
          }
    }
  };

  load_x(0);
  issue_M(0, MB0); CP_COMMIT();
  store_x(XA0);
  CP_WAIT(0);
  __syncthreads();

  for (int i = 0; i < 8; i++) {
    if (i < 7) {
      load_x((i + 1) * 64);
      issue_M((i + 1) * 64, MB0 + ((i + 1) & 1) * MBSZ); CP_COMMIT();
    }
    mma_chunk(XA0 + (i & 1) * XABUF, MB0 + (i & 1) * MBSZ);
    if (i < 7) {
      store_x(XA0 + ((i + 1) & 1) * XABUF);
      CP_WAIT(0);
    }
    __syncthreads();
  }

  issue_VB(0, VB0);
  CP_COMMIT();

  // reduction: khalf 0 writes (with dw), khalf 1 adds
  float* Ef = (float*)(sm + EF_OFF);
  if (khalf == 0) {
    #pragma unroll
    for (int wt = 0; wt < 4; wt++) {
      int wc = wy + (wt >> 1) * 16 + (wt & 1) * 8 + 2 * tq;
      float d0 = g_dw[b][wc], d1 = g_dw[b][wc + 1];
      #pragma unroll
      for (int mt = 0; mt < 2; mt++) {
        int r = ny + mt * 16 + gI;
        float2 v0 = {acc1[mt][wt][0] + d0, acc1[mt][wt][1] + d1};
        float2 v1 = {acc1[mt][wt][2] + d0, acc1[mt][wt][3] + d1};
        *(float2*)&Ef[r * 68 + wc] = v0;
        *(float2*)&Ef[(r + 8) * 68 + wc] = v1;
      }
    }
  }
  __syncthreads();
  if (khalf == 1) {
    #pragma unroll
    for (int wt = 0; wt < 4; wt++) {
      int wc = wy + (wt >> 1) * 16 + (wt & 1) * 8 + 2 * tq;
      #pragma unroll
      for (int mt = 0; mt < 2; mt++) {
        int r = ny + mt * 16 + gI;
        float2 v0 = *(float2*)&Ef[r * 68 + wc];
        float2 v1 = *(float2*)&Ef[(r + 8) * 68 + wc];
        v0.x += acc1[mt][wt][0]; v0.y += acc1[mt][wt][1];
        v1.x += acc1[mt][wt][2]; v1.y += acc1[mt][wt][3];
        *(float2*)&Ef[r * 68 + wc] = v0;
        *(float2*)&Ef[(r + 8) * 68 + wc] = v1;
      }
    }
  }
  __syncthreads();

  // softmax over w (4 threads/row, 64 rows)
  {
    int row = tid >> 2, q = tid & 3;
    float mx = -1e30f;
    for (int w = q; w < NW; w += 4) mx = fmaxf(mx, Ef[row * 68 + w]);
    mx = fmaxf(mx, __shfl_xor_sync(0xffffffffu, mx, 1));
    mx = fmaxf(mx, __shfl_xor_sync(0xffffffffu, mx, 2));
    float s = 0.f;
    for (int w = q; w < NW; w += 4) {
      float e = __expf(Ef[row * 68 + w] - mx);
      Ef[row * 68 + w] = e;
      s += e;
    }
    s += __shfl_xor_sync(0xffffffffu, s, 1);
    s += __shfl_xor_sync(0xffffffffu, s, 2);
    float inv = 1.0f / s;
    for (int w = q; w < NW; w += 4) Ef[row * 68 + w] *= inv;
  }
  __syncthreads();

  // convert attn to bf16 hi only [n][w], rows 144B (aliases XA buf0)
  #pragma unroll
  for (int i = 0; i < 8; i++) {
    int p = tid + i * 256;
    int n = p >> 5, wp = p & 31;
    float e0 = Ef[n * 68 + 2 * wp], e1 = Ef[n * 68 + 2 * wp + 1];
    *(unsigned*)(sm + ATT_H + n * 144 + wp * 4) = pack_bf2(e0, e1);
  }
  __syncthreads();

  // ---------------- phase 2: out = gamma*(vb_hi @ attn_hi^T) + x --------------
  float g = gamma[0];
  int cy = (wid >> 1) * 32;
  int nx = (wid & 1) * 32;
  for (int cc = 0; cc < 4; cc++) {
    if (cc < 3) {
      issue_VB(cc + 1, ((cc + 1) & 1) ? VB1 : VB0);
      CP_COMMIT();
      CP_WAIT(1);
    } else {
      CP_WAIT(0);
    }
    __syncthreads();

    // L2-prefetch this chunk's residual-x lines
    {
      const float* px = x + ((size_t)(b * NC + cc * 128 + (tid >> 1))) * NN
                          + n0 + (tid & 1) * 32;
      asm volatile("prefetch.global.L2 [%0];" :: "l"(px));
    }

    unsigned vbb = (cc & 1) ? VB1 : VB0;
    float acc2[2][4][4] = {};
    #pragma unroll
    for (int ks = 0; ks < 64; ks += 16) {
      unsigned Ah[2][4];
      #pragma unroll
      for (int mt = 0; mt < 2; mt++) {
        unsigned row = cy + mt * 16 + (lane & 15);
        unsigned coff = ks * 2 + ((lane >> 4) << 4);
        ldsm4(Ah[mt][0], Ah[mt][1], Ah[mt][2], Ah[mt][3], sb + vbb + row * 144 + coff);
      }
      unsigned Bh[2][4];
      #pragma unroll
      for (int bt = 0; bt < 2; bt++) {
        unsigned row = nx + bt * 16 + (lane & 7) + ((lane & 16) >> 1);
        unsigned coff = ks * 2 + ((lane & 8) << 1);
        ldsm4(Bh[bt][0], Bh[bt][1], Bh[bt][2], Bh[bt][3], sb + ATT_H + row * 144 + coff);
      }
      #pragma unroll
      for (int mt = 0; mt < 2; mt++)
        #pragma unroll
        for (int bt = 0; bt < 2; bt++)
          #pragma unroll
          for (int sub = 0; sub < 2; sub++) {
            int nt = bt * 2 + sub;
            mma16816(acc2[mt][nt], Ah[mt], Bh[bt][sub * 2], Bh[bt][sub * 2 + 1]);
          }
    }
    // epilogue: residual add + store
    #pragma unroll
    for (int mt = 0; mt < 2; mt++) {
      int c = cc * 128 + cy + mt * 16 + gI;
      #pragma unroll
      for (int nt = 0; nt < 4; nt++) {
        int n = n0 + nx + (nt >> 1) * 16 + (nt & 1) * 8 + 2 * tq;
        size_t off = ((size_t)(b * NC + c)) * NN + n;
        float2 xv0 = *(const float2*)(x + off);
        float2 xv1 = *(const float2*)(x + off + (size_t)8 * NN);
        float2 o0 = {fmaf(g, acc2[mt][nt][0], xv0.x), fmaf(g, acc2[mt][nt][1], xv0.y)};
        float2 o1 = {fmaf(g, acc2[mt][nt][2], xv1.x), fmaf(g, acc2[mt][nt][3], xv1.y)};
        *(float2*)(out + off) = o0;
        *(float2*)(out + off + (size_t)8 * NN) = o1;
      }
    }
    __syncthreads();
  }
}

// ---------------- launch -----------------------------------------------------
extern "C" void kernel_launch(void* const* d_in, const int* in_sizes, int n_in,
                              void* d_out, int out_size) {
  const float* x     = (const float*)d_in[0];
  const float* Wq    = (const float*)d_in[1];
  const float* bq    = (const float*)d_in[2];
  const float* Wk    = (const float*)d_in[3];
  const float* bk    = (const float*)d_in[4];
  const float* Wv    = (const float*)d_in[5];
  const float* bv    = (const float*)d_in[6];
  const float* gamma = (const float*)d_in[7];
  const float* pe    = (const float*)d_in[8];
  const int*   pos   = (const int*)  d_in[9];
  float* out = (float*)d_out;

  cudaFuncSetAttribute(k_MV, cudaFuncAttributeMaxDynamicSharedMemorySize, MV_SMEM);
  cudaFuncSetAttribute(k_fused, cudaFuncAttributeMaxDynamicSharedMemorySize,
                       SMEM_FUSED);

  k_front<<<616, 256>>>(x, pos, pe, Wq, Wk, Wv, bq, bk);
  k_MV<<<68, 256, MV_SMEM>>>(bv);
  k_fused<<<dim3(NN / 64, NB), 256, SMEM_FUSED>>>(x, gamma, out);
}

// round 17
// speedup vs baseline: 1.9454x; 1.0160x over previous
#include <cuda_runtime.h>
#include <cuda_bf16.h>

#define NB 4
#define NC 512
#define CKQ 256
#define NW 64
#define NH 64
#define NN 4096   // H*W

// ---------------- scratch (device globals) ----------------------------------
__device__ float g_xbar[NB][NC][NW];
__device__ float g_x2df[NB][NC][NW];
__device__ __align__(16) __nv_bfloat16 g_Gh[NC][NC], g_Gl[NC][NC];
__device__ __align__(16) __nv_bfloat16 g_Wvh[NC][NC], g_Wvl[NC][NC];
__device__ __align__(16) __nv_bfloat16 g_MTh[NB][NW][NC], g_MTl[NB][NW][NC];
__device__ __align__(16) __nv_bfloat16 g_vbh[NB][NC][NW];
__device__ float g_v1[NC];        // Wq^T bk
__device__ float g_v2[NC];        // Wk^T bq
__device__ float g_s0;            // bq . bk
__device__ float g_dw[NB][NW];

// ---------------- helpers ----------------------------------------------------
__device__ __forceinline__ unsigned pack_bf2(float e, float o) {
  __nv_bfloat162 h;
  h.x = __float2bfloat16(e);
  h.y = __float2bfloat16(o);
  return *reinterpret_cast<unsigned*>(&h);
}
__device__ __forceinline__ void split_bf(float v, __nv_bfloat16& h, __nv_bfloat16& l) {
  h = __float2bfloat16(v);
  l = __float2bfloat16(v - __bfloat162float(h));
}
__device__ __forceinline__ void hilo2(const float* a, uint2& h, uint2& l) {
  float h0 = __bfloat162float(__float2bfloat16(a[0]));
  float h1 = __bfloat162float(__float2bfloat16(a[1]));
  float h2 = __bfloat162float(__float2bfloat16(a[2]));
  float h3 = __bfloat162float(__float2bfloat16(a[3]));
  h.x = pack_bf2(a[0], a[1]);
  h.y = pack_bf2(a[2], a[3]);
  l.x = pack_bf2(a[0] - h0, a[1] - h1);
  l.y = pack_bf2(a[2] - h2, a[3] - h3);
}
__device__ __forceinline__ void ldsm4(unsigned& r0, unsigned& r1, unsigned& r2,
                                      unsigned& r3, unsigned addr) {
  asm volatile("ldmatrix.sync.aligned.m8n8.x4.shared.b16 {%0,%1,%2,%3},[%4];"
               : "=r"(r0), "=r"(r1), "=r"(r2), "=r"(r3) : "r"(addr));
}
__device__ __forceinline__ void ldsm4t(unsigned& r0, unsigned& r1, unsigned& r2,
                                       unsigned& r3, unsigned addr) {
  asm volatile("ldmatrix.sync.aligned.m8n8.x4.trans.shared.b16 {%0,%1,%2,%3},[%4];"
               : "=r"(r0), "=r"(r1), "=r"(r2), "=r"(r3) : "r"(addr));
}
__device__ __forceinline__ void mma16816(float* d, const unsigned* a,
                                         unsigned b0, unsigned b1) {
  asm volatile(
    "mma.sync.aligned.m16n8k16.row.col.f32.bf16.bf16.f32 "
    "{%0,%1,%2,%3},{%4,%5,%6,%7},{%8,%9},{%0,%1,%2,%3};"
    : "+f"(d[0]), "+f"(d[1]), "+f"(d[2]), "+f"(d[3])
    : "r"(a[0]), "r"(a[1]), "r"(a[2]), "r"(a[3]), "r"(b0), "r"(b1));
}
__device__ __forceinline__ void cp16(unsigned saddr, const void* g) {
  asm volatile("cp.async.cg.shared.global [%0],[%1],16;" :: "r"(saddr), "l"(g));
}
#define CP_COMMIT() asm volatile("cp.async.commit_group;")
#define CP_WAIT(n)  asm volatile("cp.async.wait_group %0;" :: "n"(n))

// =============================================================================
// k_front: [0,64) G | [64,96) Wv conv | [96,104) bias | [104,616) prep (4 c/blk)
// G: weight loads register-prefetched one K-chunk ahead (hides LDG latency).
// =============================================================================
#define GA_H 0
#define GA_L 4608
#define GB_H 9216
#define GB_L 13824
// prep overlay offsets within smem_all
#define P_SM4 0              // float4 [4][16][16] = 16384
#define P_XBV 16384          // float [4][64]      = 1024
#define P_X1S 17408          // float [4][16]      = 256
#define P_PIX 17664          // int   [16]

__global__ __launch_bounds__(256)
void k_front(const float* __restrict__ x, const int* __restrict__ pos,
             const float* __restrict__ pe, const float* __restrict__ Wq,
             const float* __restrict__ Wk, const float* __restrict__ Wv,
             const float* __restrict__ bq, const float* __restrict__ bk) {
  __shared__ __align__(16) char smem_all[18432];
  char* gsm = smem_all;

  int bx = blockIdx.x;
  int t = threadIdx.x;

  if (bx < 64) {                       // ---------------- G = Wq^T Wk ----------
    int cx = bx & 7, kx = bx >> 3;
    unsigned sb = (unsigned)__cvta_generic_to_shared(gsm);
    int wid = t >> 5, lane = t & 31;
    int my = (wid >> 2) * 32, nw = (wid & 3) * 16;
    int gI = lane >> 2, tq = lane & 3;
    float acc[2][2][4] = {};
    int rr0 = t >> 4, c4 = t & 15;

    float4 vq[2], vk[2];
    auto loadW = [&](int o0) {
      #pragma unroll
      for (int z = 0; z < 2; z++) {
        int row = rr0 + z * 16;
        vq[z] = *(const float4*)&Wq[(size_t)(o0 + row) * NC + cx * 64 + c4 * 4];
        vk[z] = *(const float4*)&Wk[(size_t)(o0 + row) * NC + kx * 64 + c4 * 4];
      }
    };
    auto storeW = [&]() {
      #pragma unroll
      for (int z = 0; z < 2; z++) {
        int row = rr0 + z * 16;
        uint2 h, l;
        hilo2((const float*)&vq[z], h, l);
        *(uint2*)(gsm + GA_H + row * 144 + c4 * 8) = h;
        *(uint2*)(gsm + GA_L + row * 144 + c4 * 8) = l;
        hilo2((const float*)&vk[z], h, l);
        *(uint2*)(gsm + GB_H + row * 144 + c4 * 8) = h;
        *(uint2*)(gsm + GB_L + row * 144 + c4 * 8) = l;
      }
    };

    loadW(0);
    storeW();
    __syncthreads();

    for (int i = 0; i < 8; i++) {
      if (i < 7) loadW((i + 1) * 32);       // prefetch next chunk into regs
      #pragma unroll
      for (int ks = 0; ks < 32; ks += 16) {
        unsigned Ah[2][4], Al[2][4];
        unsigned arow = ks + (lane & 7) + ((lane & 16) >> 1);
        #pragma unroll
        for (int mt = 0; mt < 2; mt++) {
          unsigned mcol = my + mt * 16 + (lane & 8);
          unsigned aaddr = sb + GA_H + arow * 144 + mcol * 2;
          ldsm4t(Ah[mt][0], Ah[mt][1], Ah[mt][2], Ah[mt][3], aaddr);
          ldsm4t(Al[mt][0], Al[mt][1], Al[mt][2], Al[mt][3], aaddr + (GA_L - GA_H));
        }
        unsigned Bh[4], Bl[4];
        {
          unsigned brow = ks + (lane & 7) + (lane & 8);
          unsigned bcol = nw + ((lane & 16) >> 1);
          unsigned baddr = sb + GB_H + brow * 144 + bcol * 2;
          ldsm4t(Bh[0], Bh[1], Bh[2], Bh[3], baddr);
          ldsm4t(Bl[0], Bl[1], Bl[2], Bl[3], baddr + (GB_L - GB_H));
        }
        #pragma unroll
        for (int mt = 0; mt < 2; mt++)
          #pragma unroll
          for (int sub = 0; sub < 2; sub++) {
            mma16816(acc[mt][sub], Ah[mt], Bh[sub * 2], Bh[sub * 2 + 1]);
            mma16816(acc[mt][sub], Ah[mt], Bl[sub * 2], Bl[sub * 2 + 1]);
            mma16816(acc[mt][sub], Al[mt], Bh[sub * 2], Bh[sub * 2 + 1]);
          }
      }
      __syncthreads();                       // all warps done reading smem
      if (i < 7) {
        storeW();
        __syncthreads();                     // next chunk visible
      }
    }
    #pragma unroll
    for (int mt = 0; mt < 2; mt++)
      #pragma unroll
      for (int nt = 0; nt < 2; nt++) {
        int cg = cx * 64 + my + mt * 16 + gI;
        int kg = kx * 64 + nw + nt * 8 + 2 * tq;
        split_bf(acc[mt][nt][0], g_Gh[cg][kg],     g_Gl[cg][kg]);
        split_bf(acc[mt][nt][1], g_Gh[cg][kg + 1], g_Gl[cg][kg + 1]);
        split_bf(acc[mt][nt][2], g_Gh[cg + 8][kg],     g_Gl[cg + 8][kg]);
        split_bf(acc[mt][nt][3], g_Gh[cg + 8][kg + 1], g_Gl[cg + 8][kg + 1]);
      }
    return;
  }

  if (bx < 96) {                       // ---------------- Wv convert -----------
    int base = (bx - 64) * 2048;
    #pragma unroll
    for (int j = 0; j < 8; j++) {
      int idx4 = base + j * 256 + t;
      float4 v = ((const float4*)Wv)[idx4];
      __nv_bfloat16 h0, l0, h1, l1;
      split_bf(v.x, h0, l0); split_bf(v.y, h1, l1);
      ((__nv_bfloat162*)g_Wvh)[idx4 * 2] = {h0, h1};
      ((__nv_bfloat162*)g_Wvl)[idx4 * 2] = {l0, l1};
      split_bf(v.z, h0, l0); split_bf(v.w, h1, l1);
      ((__nv_bfloat162*)g_Wvh)[idx4 * 2 + 1] = {h0, h1};
      ((__nv_bfloat162*)g_Wvl)[idx4 * 2 + 1] = {l0, l1};
    }
    return;
  }

  if (bx < 104) {                      // ---------------- bias blocks ----------
    int c = (bx - 96) * 64 + (t >> 2);
    int q = t & 3;
    float s1 = 0.f, s2 = 0.f;
    #pragma unroll 8
    for (int o = q; o < CKQ; o += 4) {
      s1 += Wq[(size_t)o * NC + c] * bk[o];
      s2 += Wk[(size_t)o * NC + c] * bq[o];
    }
    s1 += __shfl_xor_sync(0xffffffffu, s1, 1);
    s1 += __shfl_xor_sync(0xffffffffu, s1, 2);
    s2 += __shfl_xor_sync(0xffffffffu, s2, 1);
    s2 += __shfl_xor_sync(0xffffffffu, s2, 2);
    if (q == 0) { g_v1[c] = s1; g_v2[c] = s2; }
    if (bx == 96 && t < 32) {
      float s = 0.f;
      for (int o = t; o < CKQ; o += 32) s += bq[o] * bk[o];
      #pragma unroll
      for (int d = 16; d > 0; d >>= 1) s += __shfl_xor_sync(0xffffffffu, s, d);
      if (t == 0) g_s0 = s;
    }
    return;
  }

  // ---------------- prep: 4 channels per block --------------------------------
  {
    int p = bx - 104;                  // 0..511
    int b = p >> 7, c0 = (p & 127) * 4;
    int hq = t >> 4, tw = t & 15;
    float4* SM4 = (float4*)(smem_all + P_SM4);
    float*  XBV = (float*)(smem_all + P_XBV);
    float*  X1S = (float*)(smem_all + P_X1S);
    int*    PIX = (int*)(smem_all + P_PIX);
    if (t < 16) PIX[t] = pos[b * NN + 4 * t] >> 3;

    const float* xp = x + ((size_t)(b * NC + c0)) * NH * NW;
    float4 s[4];
    #pragma unroll
    for (int j = 0; j < 4; j++) s[j] = {0.f, 0.f, 0.f, 0.f};
    #pragma unroll
    for (int h = 0; h < 4; h++) {
      #pragma unroll
      for (int j = 0; j < 4; j++) {
        float4 v = *(const float4*)&xp[(size_t)j * NH * NW + (hq + h * 16) * NW + tw * 4];
        s[j].x += v.x; s[j].y += v.y; s[j].z += v.z; s[j].w += v.w;
      }
    }
    #pragma unroll
    for (int j = 0; j < 4; j++) SM4[j * 256 + hq * 16 + tw] = s[j];
    __syncthreads();
    if (hq < 4) {
      float4 a = {0.f, 0.f, 0.f, 0.f};
      #pragma unroll
      for (int q = 0; q < 16; q++) {
        float4 v = SM4[hq * 256 + q * 16 + tw];
        a.x += v.x; a.y += v.y; a.z += v.z; a.w += v.w;
      }
      const float inv = 1.0f / NH;
      a.x *= inv; a.y *= inv; a.z *= inv; a.w *= inv;
      *(float4*)&XBV[hq * 64 + tw * 4] = a;
      *(float4*)&g_xbar[b][c0 + hq][tw * 4] = a;
    }
    __syncthreads();
    if (t < 64) {
      int j = t >> 4, wp = t & 15;
      X1S[j * 16 + wp] = 0.25f * (XBV[j * 64 + 4 * wp] + XBV[j * 64 + 4 * wp + 1] +
                                  XBV[j * 64 + 4 * wp + 2] + XBV[j * 64 + 4 * wp + 3])
                         + pe[PIX[wp] * NC + c0 + j];
    }
    __syncthreads();
    {
      int j = t >> 6, w = t & 63;
      float src = (w * 15.0f) / 63.0f;
      int   i0  = (int)floorf(src);
      int   i1  = min(i0 + 1, 15);
      float tt  = src - (float)i0;
      g_x2df[b][c0 + j][w] = X1S[j * 16 + i0] * (1.0f - tt) + X1S[j * 16 + i1] * tt;
    }
  }
}

// =============================================================================
// k_MV: [0,32) M^T tiles | [32,64) vbar tiles (hi only out) | [64,68) dw
// =============================================================================
#define ACV0 0
#define ACVLO 9216
#define ACVBUF 18432         // 2 buffers end 36864
#define CPB0 36864
#define CPBLO 9216
#define CPBSZ 18432          // 2 buffers end 73728
#define MV_SMEM 73728

__global__ __launch_bounds__(256)
void k_MV(const float* __restrict__ bv) {
  extern __shared__ char dsm[];
  unsigned sb = (unsigned)__cvta_generic_to_shared(dsm);
  int bx = blockIdx.x, tid = threadIdx.x;

  if (bx >= 64) {                      // dw
    int b = bx - 64;
    int w = tid >> 2, q = tid & 3;
    float s = 0.f;
    #pragma unroll 8
    for (int c = q; c < NC; c += 4) s += g_x2df[b][c][w] * g_v2[c];
    s += __shfl_xor_sync(0xffffffffu, s, 1);
    s += __shfl_xor_sync(0xffffffffu, s, 2);
    if (q == 0) g_dw[b][w] = s + g_s0;
    return;
  }

  bool mtr = (bx < 32);
  int b  = mtr ? (bx >> 3) : ((bx - 32) >> 3);
  int c0 = (mtr ? (bx & 7) : ((bx - 32) & 7)) * 64;
  const float* Xf = mtr ? &g_x2df[b][0][0] : &g_xbar[b][0][0];
  const __nv_bfloat16* Bhg = mtr ? &g_Gh[c0][0] : &g_Wvh[c0][0];
  const __nv_bfloat16* Blg = mtr ? &g_Gl[c0][0] : &g_Wvl[c0][0];

  int rc = tid >> 4, ln4 = tid & 15;
  float4 xr[4];
  auto load_f = [&](int k0) {
    #pragma unroll
    for (int z = 0; z < 4; z++)
      xr[z] = *(const float4*)&Xf[(size_t)(k0 + rc + z * 16) * NW + ln4 * 4];
  };
  auto store_f = [&](unsigned base) {
    #pragma unroll
    for (int z = 0; z < 4; z++) {
      uint2 h, l;
      hilo2((const float*)&xr[z], h, l);
      unsigned a = base + (rc + z * 16) * 144 + ln4 * 8;
      *(uint2*)(dsm + a) = h;
      *(uint2*)(dsm + a + ACVLO) = l;
    }
  };
  auto issueB = [&](int k0, unsigned base) {
    #pragma unroll
    for (int u = tid; u < 512; u += 256) {
      int r = u >> 3, q = u & 7;
      cp16(sb + base + r * 144 + q * 16,         Bhg + (size_t)r * NC + k0 + q * 8);
      cp16(sb + base + CPBLO + r * 144 + q * 16, Blg + (size_t)r * NC + k0 + q * 8);
    }
  };

  int wid = tid >> 5, lane = tid & 31;
  int my = (wid >> 2) * 32, nw = (wid & 3) * 16;
  int gI = lane >> 2, tq = lane & 3;
  float acc[2][2][4] = {};

  load_f(0);
  issueB(0, CPB0); CP_COMMIT();
  store_f(ACV0);
  CP_WAIT(0);
  __syncthreads();

  for (int kc = 0; kc < 8; kc++) {
    if (kc < 7) {
      load_f((kc + 1) * 64);
      issueB((kc + 1) * 64, CPB0 + ((kc + 1) & 1) * CPBSZ); CP_COMMIT();
    }
    unsigned acv = ACV0 + (kc & 1) * ACVBUF;
    unsigned cpb = CPB0 + (kc & 1) * CPBSZ;
    if (mtr) {
      #pragma unroll
      for (int ks = 0; ks < 64; ks += 16) {
        unsigned Ah[2][4], Al[2][4];
        unsigned arow = ks + (lane & 7) + ((lane & 16) >> 1);
        #pragma unroll
        for (int mt = 0; mt < 2; mt++) {
          unsigned acol = my + mt * 16 + (lane & 8);
          unsigned aaddr = sb + acv + arow * 144 + acol * 2;
          ldsm4t(Ah[mt][0], Ah[mt][1], Ah[mt][2], Ah[mt][3], aaddr);
          ldsm4t(Al[mt][0], Al[mt][1], Al[mt][2], Al[mt][3], aaddr + ACVLO);
        }
        unsigned Bh[4], Bl[4];
        {
          unsigned row = nw + (lane & 7) + ((lane & 16) >> 1);
          unsigned coff = ks * 2 + ((lane & 8) << 1);
          unsigned baddr = sb + cpb + row * 144 + coff;
          ldsm4(Bh[0], Bh[1], Bh[2], Bh[3], baddr);
          ldsm4(Bl[0], Bl[1], Bl[2], Bl[3], baddr + CPBLO);
        }
        #pragma unroll
        for (int mt = 0; mt < 2; mt++)
          #pragma unroll
          for (int sub = 0; sub < 2; sub++) {
            mma16816(acc[mt][sub], Ah[mt], Bh[sub * 2], Bh[sub * 2 + 1]);
            mma16816(acc[mt][sub], Ah[mt], Bl[sub * 2], Bl[sub * 2 + 1]);
            mma16816(acc[mt][sub], Al[mt], Bh[sub * 2], Bh[sub * 2 + 1]);
          }
      }
    } else {
      #pragma unroll
      for (int ks = 0; ks < 64; ks += 16) {
        unsigned Ah[2][4], Al[2][4];
        #pragma unroll
        for (int mt = 0; mt < 2; mt++) {
          unsigned row = my + mt * 16 + (lane & 15);
          unsigned coff = ks * 2 + ((lane >> 4) << 4);
          unsigned aaddr = sb + cpb + row * 144 + coff;
          ldsm4(Ah[mt][0], Ah[mt][1], Ah[mt][2], Ah[mt][3], aaddr);
          ldsm4(Al[mt][0], Al[mt][1], Al[mt][2], Al[mt][3], aaddr + CPBLO);
        }
        unsigned Bh[4], Bl[4];
        {
          unsigned brow = ks + (lane & 7) + (lane & 8);
          unsigned bcol = nw + ((lane & 16) >> 1);
          unsigned baddr = sb + acv + brow * 144 + bcol * 2;
          ldsm4t(Bh[0], Bh[1], Bh[2], Bh[3], baddr);
          ldsm4t(Bl[0], Bl[1], Bl[2], Bl[3], baddr + ACVLO);
        }
        #pragma unroll
        for (int mt = 0; mt < 2; mt++)
          #pragma unroll
          for (int sub = 0; sub < 2; sub++) {
            mma16816(acc[mt][sub], Ah[mt], Bh[sub * 2], Bh[sub * 2 + 1]);
            mma16816(acc[mt][sub], Ah[mt], Bl[sub * 2], Bl[sub * 2 + 1]);
            mma16816(acc[mt][sub], Al[mt], Bh[sub * 2], Bh[sub * 2 + 1]);
          }
      }
    }
    if (kc < 7) {
      store_f(ACV0 + ((kc + 1) & 1) * ACVBUF);
      CP_WAIT(0);
    }
    __syncthreads();
  }

  if (mtr) {
    #pragma unroll
    for (int mt = 0; mt < 2; mt++)
      #pragma unroll
      for (int nt = 0; nt < 2; nt++) {
        int w = my + mt * 16 + gI;
        int c = c0 + nw + nt * 8 + 2 * tq;
        split_bf(acc[mt][nt][0] + g_v1[c],     g_MTh[b][w][c],     g_MTl[b][w][c]);
        split_bf(acc[mt][nt][1] + g_v1[c + 1], g_MTh[b][w][c + 1], g_MTl[b][w][c + 1]);
        split_bf(acc[mt][nt][2] + g_v1[c],     g_MTh[b][w + 8][c],     g_MTl[b][w + 8][c]);
        split_bf(acc[mt][nt][3] + g_v1[c + 1], g_MTh[b][w + 8][c + 1], g_MTl[b][w + 8][c + 1]);
      }
  } else {
    #pragma unroll
    for (int mt = 0; mt < 2; mt++)
      #pragma unroll
      for (int nt = 0; nt < 2; nt++) {
        int c = c0 + my + mt * 16 + gI;
        int w = nw + nt * 8 + 2 * tq;
        float bv0 = bv[c], bv8 = bv[c + 8];
        g_vbh[b][c][w]         = __float2bfloat16(acc[mt][nt][0] + bv0);
        g_vbh[b][c][w + 1]     = __float2bfloat16(acc[mt][nt][1] + bv0);
        g_vbh[b][c + 8][w]     = __float2bfloat16(acc[mt][nt][2] + bv8);
        g_vbh[b][c + 8][w + 1] = __float2bfloat16(acc[mt][nt][3] + bv8);
      }
  }
}

// =============================================================================
// k_fused: n-tile 64, 2 blocks/SM, 32x32 warp tiles.
// phase 1: 3-term hi/lo. phase 2: pure bf16 (vb_hi x attn_hi), 128c chunks.
// =============================================================================
#define XA0 0
#define XALO 9216
#define XABUF 18432          // 2 buffers end 36864
#define MB0 36864
#define MBLO 9216
#define MBSZ 18432           // 2 buffers end 73728
#define EF_OFF 73728         // 64*68*4 = 17408 -> end 91136
#define ATT_H 0              // aliases XA buf0 (dead after phase 1)
#define VB0 18432            // aliases XA buf1 (dead after phase 1)
#define VB1 36864            // aliases MB buf0 (dead after phase 1)
#define VBSZ 18432           // hi only: 128 rows x 144B
#define SMEM_FUSED 92160

__global__ __launch_bounds__(256, 2)
void k_fused(const float* __restrict__ x, const float* __restrict__ gamma,
             float* __restrict__ out) {
  extern __shared__ char sm[];
  unsigned sb = (unsigned)__cvta_generic_to_shared(sm);
  int tid = threadIdx.x;
  int wid = tid >> 5, lane = tid & 31;
  int b = blockIdx.y;
  int n0 = blockIdx.x * 64;
  int gI = lane >> 2, tq = lane & 3;

  const float* xb = x + (size_t)b * NC * NN + n0;
  int rc = tid >> 4, ln4 = tid & 15;

  float4 xr[4];
  auto load_x = [&](int c0) {
    #pragma unroll
    for (int z = 0; z < 4; z++)
      xr[z] = *(const float4*)(xb + (size_t)(c0 + rc + z * 16) * NN + ln4 * 4);
  };
  auto store_x = [&](unsigned xbase) {
    #pragma unroll
    for (int z = 0; z < 4; z++) {
      uint2 h, l;
      hilo2((const float*)&xr[z], h, l);
      unsigned base0 = xbase + (rc + z * 16) * 144 + ln4 * 8;
      *(uint2*)(sm + base0) = h;
      *(uint2*)(sm + base0 + XALO) = l;
    }
  };
  auto issue_M = [&](int c0, unsigned mb) {
    #pragma unroll
    for (int u = tid; u < 512; u += 256) {
      int rr = u >> 3, q = u & 7;
      cp16(sb + mb + rr * 144 + q * 16,        &g_MTh[b][rr][c0 + q * 8]);
      cp16(sb + mb + MBLO + rr * 144 + q * 16, &g_MTl[b][rr][c0 + q * 8]);
    }
  };
  auto issue_VB = [&](int cc, unsigned base) {
    #pragma unroll
    for (int u = tid; u < 1024; u += 256) {
      int rr = u >> 3, q = u & 7;
      cp16(sb + base + rr * 144 + q * 16, &g_vbh[b][cc * 128 + rr][q * 8]);
    }
  };

  // ---------------- phase 1: E[64n][64w], k-split across warp halves ----------
  int wq = wid & 3, khalf = wid >> 2;
  int ny = (wq >> 1) * 32, wy = (wq & 1) * 32;
  int ksb = khalf * 32;
  float acc1[2][4][4] = {};

  auto mma_chunk = [&](unsigned xab, unsigned mbb) {
    #pragma unroll
    for (int ks = 0; ks < 32; ks += 16) {
      int kk = ksb + ks;
      unsigned Ah[2][4], Al[2][4];
      unsigned arow = kk + (lane & 7) + ((lane & 16) >> 1);
      #pragma unroll
      for (int mt = 0; mt < 2; mt++) {
        unsigned acol = ny + mt * 16 + (lane & 8);
        unsigned aaddr = sb + xab + arow * 144 + acol * 2;
        ldsm4t(Ah[mt][0], Ah[mt][1], Ah[mt][2], Ah[mt][3], aaddr);
        ldsm4t(Al[mt][0], Al[mt][1], Al[mt][2], Al[mt][3], aaddr + XALO);
      }
      unsigned Bh[2][4], Bl[2][4];
      #pragma unroll
      for (int bt = 0; bt < 2; bt++) {
        unsigned brow = wy + bt * 16 + (lane & 7) + ((lane & 16) >> 1);
        unsigned coff = kk * 2 + ((lane & 8) << 1);
        unsigned baddr = sb + mbb + brow * 144 + coff;
        ldsm4(Bh[bt][0], Bh[bt][1], Bh[bt][2], Bh[bt][3], baddr);
        ldsm4(Bl[bt][0], Bl[bt][1], Bl[bt][2], Bl[bt][3], baddr + MBLO);
      }
      #pragma unroll
      for (int mt = 0; mt < 2; mt++)
        #pragma unroll
        for (int bt = 0; bt < 2; bt++)
          #pragma unroll
          for (int sub = 0; sub < 2; sub++) {
            int wt = bt * 2 + sub;
            mma16816(acc1[mt][wt], Ah[mt], Bh[bt][sub * 2], Bh[bt][sub * 2 + 1]);
            mma16816(acc1[mt][wt], Ah[mt], Bl[bt][sub * 2], Bl[bt][sub * 2 + 1]);
            mma16816(acc1[mt][wt], Al[mt], Bh[bt][sub * 2], Bh[bt][sub * 2 + 1]);
          }
    }
  };

  load_x(0);
  issue_M(0, MB0); CP_COMMIT();
  store_x(XA0);
  CP_WAIT(0);
  __syncthreads();

  for (int i = 0; i < 8; i++) {
    if (i < 7) {
      load_x((i + 1) * 64);
      issue_M((i + 1) * 64, MB0 + ((i + 1) & 1) * MBSZ); CP_COMMIT();
    }
    mma_chunk(XA0 + (i & 1) * XABUF, MB0 + (i & 1) * MBSZ);
    if (i < 7) {
      store_x(XA0 + ((i + 1) & 1) * XABUF);
      CP_WAIT(0);
    }
    __syncthreads();
  }

  issue_VB(0, VB0);
  CP_COMMIT();

  // reduction: khalf 0 writes (with dw), khalf 1 adds
  float* Ef = (float*)(sm + EF_OFF);
  if (khalf == 0) {
    #pragma unroll
    for (int wt = 0; wt < 4; wt++) {
      int wc = wy + (wt >> 1) * 16 + (wt & 1) * 8 + 2 * tq;
      float d0 = g_dw[b][wc], d1 = g_dw[b][wc + 1];
      #pragma unroll
      for (int mt = 0; mt < 2; mt++) {
        int r = ny + mt * 16 + gI;
        float2 v0 = {acc1[mt][wt][0] + d0, acc1[mt][wt][1] + d1};
        float2 v1 = {acc1[mt][wt][2] + d0, acc1[mt][wt][3] + d1};
        *(float2*)&Ef[r * 68 + wc] = v0;
        *(float2*)&Ef[(r + 8) * 68 + wc] = v1;
      }
    }
  }
  __syncthreads();
  if (khalf == 1) {
    #pragma unroll
    for (int wt = 0; wt < 4; wt++) {
      int wc = wy + (wt >> 1) * 16 + (wt & 1) * 8 + 2 * tq;
      #pragma unroll
      for (int mt = 0; mt < 2; mt++) {
        int r = ny + mt * 16 + gI;
        float2 v0 = *(float2*)&Ef[r * 68 + wc];
        float2 v1 = *(float2*)&Ef[(r + 8) * 68 + wc];
        v0.x += acc1[mt][wt][0]; v0.y += acc1[mt][wt][1];
        v1.x += acc1[mt][wt][2]; v1.y += acc1[mt][wt][3];
        *(float2*)&Ef[r * 68 + wc] = v0;
        *(float2*)&Ef[(r + 8) * 68 + wc] = v1;
      }
    }
  }
  __syncthreads();

  // softmax over w (4 threads/row, 64 rows)
  {
    int row = tid >> 2, q = tid & 3;
    float mx = -1e30f;
    for (int w = q; w < NW; w += 4) mx = fmaxf(mx, Ef[row * 68 + w]);
    mx = fmaxf(mx, __shfl_xor_sync(0xffffffffu, mx, 1));
    mx = fmaxf(mx, __shfl_xor_sync(0xffffffffu, mx, 2));
    float s = 0.f;
    for (int w = q; w < NW; w += 4) {
      float e = __expf(Ef[row * 68 + w] - mx);
      Ef[row * 68 + w] = e;
      s += e;
    }
    s += __shfl_xor_sync(0xffffffffu, s, 1);
    s += __shfl_xor_sync(0xffffffffu, s, 2);
    float inv = 1.0f / s;
    for (int w = q; w < NW; w += 4) Ef[row * 68 + w] *= inv;
  }
  __syncthreads();

  // convert attn to bf16 hi only [n][w], rows 144B (aliases XA buf0)
  #pragma unroll
  for (int i = 0; i < 8; i++) {
    int p = tid + i * 256;
    int n = p >> 5, wp = p & 31;
    float e0 = Ef[n * 68 + 2 * wp], e1 = Ef[n * 68 + 2 * wp + 1];
    *(unsigned*)(sm + ATT_H + n * 144 + wp * 4) = pack_bf2(e0, e1);
  }
  __syncthreads();

  // ---------------- phase 2: out = gamma*(vb_hi @ attn_hi^T) + x --------------
  float g = gamma[0];
  int cy = (wid >> 1) * 32;
  int nx = (wid & 1) * 32;
  for (int cc = 0; cc < 4; cc++) {
    if (cc < 3) {
      issue_VB(cc + 1, ((cc + 1) & 1) ? VB1 : VB0);
      CP_COMMIT();
      CP_WAIT(1);
    } else {
      CP_WAIT(0);
    }
    __syncthreads();

    // L2-prefetch this chunk's residual-x lines
    {
      const float* px = x + ((size_t)(b * NC + cc * 128 + (tid >> 1))) * NN
                          + n0 + (tid & 1) * 32;
      asm volatile("prefetch.global.L2 [%0];" :: "l"(px));
    }

    unsigned vbb = (cc & 1) ? VB1 : VB0;
    float acc2[2][4][4] = {};
    #pragma unroll
    for (int ks = 0; ks < 64; ks += 16) {
      unsigned Ah[2][4];
      #pragma unroll
      for (int mt = 0; mt < 2; mt++) {
        unsigned row = cy + mt * 16 + (lane & 15);
        unsigned coff = ks * 2 + ((lane >> 4) << 4);
        ldsm4(Ah[mt][0], Ah[mt][1], Ah[mt][2], Ah[mt][3], sb + vbb + row * 144 + coff);
      }
      unsigned Bh[2][4];
      #pragma unroll
      for (int bt = 0; bt < 2; bt++) {
        unsigned row = nx + bt * 16 + (lane & 7) + ((lane & 16) >> 1);
        unsigned coff = ks * 2 + ((lane & 8) << 1);
        ldsm4(Bh[bt][0], Bh[bt][1], Bh[bt][2], Bh[bt][3], sb + ATT_H + row * 144 + coff);
      }
      #pragma unroll
      for (int mt = 0; mt < 2; mt++)
        #pragma unroll
        for (int bt = 0; bt < 2; bt++)
          #pragma unroll
          for (int sub = 0; sub < 2; sub++) {
            int nt = bt * 2 + sub;
            mma16816(acc2[mt][nt], Ah[mt], Bh[bt][sub * 2], Bh[bt][sub * 2 + 1]);
          }
    }
    // epilogue: residual add + store
    #pragma unroll
    for (int mt = 0; mt < 2; mt++) {
      int c = cc * 128 + cy + mt * 16 + gI;
      #pragma unroll
      for (int nt = 0; nt < 4; nt++) {
        int n = n0 + nx + (nt >> 1) * 16 + (nt & 1) * 8 + 2 * tq;
        size_t off = ((size_t)(b * NC + c)) * NN + n;
        float2 xv0 = *(const float2*)(x + off);
        float2 xv1 = *(const float2*)(x + off + (size_t)8 * NN);
        float2 o0 = {fmaf(g, acc2[mt][nt][0], xv0.x), fmaf(g, acc2[mt][nt][1], xv0.y)};
        float2 o1 = {fmaf(g, acc2[mt][nt][2], xv1.x), fmaf(g, acc2[mt][nt][3], xv1.y)};
        *(float2*)(out + off) = o0;
        *(float2*)(out + off + (size_t)8 * NN) = o1;
      }
    }
    __syncthreads();
  }
}

// ---------------- launch -----------------------------------------------------
extern "C" void kernel_launch(void* const* d_in, const int* in_sizes, int n_in,
                              void* d_out, int out_size) {
  const float* x     = (const float*)d_in[0];
  const float* Wq    = (const float*)d_in[1];
  const float* bq    = (const float*)d_in[2];
  const float* Wk    = (const float*)d_in[3];
  const float* bk    = (const float*)d_in[4];
  const float* Wv    = (const float*)d_in[5];
  const float* bv    = (const float*)d_in[6];
  const float* gamma = (const float*)d_in[7];
  const float* pe    = (const float*)d_in[8];
  const int*   pos   = (const int*)  d_in[9];
  float* out = (float*)d_out;

  cudaFuncSetAttribute(k_MV, cudaFuncAttributeMaxDynamicSharedMemorySize, MV_SMEM);
  cudaFuncSetAttribute(k_fused, cudaFuncAttributeMaxDynamicSharedMemorySize,
                       SMEM_FUSED);

  k_front<<<616, 256>>>(x, pos, pe, Wq, Wk, Wv, bq, bk);
  k_MV<<<68, 256, MV_SMEM>>>(bv);
  k_fused<<<dim3(NN / 64, NB), 256, SMEM_FUSED>>>(x, gamma, out);
}